// round 9
// baseline (speedup 1.0000x reference)
#include <cuda_runtime.h>
#include <cuda_bf16.h>
#include <math.h>
#include <stdint.h>

// Problem dims
#define BB  32
#define SS  100
#define TT  64
#define HH  512
#define EE  512
#define VV  32000
#define G4H 2048
#define KZ  1536     // E (emb) + H (u) + H (h)
#define NBLK 128

// ---------------- device scratch ----------------
__device__ float g_W4[G4H * KZ];     // [W_E | W_U | W_hh], rows reordered rr=4h+g
__device__ float g_b4[G4H];
__device__ float g_c0[G4H * BB];     // W_O @ init_output (t=0 bias), [rr][b]
__device__ float g_wob2[G4H];        // W_O @ bo2 (t>0 bias)
__device__ float g_Wqb[HH * HH];     // Wb @ Wq
__device__ float g_bqb[HH];          // Wb @ bq + bb
__device__ float g_P[BB * SS * HH];  // mem @ Wqb
__device__ float g_q0[BB * SS];      // bqb.mem with mask folded
__device__ float g_h[2][BB * HH];
__device__ float g_c[BB * HH];
__device__ float g_ctx[BB * HH];
__device__ float g_uall[TT * BB * HH]; // all u_t  (m = t*B+b)
__device__ float g_out[TT * BB * EE];  // out = uall @ Wo2^T + bo2
__device__ int   g_trg64;
__device__ int   g_maskty;

__device__ volatile unsigned g_cnt;
__device__ volatile unsigned g_gen;

__device__ unsigned short g_Bh[(size_t)VV * EE];
__device__ unsigned short g_Bl[(size_t)VV * EE];
__device__ unsigned short g_Ah[(size_t)TT * BB * EE];
__device__ unsigned short g_Al[(size_t)TT * BB * EE];

// ---------------- helpers ----------------
__device__ __forceinline__ uint32_t smem_u32(const void* p) {
    uint32_t a;
    asm("{ .reg .u64 t; cvta.to.shared.u64 t, %1; cvt.u32.u64 %0, t; }" : "=r"(a) : "l"(p));
    return a;
}
__device__ __forceinline__ void ldm_x4(uint32_t* r, uint32_t addr) {
    asm volatile("ldmatrix.sync.aligned.m8n8.x4.shared.b16 {%0,%1,%2,%3}, [%4];"
                 : "=r"(r[0]), "=r"(r[1]), "=r"(r[2]), "=r"(r[3]) : "r"(addr));
}
__device__ __forceinline__ void mma_bf16(float* d, const uint32_t* a, uint32_t b0, uint32_t b1) {
    asm volatile(
        "mma.sync.aligned.m16n8k16.row.col.f32.bf16.bf16.f32 "
        "{%0,%1,%2,%3}, {%4,%5,%6,%7}, {%8,%9}, {%0,%1,%2,%3};"
        : "+f"(d[0]), "+f"(d[1]), "+f"(d[2]), "+f"(d[3])
        : "r"(a[0]), "r"(a[1]), "r"(a[2]), "r"(a[3]), "r"(b0), "r"(b1));
}
__device__ __forceinline__ void cp_async16(uint32_t smem_dst, const void* gsrc) {
    asm volatile("cp.async.cg.shared.global [%0], [%1], 16;"
                 :: "r"(smem_dst), "l"(gsrc) : "memory");
}

// R6-proven barrier: nanosleep backoff spin
__device__ __forceinline__ void gsync() {
    __syncthreads();
    if (threadIdx.x == 0) {
        unsigned gen = g_gen;
        __threadfence();
        if (atomicAdd((unsigned*)&g_cnt, 1u) == NBLK - 1) {
            g_cnt = 0;
            __threadfence();
            g_gen = gen + 1;
        } else {
            while (g_gen == gen) __nanosleep(20);
        }
        __threadfence();
    }
    __syncthreads();
}

__device__ __forceinline__ int jmap(int rr) { return (rr & 3) * HH + (rr >> 2); }

// ---------------- prep1: detect/init + wqb + c0 + wob2 + w4(outer) ----------------
// blocks: [0] detect+init | [1,1025) wqb | [1025,1281) c0 | [1281,1345) wob2 | [1345,3393) w4
__global__ void __launch_bounds__(256) prep1(
    const int* __restrict__ trg_w, const int* __restrict__ mask_w,
    const float* __restrict__ ih, const float* __restrict__ ic,
    const float* __restrict__ Wq, const float* __restrict__ Wb,
    const float* __restrict__ bq, const float* __restrict__ bbias,
    const float* __restrict__ Wih, const float* __restrict__ Whh,
    const float* __restrict__ bih, const float* __restrict__ bhh,
    const float* __restrict__ init_output, const float* __restrict__ bo2)
{
    int bid = blockIdx.x, tid = threadIdx.x;
    int wid = tid >> 5, lane = tid & 31;

    if (bid == 0) {
        __shared__ int s_odd_nz, s_bin, s_f32;
        if (tid == 0) { s_odd_nz = 0; s_bin = 1; s_f32 = 1; }
        __syncthreads();
        for (int i = tid; i < (BB * TT) / 2; i += 256)
            if (trg_w[2 * i + 1] != 0) atomicOr(&s_odd_nz, 1);
        for (int i = tid; i < (BB * SS) / 4; i += 256) {
            int v = mask_w[i];
            if (v != 0 && v != 1)           atomicAnd(&s_bin, 0);
            if (v != 0 && v != 0x3f800000)  atomicAnd(&s_f32, 0);
        }
        for (int i = tid; i < BB * HH; i += 256) { g_h[0][i] = ih[i]; g_c[i] = ic[i]; }
        __syncthreads();
        if (tid == 0) {
            g_trg64 = s_odd_nz ? 0 : 1;
            g_maskty = s_bin ? 1 : (s_f32 ? 2 : 0);
        }
    } else if (bid < 1025) {
        // Wqb = Wb @ Wq ; bqb = Wb @ bq + bb
        int idx = bid - 1;
        int by = idx >> 5, bx = idx & 31;
        int ty = tid >> 4, tx = tid & 15;
        int r = by * 16 + ty, c = bx * 16 + tx;
        float acc = 0.f;
        for (int k = 0; k < HH; k++) acc += Wb[r * HH + k] * Wq[k * HH + c];
        g_Wqb[r * HH + c] = acc;
        if (bx == 0 && tx == 0) {
            float a = bbias[r];
            for (int k = 0; k < HH; k++) a += Wb[r * HH + k] * bq[k];
            g_bqb[r] = a;
        }
    } else if (bid < 1281) {
        // c0[rr][b] = sum_e W_O[rr,e] * init_output[b,e]
        int idx = bid - 1025;               // 0..255
        int rr = idx * 8 + wid;             // each warp one rr
        int j = jmap(rr);
        const float* wrow = Wih + (size_t)j * (2 * EE) + EE;
        for (int b = 0; b < BB; b++) {
            const float* io = init_output + (size_t)b * EE;
            float a = 0.f;
            for (int e = lane; e < EE; e += 32) a += wrow[e] * io[e];
            #pragma unroll
            for (int off = 16; off; off >>= 1) a += __shfl_down_sync(0xffffffffu, a, off);
            if (lane == 0) g_c0[rr * BB + b] = a;
        }
    } else if (bid < 1345) {
        // wob2[rr] = sum_e W_O[rr,e] * bo2[e]
        int idx = bid - 1281;               // 0..63
        for (int q = 0; q < 4; q++) {
            int rr = idx * 32 + wid * 4 + q;
            int j = jmap(rr);
            const float* wrow = Wih + (size_t)j * (2 * EE) + EE;
            float a = 0.f;
            for (int e = lane; e < EE; e += 32) a += wrow[e] * bo2[e];
            #pragma unroll
            for (int off = 16; off; off >>= 1) a += __shfl_down_sync(0xffffffffu, a, off);
            if (lane == 0) g_wob2[rr] = a;
        }
    } else {
        // g_W4 outer columns + b4
        int rr = bid - 1345;
        int j = jmap(rr);
        for (int k = tid; k < KZ; k += 256) {
            if (k < EE)            g_W4[(size_t)rr * KZ + k] = Wih[(size_t)j * (2 * EE) + k];
            else if (k >= 2 * EE)  g_W4[(size_t)rr * KZ + k] = Whh[(size_t)j * HH + (k - 2 * EE)];
            // middle filled by prep2 (W_U)
        }
        if (tid == 0) g_b4[rr] = bih[j] + bhh[j];
    }
}

// ---------------- prep2: pgemm + q0 + wu ----------------
// blocks: [0,400) pgemm | [400,800) q0 | [800,1056) wu
__global__ void __launch_bounds__(256) prep2(
    const float* __restrict__ mem, const void* __restrict__ mask_raw,
    const float* __restrict__ Wih, const float* __restrict__ Wo2)
{
    __shared__ float As[16][68];
    __shared__ float Bs[16][68];
    int bid = blockIdx.x, tid = threadIdx.x;

    if (bid < 400) {
        // P = mem_flat(3200,512) @ Wqb(512,512)
        int m0 = (bid >> 3) * 64, j0 = (bid & 7) * 64;
        int tx = tid & 15, ty = tid >> 4;
        float acc[4][4];
        #pragma unroll
        for (int i = 0; i < 4; i++)
            #pragma unroll
            for (int j = 0; j < 4; j++) acc[i][j] = 0.f;
        for (int k0 = 0; k0 < HH; k0 += 16) {
            int row = tid >> 2, kq = (tid & 3) * 4;
            float4 va = *(const float4*)(mem + (size_t)(m0 + row) * HH + k0 + kq);
            As[kq][row] = va.x; As[kq + 1][row] = va.y;
            As[kq + 2][row] = va.z; As[kq + 3][row] = va.w;
            int kr = tid >> 4, jq = (tid & 15) * 4;
            float4 vb = *(const float4*)(g_Wqb + (size_t)(k0 + kr) * HH + j0 + jq);
            *(float4*)&Bs[kr][jq] = vb;
            __syncthreads();
            #pragma unroll
            for (int k = 0; k < 16; k++) {
                float a[4], b[4];
                #pragma unroll
                for (int i = 0; i < 4; i++) a[i] = As[k][ty * 4 + i];
                #pragma unroll
                for (int i = 0; i < 4; i++) b[i] = Bs[k][tx * 4 + i];
                #pragma unroll
                for (int i = 0; i < 4; i++)
                    #pragma unroll
                    for (int j = 0; j < 4; j++) acc[i][j] += a[i] * b[j];
            }
            __syncthreads();
        }
        #pragma unroll
        for (int i = 0; i < 4; i++)
            #pragma unroll
            for (int j = 0; j < 4; j++)
                g_P[(size_t)(m0 + ty * 4 + i) * HH + j0 + tx * 4 + j] = acc[i][j];
    } else if (bid < 800) {
        // q0
        int m = (bid - 400) * 8 + (tid >> 5);
        int l = tid & 31;
        if (m < BB * SS) {
            float a = 0.f;
            for (int k = l; k < HH; k += 32) a += g_bqb[k] * mem[(size_t)m * HH + k];
            #pragma unroll
            for (int off = 16; off; off >>= 1) a += __shfl_down_sync(0xffffffffu, a, off);
            if (l == 0) {
                int mty = g_maskty;
                bool mv;
                if      (mty == 0) mv = ((const unsigned char*)mask_raw)[m] != 0;
                else if (mty == 1) mv = ((const int*)mask_raw)[m] != 0;
                else               mv = ((const float*)mask_raw)[m] != 0.0f;
                g_q0[m] = mv ? a : -1e9f;
            }
        }
    } else {
        // W_U = W_O(2048x512, reordered rows) @ Wo2(512x512) -> g_W4 middle cols
        int idx = bid - 800;
        int r0 = (idx >> 3) * 64, h0 = (idx & 7) * 64;
        int tx = tid & 15, ty = tid >> 4;
        float acc[4][4];
        #pragma unroll
        for (int i = 0; i < 4; i++)
            #pragma unroll
            for (int j = 0; j < 4; j++) acc[i][j] = 0.f;
        for (int k0 = 0; k0 < EE; k0 += 16) {
            int row = tid >> 2, kq = (tid & 3) * 4;
            int j = jmap(r0 + row);
            float4 va = *(const float4*)(Wih + (size_t)j * (2 * EE) + EE + k0 + kq);
            As[kq][row] = va.x; As[kq + 1][row] = va.y;
            As[kq + 2][row] = va.z; As[kq + 3][row] = va.w;
            int kr = tid >> 4, jq = (tid & 15) * 4;
            float4 vb = *(const float4*)(Wo2 + (size_t)(k0 + kr) * HH + h0 + jq);
            *(float4*)&Bs[kr][jq] = vb;
            __syncthreads();
            #pragma unroll
            for (int k = 0; k < 16; k++) {
                float a[4], b[4];
                #pragma unroll
                for (int i = 0; i < 4; i++) a[i] = As[k][ty * 4 + i];
                #pragma unroll
                for (int i = 0; i < 4; i++) b[i] = Bs[k][tx * 4 + i];
                #pragma unroll
                for (int i = 0; i < 4; i++)
                    #pragma unroll
                    for (int jj = 0; jj < 4; jj++) acc[i][jj] += a[i] * b[jj];
            }
            __syncthreads();
        }
        #pragma unroll
        for (int i = 0; i < 4; i++)
            #pragma unroll
            for (int jj = 0; jj < 4; jj++)
                g_W4[(size_t)(r0 + ty * 4 + i) * KZ + EE + h0 + tx * 4 + jj] = acc[i][jj];
    }
}

// split fp32 -> bf16 hi + lo
__global__ void conv_split(const float* __restrict__ src,
                           unsigned short* __restrict__ hi,
                           unsigned short* __restrict__ lo, int n4) {
    int i = blockIdx.x * 256 + threadIdx.x;
    if (i >= n4) return;
    float4 v = ((const float4*)src)[i];
    __nv_bfloat16 h0 = __float2bfloat16(v.x);
    __nv_bfloat16 h1 = __float2bfloat16(v.y);
    __nv_bfloat16 h2 = __float2bfloat16(v.z);
    __nv_bfloat16 h3 = __float2bfloat16(v.w);
    __nv_bfloat16 l0 = __float2bfloat16(v.x - __bfloat162float(h0));
    __nv_bfloat16 l1 = __float2bfloat16(v.y - __bfloat162float(h1));
    __nv_bfloat16 l2 = __float2bfloat16(v.z - __bfloat162float(h2));
    __nv_bfloat16 l3 = __float2bfloat16(v.w - __bfloat162float(h3));
    __nv_bfloat162* H = (__nv_bfloat162*)hi;
    __nv_bfloat162* L = (__nv_bfloat162*)lo;
    H[2 * i]     = __halves2bfloat162(h0, h1);
    H[2 * i + 1] = __halves2bfloat162(h2, h3);
    L[2 * i]     = __halves2bfloat162(l0, l1);
    L[2 * i + 1] = __halves2bfloat162(l2, l3);
}

// ---------------- persistent decoder loop (3 barriers/step) ----------------
__global__ void __launch_bounds__(256) decoder_loop(
    const float* __restrict__ emb, const void* __restrict__ trg_raw,
    const float* __restrict__ mem,
    const float* __restrict__ Wo1, const float* __restrict__ bo1)
{
    __shared__ union {
        struct { float Zs[64][33]; float2 Wp[64][9]; float Gs[16][33]; int tok[BB]; } a;
        struct { float q[HH]; float sc[128]; float red[2][128]; } c;
        struct { float Zs[128][33]; float Ws[4][130]; float red[4][32]; } d;
    } sm;

    int tid = threadIdx.x, wid = tid >> 5, lane = tid & 31;
    int bid = blockIdx.x;
    int w3 = wid & 3, kh = wid >> 2;

    for (int t = 0; t < TT; t++) {
        const float* u_prev = g_uall + (size_t)(t - 1) * BB * HH;   // unused at t=0
        const float* h_prev = g_h[t & 1];
        float*       h_cur  = g_h[(t + 1) & 1];

        // ---- Phase A: gates = W_E emb + W_U u_prev + W_hh h_prev + bias; LSTM ----
        {
            int rbase = bid * 16;
            if (tid < BB) {
                long long v;
                if (g_trg64) v = ((const long long*)trg_raw)[tid * TT + t];
                else         v = ((const int*)trg_raw)[tid * TT + t];
                int tk = (int)v;
                if (tk < 0) tk = 0;
                if (tk >= VV) tk = VV - 1;
                sm.a.tok[tid] = tk;
            }
            __syncthreads();

            float acc0 = 0.f, acc1 = 0.f;
            for (int kt = 0; kt < KZ / 64; kt++) {
                int kg0 = kt * 64;
                for (int i = tid; i < 2048; i += 256) {
                    int b = i >> 6, k = i & 63, kg = kg0 + k;
                    float v;
                    if      (kg < EE)      v = emb[(size_t)sm.a.tok[b] * EE + kg];
                    else if (kg < 2 * EE)  v = (t == 0) ? 0.f : u_prev[b * HH + (kg - EE)];
                    else                   v = h_prev[b * HH + (kg - 2 * EE)];
                    sm.a.Zs[k][b] = v;
                }
                for (int i = tid; i < 1024; i += 256) {
                    int r = i >> 6, k = i & 63;
                    float v = g_W4[(size_t)(rbase + r) * KZ + kg0 + k];
                    ((float*)sm.a.Wp)[k * 18 + (r & 7) * 2 + (r >> 3)] = v;
                }
                __syncthreads();
                #pragma unroll
                for (int kk = 0; kk < 64; kk++) {
                    float z = sm.a.Zs[kk][lane];
                    float2 wv = sm.a.Wp[kk][wid];
                    acc0 += wv.x * z;
                    acc1 += wv.y * z;
                }
                __syncthreads();
            }
            {
                int r0 = rbase + wid, r1 = rbase + wid + 8;
                float e0 = (t == 0) ? g_c0[r0 * BB + lane] : g_wob2[r0];
                float e1 = (t == 0) ? g_c0[r1 * BB + lane] : g_wob2[r1];
                sm.a.Gs[wid][lane]     = acc0 + g_b4[r0] + e0;
                sm.a.Gs[wid + 8][lane] = acc1 + g_b4[r1] + e1;
            }
            __syncthreads();

            if (tid < 128) {
                int hl = tid >> 5, b = tid & 31;
                float gi = sm.a.Gs[4 * hl + 0][b];
                float gf = sm.a.Gs[4 * hl + 1][b];
                float gg = sm.a.Gs[4 * hl + 2][b];
                float go = sm.a.Gs[4 * hl + 3][b];
                gi = 1.f / (1.f + expf(-gi));
                gf = 1.f / (1.f + expf(-gf));
                go = 1.f / (1.f + expf(-go));
                gg = tanhf(gg);
                int h = bid * 4 + hl;
                int idx = b * HH + h;
                float c = gf * g_c[idx] + gi * gg;
                g_c[idx] = c;
                h_cur[idx] = go * tanhf(c);
            }
        }
        gsync();

        // ---- Phase C: attention; 4 blocks per batch (redundant softmax, split ctx) ----
        {
            int b = bid & 31;
            int slice = bid >> 5;          // 0..3 -> 128 ctx components each
            for (int i = tid; i < HH; i += 256) sm.c.q[i] = h_cur[b * HH + i];
            __syncthreads();

            for (int s = wid; s < SS; s += 8) {
                const float* prow = g_P + (size_t)(b * SS + s) * HH;
                float a = 0.f;
                for (int k = lane; k < HH; k += 32) a += sm.c.q[k] * prow[k];
                #pragma unroll
                for (int off = 16; off; off >>= 1) a += __shfl_down_sync(0xffffffffu, a, off);
                if (lane == 0) sm.c.sc[s] = a + g_q0[b * SS + s];
            }
            __syncthreads();

            if (wid == 0) {
                float m = -1e30f;
                for (int s = lane; s < SS; s += 32) m = fmaxf(m, sm.c.sc[s]);
                #pragma unroll
                for (int off = 16; off; off >>= 1) m = fmaxf(m, __shfl_xor_sync(0xffffffffu, m, off));
                float sum = 0.f;
                for (int s = lane; s < SS; s += 32) {
                    float e = expf(sm.c.sc[s] - m); sm.c.sc[s] = e; sum += e;
                }
                #pragma unroll
                for (int off = 16; off; off >>= 1) sum += __shfl_xor_sync(0xffffffffu, sum, off);
                float inv = 1.f / sum;
                for (int s = lane; s < SS; s += 32) sm.c.sc[s] *= inv;
            }
            __syncthreads();

            {
                int h_local = tid & 127, sh = tid >> 7;   // split s-range in 2
                const float* mbase = mem + (size_t)b * SS * HH + slice * 128 + h_local;
                float a = 0.f;
                int s0 = sh * 50;
                #pragma unroll 5
                for (int s = s0; s < s0 + 50; s++) a += sm.c.sc[s] * mbase[(size_t)s * HH];
                sm.c.red[sh][h_local] = a;
            }
            __syncthreads();
            if (tid < 128)
                g_ctx[b * HH + slice * 128 + tid] = sm.c.red[0][tid] + sm.c.red[1][tid];
        }
        gsync();

        // ---- Phase D1: u = tanh(Wo1 [h|ctx] + bo1); write to uall[t] ----
        {
            int r0 = bid * 4;
            float acc = 0.f;
            for (int kt = 0; kt < 8; kt++) {
                int kgA = kt * 64;
                int kgB = 512 + kt * 64;
                for (int i = tid; i < 4096; i += 256) {
                    int b = i >> 7, kk = i & 127;
                    int kg = (kk < 64) ? (kgA + kk) : (kgB + kk - 64);
                    float v = (kg < HH) ? h_cur[b * HH + kg] : g_ctx[b * HH + (kg - HH)];
                    sm.d.Zs[kk][b] = v;
                }
                for (int i = tid; i < 512; i += 256) {
                    int r = i >> 7, kk = i & 127;
                    int kg = (kk < 64) ? (kgA + kk) : (kgB + kk - 64);
                    sm.d.Ws[r][kk] = Wo1[(size_t)(r0 + r) * (2 * HH) + kg];
                }
                __syncthreads();
                #pragma unroll
                for (int kk = 0; kk < 64; kk++)
                    acc += sm.d.Ws[w3][kh * 64 + kk] * sm.d.Zs[kh * 64 + kk][lane];
                __syncthreads();
            }
            if (kh == 1) sm.d.red[w3][lane] = acc;
            __syncthreads();
            if (kh == 0) {
                acc += sm.d.red[w3][lane];
                g_uall[((size_t)t * BB + lane) * HH + r0 + w3] = tanhf(acc + bo1[r0 + w3]);
            }
        }
        gsync();
    }
}

// ---------------- out = uall(2048,512) @ Wo2(512,512)^T + bo2 ----------------
__global__ void __launch_bounds__(256) out_gemm(const float* __restrict__ Wo2,
                                                const float* __restrict__ bo2)
{
    __shared__ float As[16][68];
    __shared__ float Bs[16][68];
    int tid = threadIdx.x;
    int m0 = blockIdx.y * 64, e0 = blockIdx.x * 64;
    int tx = tid & 15, ty = tid >> 4;

    float acc[4][4];
    #pragma unroll
    for (int i = 0; i < 4; i++)
        #pragma unroll
        for (int j = 0; j < 4; j++) acc[i][j] = 0.f;

    for (int k0 = 0; k0 < HH; k0 += 16) {
        int row = tid >> 2, kq = (tid & 3) * 4;
        float4 va = *(const float4*)(g_uall + (size_t)(m0 + row) * HH + k0 + kq);
        As[kq][row] = va.x; As[kq + 1][row] = va.y;
        As[kq + 2][row] = va.z; As[kq + 3][row] = va.w;
        float4 vb = *(const float4*)(Wo2 + (size_t)(e0 + row) * HH + k0 + kq);
        Bs[kq][row] = vb.x; Bs[kq + 1][row] = vb.y;
        Bs[kq + 2][row] = vb.z; Bs[kq + 3][row] = vb.w;
        __syncthreads();
        #pragma unroll
        for (int k = 0; k < 16; k++) {
            float a[4], b[4];
            #pragma unroll
            for (int i = 0; i < 4; i++) a[i] = As[k][ty * 4 + i];
            #pragma unroll
            for (int i = 0; i < 4; i++) b[i] = Bs[k][tx * 4 + i];
            #pragma unroll
            for (int i = 0; i < 4; i++)
                #pragma unroll
                for (int j = 0; j < 4; j++) acc[i][j] += a[i] * b[j];
        }
        __syncthreads();
    }
    #pragma unroll
    for (int i = 0; i < 4; i++)
        #pragma unroll
        for (int j = 0; j < 4; j++)
            g_out[(size_t)(m0 + ty * 4 + i) * EE + e0 + tx * 4 + j] =
                acc[i][j] + bo2[e0 + tx * 4 + j];
}

// ---------------- HMMA logits GEMM (cp.async double-buffered) ----------------
// D(2048,32000) = A(2048,512) @ B(32000,512)^T via bf16 split (3 passes, fp32 acc).
#define SPAD 72
#define TILE_B (128 * SPAD * 2)     // 18432 bytes per operand tile
__global__ void __launch_bounds__(256) logits_mma(float* __restrict__ outp)
{
    extern __shared__ __align__(16) unsigned char dynsm[];

    int tid = threadIdx.x, lane = tid & 31, wid = tid >> 5;
    int wm = wid >> 2;
    int wn = wid & 3;
    int mblk = blockIdx.x * 128;
    int nblk = blockIdx.y * 128;

    uint32_t sbase = smem_u32(dynsm);
    uint32_t aoff = (uint32_t)((wm * 64 + (lane & 15)) * SPAD * 2 + (lane >> 4) * 16);
    uint32_t boff = (uint32_t)((wn * 32 + (lane & 15)) * SPAD * 2 + (lane >> 4) * 16);

    // issue one chunk's async loads into buffer (c&1)
    auto issue = [&](int c) {
        int pass = c >> 3;
        int kb = (c & 7) * 64;
        const unsigned short* Ap = (pass == 2) ? g_Al : g_Ah;
        const unsigned short* Bp = (pass == 1) ? g_Bl : g_Bh;
        uint32_t dA = sbase + (uint32_t)(c & 1) * (2 * TILE_B);
        uint32_t dB = dA + TILE_B;
        #pragma unroll
        for (int u = 0; u < 4; u++) {
            int unit = u * 256 + tid;
            int row = unit >> 3, seg = unit & 7;
            uint32_t so = (uint32_t)(row * (SPAD * 2) + seg * 16);
            cp_async16(dA + so, Ap + (size_t)(mblk + row) * 512 + kb + seg * 8);
            cp_async16(dB + so, Bp + (size_t)(nblk + row) * 512 + kb + seg * 8);
        }
        asm volatile("cp.async.commit_group;" ::: "memory");
    };

    float acc[4][4][4];
    #pragma unroll
    for (int i = 0; i < 4; i++)
        #pragma unroll
        for (int j = 0; j < 4; j++)
            #pragma unroll
            for (int k = 0; k < 4; k++) acc[i][j][k] = 0.f;

    issue(0);
    for (int c = 0; c < 24; c++) {
        if (c < 23) {
            issue(c + 1);
            asm volatile("cp.async.wait_group 1;" ::: "memory");
        } else {
            asm volatile("cp.async.wait_group 0;" ::: "memory");
        }
        __syncthreads();

        uint32_t abase = sbase + (uint32_t)(c & 1) * (2 * TILE_B) + aoff;
        uint32_t bbase = sbase + (uint32_t)(c & 1) * (2 * TILE_B) + TILE_B + boff;
        #pragma unroll
        for (int ks = 0; ks < 4; ks++) {
            uint32_t afr[4][4];
            #pragma unroll
            for (int mf = 0; mf < 4; mf++)
                ldm_x4(afr[mf], abase + (uint32_t)(mf * 16 * SPAD * 2 + ks * 32));
            uint32_t bfr[2][4];
            #pragma unroll
            for (int g = 0; g < 2; g++)
                ldm_x4(bfr[g], bbase + (uint32_t)(g * 16 * SPAD * 2 + ks * 32));
            #pragma unroll
            for (int mf = 0; mf < 4; mf++)
                #pragma unroll
                for (int nf = 0; nf < 4; nf++)
                    mma_bf16(acc[mf][nf], afr[mf],
                             bfr[nf >> 1][nf & 1], bfr[nf >> 1][(nf & 1) + 2]);
        }
        __syncthreads();   // buffer (c&1) free for issue(c+2) next iteration
    }

    #pragma unroll
    for (int mf = 0; mf < 4; mf++) {
        int r0 = mblk + wm * 64 + mf * 16 + (lane >> 2);
        #pragma unroll
        for (int half = 0; half < 2; half++) {
            int r = r0 + half * 8;
            int tt = r >> 5, b2 = r & 31;
            float* orow = outp + (size_t)(b2 * TT + tt) * VV + nblk + wn * 32 + (lane & 3) * 2;
            #pragma unroll
            for (int nf = 0; nf < 4; nf++) {
                float2 v = make_float2(acc[mf][nf][2 * half], acc[mf][nf][2 * half + 1]);
                *(float2*)(orow + nf * 8) = v;
            }
        }
    }
}

// ---------------- host launch ----------------
extern "C" void kernel_launch(void* const* d_in, const int* in_sizes, int n_in,
                              void* d_out, int out_size)
{
    const float* src_memory  = (const float*)d_in[0];
    const void*  src_mask    = d_in[1];
    const float* init_hidden = (const float*)d_in[2];
    const float* init_cell   = (const float*)d_in[3];
    const float* init_output = (const float*)d_in[4];
    const void*  trg         = d_in[5];
    const float* emb         = (const float*)d_in[6];
    const float* W_ih        = (const float*)d_in[7];
    const float* W_hh        = (const float*)d_in[8];
    const float* b_ih        = (const float*)d_in[9];
    const float* b_hh        = (const float*)d_in[10];
    const float* Wq          = (const float*)d_in[11];
    const float* bq          = (const float*)d_in[12];
    const float* Wb          = (const float*)d_in[13];
    const float* bbias       = (const float*)d_in[14];
    const float* Wo1         = (const float*)d_in[15];
    const float* bo1         = (const float*)d_in[16];
    const float* Wo2         = (const float*)d_in[17];
    const float* bo2         = (const float*)d_in[18];

    float *p_out;
    unsigned short *p_Bh, *p_Bl, *p_Ah, *p_Al;
    cudaGetSymbolAddress((void**)&p_out, g_out);
    cudaGetSymbolAddress((void**)&p_Bh,  g_Bh);
    cudaGetSymbolAddress((void**)&p_Bl,  g_Bl);
    cudaGetSymbolAddress((void**)&p_Ah,  g_Ah);
    cudaGetSymbolAddress((void**)&p_Al,  g_Al);

    static int smem_set = 0;
    if (!smem_set) {
        cudaFuncSetAttribute(logits_mma, cudaFuncAttributeMaxDynamicSharedMemorySize,
                             4 * TILE_B);
        smem_set = 1;
    }

    // #1
    prep1<<<3393, 256>>>((const int*)trg, (const int*)src_mask, init_hidden, init_cell,
                         Wq, Wb, bq, bbias, W_ih, W_hh, b_ih, b_hh, init_output, bo2);
    // #2
    prep2<<<1056, 256>>>(src_memory, src_mask, W_ih, Wo2);
    // #3
    {
        int n4 = (VV * EE) / 4;
        conv_split<<<(n4 + 255) / 256, 256>>>(emb, p_Bh, p_Bl, n4);
    }
    // #4: ncu probe — 32-CTA mini logits_mma (output overwritten by full run below)
    logits_mma<<<dim3(16, 2), 256, 4 * TILE_B>>>((float*)d_out);
    // #5
    decoder_loop<<<NBLK, 256>>>(emb, trg, src_memory, Wo1, bo1);
    // #6
    out_gemm<<<dim3(EE / 64, (TT * BB) / 64), 256>>>(Wo2, bo2);
    // #7
    {
        int n4 = (TT * BB * EE) / 4;
        conv_split<<<(n4 + 255) / 256, 256>>>(p_out, p_Ah, p_Al, n4);
    }
    // #8
    logits_mma<<<dim3(16, 250), 256, 4 * TILE_B>>>((float*)d_out);
}

// round 10
// speedup vs baseline: 1.9324x; 1.9324x over previous
#include <cuda_runtime.h>
#include <cuda_bf16.h>
#include <math.h>
#include <stdint.h>

// Problem dims
#define BB  32
#define SS  100
#define TT  64
#define HH  512
#define EE  512
#define VV  32000
#define G4H 2048
#define KZ  1536     // E (emb) + H (u) + H (h)
#define NBLK 128

// ---------------- device scratch ----------------
__device__ float2 g_W4p[1024 * KZ];  // paired gate weights: pair pi=(blk*8+w) -> rows (blk*16+w, +8)
__device__ float g_b4[G4H];
__device__ float g_c0[G4H * BB];     // W_O @ init_output (t=0 bias), [rr][b]
__device__ float g_wob2[G4H];        // W_O @ bo2 (t>0 bias)
__device__ float g_Wqb[HH * HH];     // Wb @ Wq
__device__ float g_bqb[HH];          // Wb @ bq + bb
__device__ float g_P[BB * SS * HH];  // mem @ Wqb
__device__ float g_q0[BB * SS];      // bqb.mem with mask folded
__device__ float g_M2[(size_t)SS * HH * BB]; // [s][r][b] = Wo1_ctx . mem[b,s]
__device__ float g_w[SS * BB];       // softmax weights [s][b]
__device__ float g_h[2][BB * HH];
__device__ float g_c[BB * HH];
__device__ float g_uall[TT * BB * HH]; // all u_t  (m = t*B+b)
__device__ float g_out[TT * BB * EE];  // out = uall @ Wo2^T + bo2
__device__ int   g_trg64;
__device__ int   g_maskty;

__device__ volatile unsigned g_cnt;
__device__ volatile unsigned g_gen;

__device__ unsigned short g_Bh[(size_t)VV * EE];
__device__ unsigned short g_Bl[(size_t)VV * EE];
__device__ unsigned short g_Ah[(size_t)TT * BB * EE];
__device__ unsigned short g_Al[(size_t)TT * BB * EE];

// ---------------- helpers ----------------
__device__ __forceinline__ uint32_t smem_u32(const void* p) {
    uint32_t a;
    asm("{ .reg .u64 t; cvta.to.shared.u64 t, %1; cvt.u32.u64 %0, t; }" : "=r"(a) : "l"(p));
    return a;
}
__device__ __forceinline__ void ldm_x4(uint32_t* r, uint32_t addr) {
    asm volatile("ldmatrix.sync.aligned.m8n8.x4.shared.b16 {%0,%1,%2,%3}, [%4];"
                 : "=r"(r[0]), "=r"(r[1]), "=r"(r[2]), "=r"(r[3]) : "r"(addr));
}
__device__ __forceinline__ void mma_bf16(float* d, const uint32_t* a, uint32_t b0, uint32_t b1) {
    asm volatile(
        "mma.sync.aligned.m16n8k16.row.col.f32.bf16.bf16.f32 "
        "{%0,%1,%2,%3}, {%4,%5,%6,%7}, {%8,%9}, {%0,%1,%2,%3};"
        : "+f"(d[0]), "+f"(d[1]), "+f"(d[2]), "+f"(d[3])
        : "r"(a[0]), "r"(a[1]), "r"(a[2]), "r"(a[3]), "r"(b0), "r"(b1));
}
__device__ __forceinline__ void cp_async16(uint32_t smem_dst, const void* gsrc) {
    asm volatile("cp.async.cg.shared.global [%0], [%1], 16;"
                 :: "r"(smem_dst), "l"(gsrc) : "memory");
}

// R6/R8-proven barrier: nanosleep backoff spin
__device__ __forceinline__ void gsync() {
    __syncthreads();
    if (threadIdx.x == 0) {
        unsigned gen = g_gen;
        __threadfence();
        if (atomicAdd((unsigned*)&g_cnt, 1u) == NBLK - 1) {
            g_cnt = 0;
            __threadfence();
            g_gen = gen + 1;
        } else {
            while (g_gen == gen) __nanosleep(20);
        }
        __threadfence();
    }
    __syncthreads();
}

__device__ __forceinline__ int jmap(int rr) { return (rr & 3) * HH + (rr >> 2); }

// ---------------- prep1 ----------------
// blocks: [0] detect+init | [1,1025) wqb | [1025,1281) c0 | [1281,1345) wob2 | [1345,2369) w4 pairs
__global__ void __launch_bounds__(256) prep1(
    const int* __restrict__ trg_w, const int* __restrict__ mask_w,
    const float* __restrict__ ih, const float* __restrict__ ic,
    const float* __restrict__ Wq, const float* __restrict__ Wb,
    const float* __restrict__ bq, const float* __restrict__ bbias,
    const float* __restrict__ Wih, const float* __restrict__ Whh,
    const float* __restrict__ bih, const float* __restrict__ bhh,
    const float* __restrict__ init_output, const float* __restrict__ bo2)
{
    int bid = blockIdx.x, tid = threadIdx.x;
    int wid = tid >> 5, lane = tid & 31;

    if (bid == 0) {
        __shared__ int s_odd_nz, s_bin, s_f32;
        if (tid == 0) { s_odd_nz = 0; s_bin = 1; s_f32 = 1; }
        __syncthreads();
        for (int i = tid; i < (BB * TT) / 2; i += 256)
            if (trg_w[2 * i + 1] != 0) atomicOr(&s_odd_nz, 1);
        for (int i = tid; i < (BB * SS) / 4; i += 256) {
            int v = mask_w[i];
            if (v != 0 && v != 1)           atomicAnd(&s_bin, 0);
            if (v != 0 && v != 0x3f800000)  atomicAnd(&s_f32, 0);
        }
        for (int i = tid; i < BB * HH; i += 256) { g_h[0][i] = ih[i]; g_c[i] = ic[i]; }
        __syncthreads();
        if (tid == 0) {
            g_trg64 = s_odd_nz ? 0 : 1;
            g_maskty = s_bin ? 1 : (s_f32 ? 2 : 0);
        }
    } else if (bid < 1025) {
        int idx = bid - 1;
        int by = idx >> 5, bx = idx & 31;
        int ty = tid >> 4, tx = tid & 15;
        int r = by * 16 + ty, c = bx * 16 + tx;
        float acc = 0.f;
        for (int k = 0; k < HH; k++) acc += Wb[r * HH + k] * Wq[k * HH + c];
        g_Wqb[r * HH + c] = acc;
        if (bx == 0 && tx == 0) {
            float a = bbias[r];
            for (int k = 0; k < HH; k++) a += Wb[r * HH + k] * bq[k];
            g_bqb[r] = a;
        }
    } else if (bid < 1281) {
        int idx = bid - 1025;
        int rr = idx * 8 + wid;
        int j = jmap(rr);
        const float* wrow = Wih + (size_t)j * (2 * EE) + EE;
        for (int b = 0; b < BB; b++) {
            const float* io = init_output + (size_t)b * EE;
            float a = 0.f;
            for (int e = lane; e < EE; e += 32) a += wrow[e] * io[e];
            #pragma unroll
            for (int off = 16; off; off >>= 1) a += __shfl_down_sync(0xffffffffu, a, off);
            if (lane == 0) g_c0[rr * BB + b] = a;
        }
    } else if (bid < 1345) {
        int idx = bid - 1281;
        for (int q = 0; q < 4; q++) {
            int rr = idx * 32 + wid * 4 + q;
            int j = jmap(rr);
            const float* wrow = Wih + (size_t)j * (2 * EE) + EE;
            float a = 0.f;
            for (int e = lane; e < EE; e += 32) a += wrow[e] * bo2[e];
            #pragma unroll
            for (int off = 16; off; off >>= 1) a += __shfl_down_sync(0xffffffffu, a, off);
            if (lane == 0) g_wob2[rr] = a;
        }
    } else {
        // paired gate weights (outer columns: emb + hh) + biases
        int pi = bid - 1345;                 // 0..1023
        int bq2 = pi >> 3, w = pi & 7;
        int rrA = bq2 * 16 + w, rrB = rrA + 8;
        int jA = jmap(rrA), jB = jmap(rrB);
        for (int k = tid; k < KZ; k += 256) {
            float a, bv;
            if (k < EE) {
                a  = Wih[(size_t)jA * (2 * EE) + k];
                bv = Wih[(size_t)jB * (2 * EE) + k];
            } else if (k >= 2 * EE) {
                a  = Whh[(size_t)jA * HH + (k - 2 * EE)];
                bv = Whh[(size_t)jB * HH + (k - 2 * EE)];
            } else continue;                 // middle (W_U) filled by prep2
            g_W4p[(size_t)pi * KZ + k] = make_float2(a, bv);
        }
        if (tid == 0) g_b4[rrA] = bih[jA] + bhh[jA];
        if (tid == 1) g_b4[rrB] = bih[jB] + bhh[jB];
    }
}

// ---------------- prep2 ----------------
// blocks: [0,400) P | [400,800) q0 | [800,1056) W_U | [1056,1456) M2
__global__ void __launch_bounds__(256) prep2(
    const float* __restrict__ mem, const void* __restrict__ mask_raw,
    const float* __restrict__ Wih, const float* __restrict__ Wo2,
    const float* __restrict__ Wo1)
{
    __shared__ float As[16][68];
    __shared__ float Bs[16][68];
    int bid = blockIdx.x, tid = threadIdx.x;

    if (bid < 400) {
        // P = mem_flat(3200,512) @ Wqb(512,512)
        int m0 = (bid >> 3) * 64, j0 = (bid & 7) * 64;
        int tx = tid & 15, ty = tid >> 4;
        float acc[4][4];
        #pragma unroll
        for (int i = 0; i < 4; i++)
            #pragma unroll
            for (int j = 0; j < 4; j++) acc[i][j] = 0.f;
        for (int k0 = 0; k0 < HH; k0 += 16) {
            int row = tid >> 2, kq = (tid & 3) * 4;
            float4 va = *(const float4*)(mem + (size_t)(m0 + row) * HH + k0 + kq);
            As[kq][row] = va.x; As[kq + 1][row] = va.y;
            As[kq + 2][row] = va.z; As[kq + 3][row] = va.w;
            int kr = tid >> 4, jq = (tid & 15) * 4;
            float4 vb = *(const float4*)(g_Wqb + (size_t)(k0 + kr) * HH + j0 + jq);
            *(float4*)&Bs[kr][jq] = vb;
            __syncthreads();
            #pragma unroll
            for (int k = 0; k < 16; k++) {
                float a[4], b[4];
                #pragma unroll
                for (int i = 0; i < 4; i++) a[i] = As[k][ty * 4 + i];
                #pragma unroll
                for (int i = 0; i < 4; i++) b[i] = Bs[k][tx * 4 + i];
                #pragma unroll
                for (int i = 0; i < 4; i++)
                    #pragma unroll
                    for (int j = 0; j < 4; j++) acc[i][j] += a[i] * b[j];
            }
            __syncthreads();
        }
        #pragma unroll
        for (int i = 0; i < 4; i++)
            #pragma unroll
            for (int j = 0; j < 4; j++)
                g_P[(size_t)(m0 + ty * 4 + i) * HH + j0 + tx * 4 + j] = acc[i][j];
    } else if (bid < 800) {
        int m = (bid - 400) * 8 + (tid >> 5);
        int l = tid & 31;
        if (m < BB * SS) {
            float a = 0.f;
            for (int k = l; k < HH; k += 32) a += g_bqb[k] * mem[(size_t)m * HH + k];
            #pragma unroll
            for (int off = 16; off; off >>= 1) a += __shfl_down_sync(0xffffffffu, a, off);
            if (l == 0) {
                int mty = g_maskty;
                bool mv;
                if      (mty == 0) mv = ((const unsigned char*)mask_raw)[m] != 0;
                else if (mty == 1) mv = ((const int*)mask_raw)[m] != 0;
                else               mv = ((const float*)mask_raw)[m] != 0.0f;
                g_q0[m] = mv ? a : -1e9f;
            }
        }
    } else if (bid < 1056) {
        // W_U[rr][h] = sum_e W_O[rr,e]*Wo2[e,h] -> paired middle columns of g_W4p
        int idx = bid - 800;
        int r0 = (idx >> 3) * 64, h0 = (idx & 7) * 64;
        int tx = tid & 15, ty = tid >> 4;
        float acc[4][4];
        #pragma unroll
        for (int i = 0; i < 4; i++)
            #pragma unroll
            for (int j = 0; j < 4; j++) acc[i][j] = 0.f;
        for (int k0 = 0; k0 < EE; k0 += 16) {
            int row = tid >> 2, kq = (tid & 3) * 4;
            int j = jmap(r0 + row);
            float4 va = *(const float4*)(Wih + (size_t)j * (2 * EE) + EE + k0 + kq);
            As[kq][row] = va.x; As[kq + 1][row] = va.y;
            As[kq + 2][row] = va.z; As[kq + 3][row] = va.w;
            int kr = tid >> 4, jq = (tid & 15) * 4;
            float4 vb = *(const float4*)(Wo2 + (size_t)(k0 + kr) * HH + h0 + jq);
            *(float4*)&Bs[kr][jq] = vb;
            __syncthreads();
            #pragma unroll
            for (int k = 0; k < 16; k++) {
                float a[4], b[4];
                #pragma unroll
                for (int i = 0; i < 4; i++) a[i] = As[k][ty * 4 + i];
                #pragma unroll
                for (int i = 0; i < 4; i++) b[i] = Bs[k][tx * 4 + i];
                #pragma unroll
                for (int i = 0; i < 4; i++)
                    #pragma unroll
                    for (int jj = 0; jj < 4; jj++) acc[i][jj] += a[i] * b[jj];
            }
            __syncthreads();
        }
        #pragma unroll
        for (int i = 0; i < 4; i++) {
            int rr = r0 + ty * 4 + i;
            size_t pbase = ((size_t)((rr >> 4) * 8 + (rr & 7)) * KZ);
            int half = (rr >> 3) & 1;
            #pragma unroll
            for (int jj = 0; jj < 4; jj++) {
                int h = h0 + tx * 4 + jj;
                ((float*)g_W4p)[(pbase + EE + h) * 2 + half] = acc[i][jj];
            }
        }
    } else {
        // M2[s][r][b] = Wo1_ctx(512r x 512h) . mem[b,s,:]
        int idx = bid - 1056;
        int m0 = (idx >> 3) * 64, r0j = (idx & 7) * 64;
        int tx = tid & 15, ty = tid >> 4;
        float acc[4][4];
        #pragma unroll
        for (int i = 0; i < 4; i++)
            #pragma unroll
            for (int j = 0; j < 4; j++) acc[i][j] = 0.f;
        for (int k0 = 0; k0 < HH; k0 += 16) {
            int row = tid >> 2, kq = (tid & 3) * 4;
            float4 va = *(const float4*)(mem + (size_t)(m0 + row) * HH + k0 + kq);
            As[kq][row] = va.x; As[kq + 1][row] = va.y;
            As[kq + 2][row] = va.z; As[kq + 3][row] = va.w;
            float4 vb = *(const float4*)(Wo1 + (size_t)(r0j + row) * (2 * HH) + HH + k0 + kq);
            Bs[kq][row] = vb.x; Bs[kq + 1][row] = vb.y;
            Bs[kq + 2][row] = vb.z; Bs[kq + 3][row] = vb.w;
            __syncthreads();
            #pragma unroll
            for (int k = 0; k < 16; k++) {
                float a[4], b[4];
                #pragma unroll
                for (int i = 0; i < 4; i++) a[i] = As[k][ty * 4 + i];
                #pragma unroll
                for (int i = 0; i < 4; i++) b[i] = Bs[k][tx * 4 + i];
                #pragma unroll
                for (int i = 0; i < 4; i++)
                    #pragma unroll
                    for (int j = 0; j < 4; j++) acc[i][j] += a[i] * b[j];
            }
            __syncthreads();
        }
        #pragma unroll
        for (int i = 0; i < 4; i++) {
            int m = m0 + ty * 4 + i;
            int b = m / SS, s = m - b * SS;
            #pragma unroll
            for (int j = 0; j < 4; j++) {
                int r = r0j + tx * 4 + j;
                g_M2[((size_t)s * HH + r) * BB + b] = acc[i][j];
            }
        }
    }
}

// split fp32 -> bf16 hi + lo
__global__ void conv_split(const float* __restrict__ src,
                           unsigned short* __restrict__ hi,
                           unsigned short* __restrict__ lo, int n4) {
    int i = blockIdx.x * 256 + threadIdx.x;
    if (i >= n4) return;
    float4 v = ((const float4*)src)[i];
    __nv_bfloat16 h0 = __float2bfloat16(v.x);
    __nv_bfloat16 h1 = __float2bfloat16(v.y);
    __nv_bfloat16 h2 = __float2bfloat16(v.z);
    __nv_bfloat16 h3 = __float2bfloat16(v.w);
    __nv_bfloat16 l0 = __float2bfloat16(v.x - __bfloat162float(h0));
    __nv_bfloat16 l1 = __float2bfloat16(v.y - __bfloat162float(h1));
    __nv_bfloat16 l2 = __float2bfloat16(v.z - __bfloat162float(h2));
    __nv_bfloat16 l3 = __float2bfloat16(v.w - __bfloat162float(h3));
    __nv_bfloat162* H = (__nv_bfloat162*)hi;
    __nv_bfloat162* L = (__nv_bfloat162*)lo;
    H[2 * i]     = __halves2bfloat162(h0, h1);
    H[2 * i + 1] = __halves2bfloat162(h2, h3);
    L[2 * i]     = __halves2bfloat162(l0, l1);
    L[2 * i + 1] = __halves2bfloat162(l2, l3);
}

// ---------------- persistent decoder loop (3 barriers/step) ----------------
__global__ void __launch_bounds__(256) decoder_loop(
    const float* __restrict__ emb, const void* __restrict__ trg_raw,
    const float* __restrict__ Wo1, const float* __restrict__ bo1)
{
    __shared__ union {
        struct { float Zs[32][65]; float2 Wp[64][8]; float Gs[16][33]; int tok[BB]; } a;
        struct { float q[HH]; float sc[112]; } c;
        struct { float Zs[32][257]; float Ws[4][257]; float red[4][32]; } d;
    } sm;

    int tid = threadIdx.x, wid = tid >> 5, lane = tid & 31;
    int bid = blockIdx.x;
    int w3 = wid & 3, kh = wid >> 2;

    for (int t = 0; t < TT; t++) {
        const float* u_prev = g_uall + (size_t)(t - 1) * BB * HH;   // unused at t=0
        const float* h_prev = g_h[t & 1];
        float*       h_cur  = g_h[(t + 1) & 1];

        // ---- Phase A: gates = W_E emb + W_U u_prev + W_hh h_prev + bias; LSTM ----
        {
            if (tid < BB) {
                long long v;
                if (g_trg64) v = ((const long long*)trg_raw)[tid * TT + t];
                else         v = ((const int*)trg_raw)[tid * TT + t];
                int tk = (int)v;
                if (tk < 0) tk = 0;
                if (tk >= VV) tk = VV - 1;
                sm.a.tok[tid] = tk;
            }
            __syncthreads();

            float a0 = 0.f, a1 = 0.f, a2 = 0.f, a3 = 0.f;
            for (int kt = 0; kt < KZ / 64; kt++) {
                int kg0 = kt * 64;
                int mode = (kt < 8) ? 0 : (kt < 16) ? 1 : 2;
                // Z tile: batch-major [32][65], float4 loads + scalar stores
                #pragma unroll
                for (int u2 = 0; u2 < 2; u2++) {
                    int slot = u2 * 256 + tid;
                    int b = slot >> 4, c4 = (slot & 15) * 4;
                    float4 v;
                    if (mode == 0)
                        v = *(const float4*)(emb + (size_t)sm.a.tok[b] * EE + kg0 + c4);
                    else if (mode == 1)
                        v = (t == 0) ? make_float4(0.f, 0.f, 0.f, 0.f)
                                     : *(const float4*)(u_prev + b * HH + (kg0 - EE) + c4);
                    else
                        v = *(const float4*)(h_prev + b * HH + (kg0 - 2 * EE) + c4);
                    float* zr = &sm.a.Zs[b][c4];
                    zr[0] = v.x; zr[1] = v.y; zr[2] = v.z; zr[3] = v.w;
                }
                // W tile: paired float2 rows, float4 loads
                {
                    int p = tid >> 5, kq = (tid & 31) * 2;
                    float4 wv4 = *(const float4*)(g_W4p + (size_t)(bid * 8 + p) * KZ + kg0 + kq);
                    sm.a.Wp[kq][p]     = make_float2(wv4.x, wv4.y);
                    sm.a.Wp[kq + 1][p] = make_float2(wv4.z, wv4.w);
                }
                __syncthreads();
                #pragma unroll
                for (int kk = 0; kk < 64; kk += 2) {
                    float z0 = sm.a.Zs[lane][kk], z1 = sm.a.Zs[lane][kk + 1];
                    float2 w0 = sm.a.Wp[kk][wid], w1 = sm.a.Wp[kk + 1][wid];
                    a0 += w0.x * z0; a1 += w0.y * z0;
                    a2 += w1.x * z1; a3 += w1.y * z1;
                }
                __syncthreads();
            }
            {
                int rbase = bid * 16;
                int r0 = rbase + wid, r1 = rbase + wid + 8;
                float e0 = (t == 0) ? g_c0[r0 * BB + lane] : g_wob2[r0];
                float e1 = (t == 0) ? g_c0[r1 * BB + lane] : g_wob2[r1];
                sm.a.Gs[wid][lane]     = a0 + a2 + g_b4[r0] + e0;
                sm.a.Gs[wid + 8][lane] = a1 + a3 + g_b4[r1] + e1;
            }
            __syncthreads();

            if (tid < 128) {
                int hl = tid >> 5, b = tid & 31;
                float gi = sm.a.Gs[4 * hl + 0][b];
                float gf = sm.a.Gs[4 * hl + 1][b];
                float gg = sm.a.Gs[4 * hl + 2][b];
                float go = sm.a.Gs[4 * hl + 3][b];
                gi = 1.f / (1.f + expf(-gi));
                gf = 1.f / (1.f + expf(-gf));
                go = 1.f / (1.f + expf(-go));
                gg = tanhf(gg);
                int h = bid * 4 + hl;
                int idx = b * HH + h;
                float c = gf * g_c[idx] + gi * gg;
                g_c[idx] = c;
                h_cur[idx] = go * tanhf(c);
            }
        }
        gsync();

        // ---- Phase C: scores + softmax only (4 blocks/batch; slice-write weights) ----
        {
            int b = bid & 31;
            int slice = bid >> 5;          // 0..3 -> writes s in [slice*25, slice*25+25)
            for (int i = tid; i < HH; i += 256) sm.c.q[i] = h_cur[b * HH + i];
            __syncthreads();

            for (int s = wid; s < SS; s += 8) {
                const float* prow = g_P + (size_t)(b * SS + s) * HH;
                float a = 0.f;
                for (int k = lane; k < HH; k += 32) a += sm.c.q[k] * prow[k];
                #pragma unroll
                for (int off = 16; off; off >>= 1) a += __shfl_down_sync(0xffffffffu, a, off);
                if (lane == 0) sm.c.sc[s] = a + g_q0[b * SS + s];
            }
            __syncthreads();

            if (wid == 0) {
                float m = -1e30f;
                for (int s = lane; s < SS; s += 32) m = fmaxf(m, sm.c.sc[s]);
                #pragma unroll
                for (int off = 16; off; off >>= 1) m = fmaxf(m, __shfl_xor_sync(0xffffffffu, m, off));
                float sum = 0.f;
                for (int s = lane; s < SS; s += 32) {
                    float e = expf(sm.c.sc[s] - m); sm.c.sc[s] = e; sum += e;
                }
                #pragma unroll
                for (int off = 16; off; off >>= 1) sum += __shfl_xor_sync(0xffffffffu, sum, off);
                float inv = 1.f / sum;
                for (int s = lane; s < SS; s += 32) sm.c.sc[s] *= inv;
            }
            __syncthreads();

            if (tid < 25) {
                int s = slice * 25 + tid;
                g_w[s * BB + b] = sm.c.sc[s];
            }
        }
        gsync();

        // ---- Phase D1: u = tanh(Wo1_h.h + sum_s w*M2 + bo1); 4 rows/block ----
        {
            int r0 = bid * 4;
            float acc = 0.f;
            #pragma unroll
            for (int stg = 0; stg < 2; stg++) {
                int koff = stg * 256;
                // stage h chunk [koff, koff+256) into Zs[32][257]
                #pragma unroll
                for (int u2 = 0; u2 < 8; u2++) {
                    int slot = u2 * 256 + tid;
                    int b = slot >> 6, c4 = (slot & 63) * 4;
                    float4 v = *(const float4*)(h_cur + b * HH + koff + c4);
                    float* zr = &sm.d.Zs[b][c4];
                    zr[0] = v.x; zr[1] = v.y; zr[2] = v.z; zr[3] = v.w;
                }
                {
                    int r = tid >> 6, c4 = (tid & 63) * 4;
                    float4 v = *(const float4*)(Wo1 + (size_t)(r0 + r) * (2 * HH) + koff + c4);
                    float* wr = &sm.d.Ws[r][c4];
                    wr[0] = v.x; wr[1] = v.y; wr[2] = v.z; wr[3] = v.w;
                }
                __syncthreads();
                int kl = kh * 128;
                float pa = 0.f, pb = 0.f;
                #pragma unroll
                for (int kk = 0; kk < 128; kk += 2) {
                    pa += sm.d.Ws[w3][kl + kk]     * sm.d.Zs[lane][kl + kk];
                    pb += sm.d.Ws[w3][kl + kk + 1] * sm.d.Zs[lane][kl + kk + 1];
                }
                acc += pa + pb;
                __syncthreads();
            }
            // kh=0 warps add the attention-context contribution via M2
            if (kh == 0) {
                int r = r0 + w3;
                float sa = 0.f, sb = 0.f;
                #pragma unroll 2
                for (int s = 0; s < SS; s += 2) {
                    sa += g_w[s * BB + lane] * g_M2[((size_t)s * HH + r) * BB + lane];
                    sb += g_w[(s + 1) * BB + lane] * g_M2[((size_t)(s + 1) * HH + r) * BB + lane];
                }
                acc += sa + sb;
            }
            if (kh == 1) sm.d.red[w3][lane] = acc;
            __syncthreads();
            if (kh == 0) {
                int r = r0 + w3;
                float tot = acc + sm.d.red[w3][lane] + bo1[r];
                g_uall[((size_t)t * BB + lane) * HH + r] = tanhf(tot);
            }
        }
        gsync();
    }
}

// ---------------- out = uall(2048,512) @ Wo2(512,512)^T + bo2 ----------------
__global__ void __launch_bounds__(256) out_gemm(const float* __restrict__ Wo2,
                                                const float* __restrict__ bo2)
{
    __shared__ float As[16][68];
    __shared__ float Bs[16][68];
    int tid = threadIdx.x;
    int m0 = blockIdx.y * 64, e0 = blockIdx.x * 64;
    int tx = tid & 15, ty = tid >> 4;

    float acc[4][4];
    #pragma unroll
    for (int i = 0; i < 4; i++)
        #pragma unroll
        for (int j = 0; j < 4; j++) acc[i][j] = 0.f;

    for (int k0 = 0; k0 < HH; k0 += 16) {
        int row = tid >> 2, kq = (tid & 3) * 4;
        float4 va = *(const float4*)(g_uall + (size_t)(m0 + row) * HH + k0 + kq);
        As[kq][row] = va.x; As[kq + 1][row] = va.y;
        As[kq + 2][row] = va.z; As[kq + 3][row] = va.w;
        float4 vb = *(const float4*)(Wo2 + (size_t)(e0 + row) * HH + k0 + kq);
        Bs[kq][row] = vb.x; Bs[kq + 1][row] = vb.y;
        Bs[kq + 2][row] = vb.z; Bs[kq + 3][row] = vb.w;
        __syncthreads();
        #pragma unroll
        for (int k = 0; k < 16; k++) {
            float a[4], b[4];
            #pragma unroll
            for (int i = 0; i < 4; i++) a[i] = As[k][ty * 4 + i];
            #pragma unroll
            for (int i = 0; i < 4; i++) b[i] = Bs[k][tx * 4 + i];
            #pragma unroll
            for (int i = 0; i < 4; i++)
                #pragma unroll
                for (int j = 0; j < 4; j++) acc[i][j] += a[i] * b[j];
        }
        __syncthreads();
    }
    #pragma unroll
    for (int i = 0; i < 4; i++)
        #pragma unroll
        for (int j = 0; j < 4; j++)
            g_out[(size_t)(m0 + ty * 4 + i) * EE + e0 + tx * 4 + j] =
                acc[i][j] + bo2[e0 + tx * 4 + j];
}

// ---------------- HMMA logits GEMM (cp.async double-buffered) ----------------
#define SPAD 72
#define TILE_B (128 * SPAD * 2)
__global__ void __launch_bounds__(256) logits_mma(float* __restrict__ outp)
{
    extern __shared__ __align__(16) unsigned char dynsm[];

    int tid = threadIdx.x, lane = tid & 31, wid = tid >> 5;
    int wm = wid >> 2;
    int wn = wid & 3;
    int mblk = blockIdx.x * 128;
    int nblk = blockIdx.y * 128;

    uint32_t sbase = smem_u32(dynsm);
    uint32_t aoff = (uint32_t)((wm * 64 + (lane & 15)) * SPAD * 2 + (lane >> 4) * 16);
    uint32_t boff = (uint32_t)((wn * 32 + (lane & 15)) * SPAD * 2 + (lane >> 4) * 16);

    auto issue = [&](int c) {
        int pass = c >> 3;
        int kb = (c & 7) * 64;
        const unsigned short* Ap = (pass == 2) ? g_Al : g_Ah;
        const unsigned short* Bp = (pass == 1) ? g_Bl : g_Bh;
        uint32_t dA = sbase + (uint32_t)(c & 1) * (2 * TILE_B);
        uint32_t dB = dA + TILE_B;
        #pragma unroll
        for (int u = 0; u < 4; u++) {
            int unit = u * 256 + tid;
            int row = unit >> 3, seg = unit & 7;
            uint32_t so = (uint32_t)(row * (SPAD * 2) + seg * 16);
            cp_async16(dA + so, Ap + (size_t)(mblk + row) * 512 + kb + seg * 8);
            cp_async16(dB + so, Bp + (size_t)(nblk + row) * 512 + kb + seg * 8);
        }
        asm volatile("cp.async.commit_group;" ::: "memory");
    };

    float acc[4][4][4];
    #pragma unroll
    for (int i = 0; i < 4; i++)
        #pragma unroll
        for (int j = 0; j < 4; j++)
            #pragma unroll
            for (int k = 0; k < 4; k++) acc[i][j][k] = 0.f;

    issue(0);
    for (int c = 0; c < 24; c++) {
        if (c < 23) {
            issue(c + 1);
            asm volatile("cp.async.wait_group 1;" ::: "memory");
        } else {
            asm volatile("cp.async.wait_group 0;" ::: "memory");
        }
        __syncthreads();

        uint32_t abase = sbase + (uint32_t)(c & 1) * (2 * TILE_B) + aoff;
        uint32_t bbase = sbase + (uint32_t)(c & 1) * (2 * TILE_B) + TILE_B + boff;
        #pragma unroll
        for (int ks = 0; ks < 4; ks++) {
            uint32_t afr[4][4];
            #pragma unroll
            for (int mf = 0; mf < 4; mf++)
                ldm_x4(afr[mf], abase + (uint32_t)(mf * 16 * SPAD * 2 + ks * 32));
            uint32_t bfr[2][4];
            #pragma unroll
            for (int g = 0; g < 2; g++)
                ldm_x4(bfr[g], bbase + (uint32_t)(g * 16 * SPAD * 2 + ks * 32));
            #pragma unroll
            for (int mf = 0; mf < 4; mf++)
                #pragma unroll
                for (int nf = 0; nf < 4; nf++)
                    mma_bf16(acc[mf][nf], afr[mf],
                             bfr[nf >> 1][nf & 1], bfr[nf >> 1][(nf & 1) + 2]);
        }
        __syncthreads();
    }

    #pragma unroll
    for (int mf = 0; mf < 4; mf++) {
        int r0 = mblk + wm * 64 + mf * 16 + (lane >> 2);
        #pragma unroll
        for (int half = 0; half < 2; half++) {
            int r = r0 + half * 8;
            int tt = r >> 5, b2 = r & 31;
            float* orow = outp + (size_t)(b2 * TT + tt) * VV + nblk + wn * 32 + (lane & 3) * 2;
            #pragma unroll
            for (int nf = 0; nf < 4; nf++) {
                float2 v = make_float2(acc[mf][nf][2 * half], acc[mf][nf][2 * half + 1]);
                *(float2*)(orow + nf * 8) = v;
            }
        }
    }
}

// ---------------- host launch ----------------
extern "C" void kernel_launch(void* const* d_in, const int* in_sizes, int n_in,
                              void* d_out, int out_size)
{
    const float* src_memory  = (const float*)d_in[0];
    const void*  src_mask    = d_in[1];
    const float* init_hidden = (const float*)d_in[2];
    const float* init_cell   = (const float*)d_in[3];
    const float* init_output = (const float*)d_in[4];
    const void*  trg         = d_in[5];
    const float* emb         = (const float*)d_in[6];
    const float* W_ih        = (const float*)d_in[7];
    const float* W_hh        = (const float*)d_in[8];
    const float* b_ih        = (const float*)d_in[9];
    const float* b_hh        = (const float*)d_in[10];
    const float* Wq          = (const float*)d_in[11];
    const float* bq          = (const float*)d_in[12];
    const float* Wb          = (const float*)d_in[13];
    const float* bbias       = (const float*)d_in[14];
    const float* Wo1         = (const float*)d_in[15];
    const float* bo1         = (const float*)d_in[16];
    const float* Wo2         = (const float*)d_in[17];
    const float* bo2         = (const float*)d_in[18];

    float *p_out;
    unsigned short *p_Bh, *p_Bl, *p_Ah, *p_Al;
    cudaGetSymbolAddress((void**)&p_out, g_out);
    cudaGetSymbolAddress((void**)&p_Bh,  g_Bh);
    cudaGetSymbolAddress((void**)&p_Bl,  g_Bl);
    cudaGetSymbolAddress((void**)&p_Ah,  g_Ah);
    cudaGetSymbolAddress((void**)&p_Al,  g_Al);

    cudaFuncSetAttribute(logits_mma, cudaFuncAttributeMaxDynamicSharedMemorySize,
                         4 * TILE_B);

    // #1
    prep1<<<2369, 256>>>((const int*)trg, (const int*)src_mask, init_hidden, init_cell,
                         Wq, Wb, bq, bbias, W_ih, W_hh, b_ih, b_hh, init_output, bo2);
    // #2
    prep2<<<1456, 256>>>(src_memory, src_mask, W_ih, Wo2, Wo1);
    // #3
    {
        int n4 = (VV * EE) / 4;
        conv_split<<<(n4 + 255) / 256, 256>>>(emb, p_Bh, p_Bl, n4);
    }
    // #4 — profiled by ncu (-s 5 -c 1)
    decoder_loop<<<NBLK, 256>>>(emb, trg, Wo1, bo1);
    // #5
    out_gemm<<<dim3(EE / 64, (TT * BB) / 64), 256>>>(Wo2, bo2);
    // #6
    {
        int n4 = (TT * BB * EE) / 4;
        conv_split<<<(n4 + 255) / 256, 256>>>(p_out, p_Ah, p_Al, n4);
    }
    // #7
    logits_mma<<<dim3(16, 250), 256, 4 * TILE_B>>>((float*)d_out);
}

// round 11
// speedup vs baseline: 2.5080x; 1.2978x over previous
#include <cuda_runtime.h>
#include <cuda_bf16.h>
#include <math.h>
#include <stdint.h>

// Problem dims
#define BB  32
#define SS  100
#define TT  64
#define HH  512
#define EE  512
#define VV  32000
#define G4H 2048
#define KU  1024     // recurrent gate K: H (u) + H (h); emb part precomputed
#define NBLK 128

// ---------------- device scratch ----------------
__device__ float2 g_W4p[1024 * KU];  // paired gate weights [pair][k2]: k2<512 W_U, else W_hh
__device__ float g_b4[G4H];
__device__ float g_GE[(size_t)TT * G4H * BB]; // [t][rr][b] = W_E . emb[token[b,t]]
__device__ float g_c0[G4H * BB];     // W_O @ init_output (t=0 bias), [rr][b]
__device__ float g_wob2[G4H];        // W_O @ bo2 (t>0 bias)
__device__ float g_Wqb[HH * HH];     // Wb @ Wq
__device__ float g_bqb[HH];          // Wb @ bq + bb
__device__ float g_P[BB * SS * HH];  // mem @ Wqb
__device__ float g_q0[BB * SS];      // bqb.mem with mask folded
__device__ float g_M2[(size_t)SS * HH * BB]; // [s][r][b] = Wo1_ctx . mem[b,s]
__device__ float g_w[SS * BB];       // softmax weights [s][b]
__device__ float g_h[2][BB * HH];
__device__ float g_c[BB * HH];
__device__ float g_uall[TT * BB * HH];
__device__ float g_out[TT * BB * EE];
__device__ int   g_trg64;
__device__ int   g_maskty;

// tree barrier state
__device__ volatile unsigned g_leaf[8];
__device__ volatile unsigned g_root;
__device__ volatile unsigned g_gen;

__device__ unsigned short g_Bh[(size_t)VV * EE];
__device__ unsigned short g_Bl[(size_t)VV * EE];
__device__ unsigned short g_Ah[(size_t)TT * BB * EE];
__device__ unsigned short g_Al[(size_t)TT * BB * EE];

// ---------------- helpers ----------------
__device__ __forceinline__ uint32_t smem_u32(const void* p) {
    uint32_t a;
    asm("{ .reg .u64 t; cvta.to.shared.u64 t, %1; cvt.u32.u64 %0, t; }" : "=r"(a) : "l"(p));
    return a;
}
__device__ __forceinline__ void ldm_x4(uint32_t* r, uint32_t addr) {
    asm volatile("ldmatrix.sync.aligned.m8n8.x4.shared.b16 {%0,%1,%2,%3}, [%4];"
                 : "=r"(r[0]), "=r"(r[1]), "=r"(r[2]), "=r"(r[3]) : "r"(addr));
}
__device__ __forceinline__ void mma_bf16(float* d, const uint32_t* a, uint32_t b0, uint32_t b1) {
    asm volatile(
        "mma.sync.aligned.m16n8k16.row.col.f32.bf16.bf16.f32 "
        "{%0,%1,%2,%3}, {%4,%5,%6,%7}, {%8,%9}, {%0,%1,%2,%3};"
        : "+f"(d[0]), "+f"(d[1]), "+f"(d[2]), "+f"(d[3])
        : "r"(a[0]), "r"(a[1]), "r"(a[2]), "r"(a[3]), "r"(b0), "r"(b1));
}
__device__ __forceinline__ void cp_async16(uint32_t smem_dst, const void* gsrc) {
    asm volatile("cp.async.cg.shared.global [%0], [%1], 16;"
                 :: "r"(smem_dst), "l"(gsrc) : "memory");
}

// two-level tree barrier: 8 leaves x 16 arrivals + root of 8; nanosleep spin (proven)
__device__ __forceinline__ void gsync(int bid) {
    __syncthreads();
    if (threadIdx.x == 0) {
        unsigned gen = g_gen;
        __threadfence();
        int lf = bid & 7;
        if (atomicAdd((unsigned*)&g_leaf[lf], 1u) == 15) {
            g_leaf[lf] = 0;
            if (atomicAdd((unsigned*)&g_root, 1u) == 7) {
                g_root = 0;
                __threadfence();
                g_gen = gen + 1;
            } else {
                while (g_gen == gen) __nanosleep(20);
            }
        } else {
            while (g_gen == gen) __nanosleep(20);
        }
        __threadfence();
    }
    __syncthreads();
}

__device__ __forceinline__ int jmap(int rr) { return (rr & 3) * HH + (rr >> 2); }

// ---------------- prep1 ----------------
// blocks: [0] detect+init | [1,1025) wqb | [1025,1281) c0 | [1281,1345) wob2 | [1345,2369) w4 hh pairs
__global__ void __launch_bounds__(256) prep1(
    const int* __restrict__ trg_w, const int* __restrict__ mask_w,
    const float* __restrict__ ih, const float* __restrict__ ic,
    const float* __restrict__ Wq, const float* __restrict__ Wb,
    const float* __restrict__ bq, const float* __restrict__ bbias,
    const float* __restrict__ Wih, const float* __restrict__ Whh,
    const float* __restrict__ bih, const float* __restrict__ bhh,
    const float* __restrict__ init_output, const float* __restrict__ bo2)
{
    int bid = blockIdx.x, tid = threadIdx.x;
    int wid = tid >> 5, lane = tid & 31;

    if (bid == 0) {
        __shared__ int s_odd_nz, s_bin, s_f32;
        if (tid == 0) { s_odd_nz = 0; s_bin = 1; s_f32 = 1; }
        __syncthreads();
        for (int i = tid; i < (BB * TT) / 2; i += 256)
            if (trg_w[2 * i + 1] != 0) atomicOr(&s_odd_nz, 1);
        for (int i = tid; i < (BB * SS) / 4; i += 256) {
            int v = mask_w[i];
            if (v != 0 && v != 1)           atomicAnd(&s_bin, 0);
            if (v != 0 && v != 0x3f800000)  atomicAnd(&s_f32, 0);
        }
        for (int i = tid; i < BB * HH; i += 256) { g_h[0][i] = ih[i]; g_c[i] = ic[i]; }
        __syncthreads();
        if (tid == 0) {
            g_trg64 = s_odd_nz ? 0 : 1;
            g_maskty = s_bin ? 1 : (s_f32 ? 2 : 0);
        }
    } else if (bid < 1025) {
        int idx = bid - 1;
        int by = idx >> 5, bx = idx & 31;
        int ty = tid >> 4, tx = tid & 15;
        int r = by * 16 + ty, c = bx * 16 + tx;
        float acc = 0.f;
        for (int k = 0; k < HH; k++) acc += Wb[r * HH + k] * Wq[k * HH + c];
        g_Wqb[r * HH + c] = acc;
        if (bx == 0 && tx == 0) {
            float a = bbias[r];
            for (int k = 0; k < HH; k++) a += Wb[r * HH + k] * bq[k];
            g_bqb[r] = a;
        }
    } else if (bid < 1281) {
        int idx = bid - 1025;
        int rr = idx * 8 + wid;
        int j = jmap(rr);
        const float* wrow = Wih + (size_t)j * (2 * EE) + EE;
        for (int b = 0; b < BB; b++) {
            const float* io = init_output + (size_t)b * EE;
            float a = 0.f;
            for (int e = lane; e < EE; e += 32) a += wrow[e] * io[e];
            #pragma unroll
            for (int off = 16; off; off >>= 1) a += __shfl_down_sync(0xffffffffu, a, off);
            if (lane == 0) g_c0[rr * BB + b] = a;
        }
    } else if (bid < 1345) {
        int idx = bid - 1281;
        for (int q = 0; q < 4; q++) {
            int rr = idx * 32 + wid * 4 + q;
            int j = jmap(rr);
            const float* wrow = Wih + (size_t)j * (2 * EE) + EE;
            float a = 0.f;
            for (int e = lane; e < EE; e += 32) a += wrow[e] * bo2[e];
            #pragma unroll
            for (int off = 16; off; off >>= 1) a += __shfl_down_sync(0xffffffffu, a, off);
            if (lane == 0) g_wob2[rr] = a;
        }
    } else {
        // paired W_hh columns (k2 in [512,1024)) + biases
        int pi = bid - 1345;                 // 0..1023
        int bq2 = pi >> 3, w = pi & 7;
        int rrA = bq2 * 16 + w, rrB = rrA + 8;
        int jA = jmap(rrA), jB = jmap(rrB);
        for (int k = tid; k < HH; k += 256) {
            float a  = Whh[(size_t)jA * HH + k];
            float bv = Whh[(size_t)jB * HH + k];
            g_W4p[(size_t)pi * KU + 512 + k] = make_float2(a, bv);
        }
        if (tid == 0) g_b4[rrA] = bih[jA] + bhh[jA];
        if (tid == 1) g_b4[rrB] = bih[jB] + bhh[jB];
    }
}

// ---------------- prep2 ----------------
// blocks: [0,400) P | [400,800) q0 | [800,1056) W_U | [1056,1456) M2 | [1456,2480) G_E
__global__ void __launch_bounds__(256) prep2(
    const float* __restrict__ mem, const void* __restrict__ mask_raw,
    const float* __restrict__ Wih, const float* __restrict__ Wo2,
    const float* __restrict__ Wo1, const float* __restrict__ emb,
    const void* __restrict__ trg_raw)
{
    __shared__ float As[16][68];
    __shared__ float Bs[16][68];
    __shared__ int tokbuf[64];
    int bid = blockIdx.x, tid = threadIdx.x;

    if (bid < 400) {
        // P = mem_flat(3200,512) @ Wqb(512,512)
        int m0 = (bid >> 3) * 64, j0 = (bid & 7) * 64;
        int tx = tid & 15, ty = tid >> 4;
        float acc[4][4];
        #pragma unroll
        for (int i = 0; i < 4; i++)
            #pragma unroll
            for (int j = 0; j < 4; j++) acc[i][j] = 0.f;
        for (int k0 = 0; k0 < HH; k0 += 16) {
            int row = tid >> 2, kq = (tid & 3) * 4;
            float4 va = *(const float4*)(mem + (size_t)(m0 + row) * HH + k0 + kq);
            As[kq][row] = va.x; As[kq + 1][row] = va.y;
            As[kq + 2][row] = va.z; As[kq + 3][row] = va.w;
            int kr = tid >> 4, jq = (tid & 15) * 4;
            float4 vb = *(const float4*)(g_Wqb + (size_t)(k0 + kr) * HH + j0 + jq);
            *(float4*)&Bs[kr][jq] = vb;
            __syncthreads();
            #pragma unroll
            for (int k = 0; k < 16; k++) {
                float a[4], b[4];
                #pragma unroll
                for (int i = 0; i < 4; i++) a[i] = As[k][ty * 4 + i];
                #pragma unroll
                for (int i = 0; i < 4; i++) b[i] = Bs[k][tx * 4 + i];
                #pragma unroll
                for (int i = 0; i < 4; i++)
                    #pragma unroll
                    for (int j = 0; j < 4; j++) acc[i][j] += a[i] * b[j];
            }
            __syncthreads();
        }
        #pragma unroll
        for (int i = 0; i < 4; i++)
            #pragma unroll
            for (int j = 0; j < 4; j++)
                g_P[(size_t)(m0 + ty * 4 + i) * HH + j0 + tx * 4 + j] = acc[i][j];
    } else if (bid < 800) {
        int m = (bid - 400) * 8 + (tid >> 5);
        int l = tid & 31;
        if (m < BB * SS) {
            float a = 0.f;
            for (int k = l; k < HH; k += 32) a += g_bqb[k] * mem[(size_t)m * HH + k];
            #pragma unroll
            for (int off = 16; off; off >>= 1) a += __shfl_down_sync(0xffffffffu, a, off);
            if (l == 0) {
                int mty = g_maskty;
                bool mv;
                if      (mty == 0) mv = ((const unsigned char*)mask_raw)[m] != 0;
                else if (mty == 1) mv = ((const int*)mask_raw)[m] != 0;
                else               mv = ((const float*)mask_raw)[m] != 0.0f;
                g_q0[m] = mv ? a : -1e9f;
            }
        }
    } else if (bid < 1056) {
        // W_U[rr][h] = sum_e W_O[rr,e]*Wo2[e,h] -> paired k2 in [0,512)
        int idx = bid - 800;
        int r0 = (idx >> 3) * 64, h0 = (idx & 7) * 64;
        int tx = tid & 15, ty = tid >> 4;
        float acc[4][4];
        #pragma unroll
        for (int i = 0; i < 4; i++)
            #pragma unroll
            for (int j = 0; j < 4; j++) acc[i][j] = 0.f;
        for (int k0 = 0; k0 < EE; k0 += 16) {
            int row = tid >> 2, kq = (tid & 3) * 4;
            int j = jmap(r0 + row);
            float4 va = *(const float4*)(Wih + (size_t)j * (2 * EE) + EE + k0 + kq);
            As[kq][row] = va.x; As[kq + 1][row] = va.y;
            As[kq + 2][row] = va.z; As[kq + 3][row] = va.w;
            int kr = tid >> 4, jq = (tid & 15) * 4;
            float4 vb = *(const float4*)(Wo2 + (size_t)(k0 + kr) * HH + h0 + jq);
            *(float4*)&Bs[kr][jq] = vb;
            __syncthreads();
            #pragma unroll
            for (int k = 0; k < 16; k++) {
                float a[4], b[4];
                #pragma unroll
                for (int i = 0; i < 4; i++) a[i] = As[k][ty * 4 + i];
                #pragma unroll
                for (int i = 0; i < 4; i++) b[i] = Bs[k][tx * 4 + i];
                #pragma unroll
                for (int i = 0; i < 4; i++)
                    #pragma unroll
                    for (int jj = 0; jj < 4; jj++) acc[i][jj] += a[i] * b[jj];
            }
            __syncthreads();
        }
        #pragma unroll
        for (int i = 0; i < 4; i++) {
            int rr = r0 + ty * 4 + i;
            size_t pbase = ((size_t)((rr >> 4) * 8 + (rr & 7)) * KU);
            int half = (rr >> 3) & 1;
            #pragma unroll
            for (int jj = 0; jj < 4; jj++) {
                int h = h0 + tx * 4 + jj;
                ((float*)g_W4p)[(pbase + h) * 2 + half] = acc[i][jj];
            }
        }
    } else if (bid < 1456) {
        // M2[s][r][b] = Wo1_ctx . mem[b,s,:]
        int idx = bid - 1056;
        int m0 = (idx >> 3) * 64, r0j = (idx & 7) * 64;
        int tx = tid & 15, ty = tid >> 4;
        float acc[4][4];
        #pragma unroll
        for (int i = 0; i < 4; i++)
            #pragma unroll
            for (int j = 0; j < 4; j++) acc[i][j] = 0.f;
        for (int k0 = 0; k0 < HH; k0 += 16) {
            int row = tid >> 2, kq = (tid & 3) * 4;
            float4 va = *(const float4*)(mem + (size_t)(m0 + row) * HH + k0 + kq);
            As[kq][row] = va.x; As[kq + 1][row] = va.y;
            As[kq + 2][row] = va.z; As[kq + 3][row] = va.w;
            float4 vb = *(const float4*)(Wo1 + (size_t)(r0j + row) * (2 * HH) + HH + k0 + kq);
            Bs[kq][row] = vb.x; Bs[kq + 1][row] = vb.y;
            Bs[kq + 2][row] = vb.z; Bs[kq + 3][row] = vb.w;
            __syncthreads();
            #pragma unroll
            for (int k = 0; k < 16; k++) {
                float a[4], b[4];
                #pragma unroll
                for (int i = 0; i < 4; i++) a[i] = As[k][ty * 4 + i];
                #pragma unroll
                for (int i = 0; i < 4; i++) b[i] = Bs[k][tx * 4 + i];
                #pragma unroll
                for (int i = 0; i < 4; i++)
                    #pragma unroll
                    for (int j = 0; j < 4; j++) acc[i][j] += a[i] * b[j];
            }
            __syncthreads();
        }
        #pragma unroll
        for (int i = 0; i < 4; i++) {
            int m = m0 + ty * 4 + i;
            int b = m / SS, s = m - b * SS;
            #pragma unroll
            for (int j = 0; j < 4; j++) {
                int r = r0j + tx * 4 + j;
                g_M2[((size_t)s * HH + r) * BB + b] = acc[i][j];
            }
        }
    } else {
        // G_E[t][rr][b] = W_E[rr,:] . emb[token[b,t],:]   (m = t*32+b over 2048 rows)
        int idx = bid - 1456;                 // 0..1023
        int m0 = (idx >> 5) * 64, rr0 = (idx & 31) * 64;
        int tx = tid & 15, ty = tid >> 4;
        if (tid < 64) {
            int m = m0 + tid;
            int t = m >> 5, b = m & 31;
            long long v;
            if (g_trg64) v = ((const long long*)trg_raw)[b * TT + t];
            else         v = ((const int*)trg_raw)[b * TT + t];
            int tk = (int)v;
            if (tk < 0) tk = 0;
            if (tk >= VV) tk = VV - 1;
            tokbuf[tid] = tk;
        }
        __syncthreads();
        float acc[4][4];
        #pragma unroll
        for (int i = 0; i < 4; i++)
            #pragma unroll
            for (int j = 0; j < 4; j++) acc[i][j] = 0.f;
        for (int k0 = 0; k0 < EE; k0 += 16) {
            int row = tid >> 2, kq = (tid & 3) * 4;
            float4 va = *(const float4*)(emb + (size_t)tokbuf[row] * EE + k0 + kq);
            As[kq][row] = va.x; As[kq + 1][row] = va.y;
            As[kq + 2][row] = va.z; As[kq + 3][row] = va.w;
            float4 vb = *(const float4*)(Wih + (size_t)jmap(rr0 + row) * (2 * EE) + k0 + kq);
            Bs[kq][row] = vb.x; Bs[kq + 1][row] = vb.y;
            Bs[kq + 2][row] = vb.z; Bs[kq + 3][row] = vb.w;
            __syncthreads();
            #pragma unroll
            for (int k = 0; k < 16; k++) {
                float a[4], b[4];
                #pragma unroll
                for (int i = 0; i < 4; i++) a[i] = As[k][ty * 4 + i];
                #pragma unroll
                for (int i = 0; i < 4; i++) b[i] = Bs[k][tx * 4 + i];
                #pragma unroll
                for (int i = 0; i < 4; i++)
                    #pragma unroll
                    for (int j = 0; j < 4; j++) acc[i][j] += a[i] * b[j];
            }
            __syncthreads();
        }
        #pragma unroll
        for (int i = 0; i < 4; i++) {
            int m = m0 + ty * 4 + i;
            int t = m >> 5, b = m & 31;
            #pragma unroll
            for (int j = 0; j < 4; j++) {
                int rr = rr0 + tx * 4 + j;
                g_GE[((size_t)t * G4H + rr) * BB + b] = acc[i][j];
            }
        }
    }
}

// split fp32 -> bf16 hi + lo
__global__ void conv_split(const float* __restrict__ src,
                           unsigned short* __restrict__ hi,
                           unsigned short* __restrict__ lo, int n4) {
    int i = blockIdx.x * 256 + threadIdx.x;
    if (i >= n4) return;
    float4 v = ((const float4*)src)[i];
    __nv_bfloat16 h0 = __float2bfloat16(v.x);
    __nv_bfloat16 h1 = __float2bfloat16(v.y);
    __nv_bfloat16 h2 = __float2bfloat16(v.z);
    __nv_bfloat16 h3 = __float2bfloat16(v.w);
    __nv_bfloat16 l0 = __float2bfloat16(v.x - __bfloat162float(h0));
    __nv_bfloat16 l1 = __float2bfloat16(v.y - __bfloat162float(h1));
    __nv_bfloat16 l2 = __float2bfloat16(v.z - __bfloat162float(h2));
    __nv_bfloat16 l3 = __float2bfloat16(v.w - __bfloat162float(h3));
    __nv_bfloat162* H = (__nv_bfloat162*)hi;
    __nv_bfloat162* L = (__nv_bfloat162*)lo;
    H[2 * i]     = __halves2bfloat162(h0, h1);
    H[2 * i + 1] = __halves2bfloat162(h2, h3);
    L[2 * i]     = __halves2bfloat162(l0, l1);
    L[2 * i + 1] = __halves2bfloat162(l2, l3);
}

// ---------------- persistent decoder loop (3 tree-barriers/step) ----------------
__global__ void __launch_bounds__(256) decoder_loop(
    const float* __restrict__ Wo1, const float* __restrict__ bo1)
{
    __shared__ union {
        struct { float Zs[32][65]; float2 Wp[64][8]; float Gs[16][33]; } a;
        struct { float q[HH]; float sc[112]; } c;
        struct { float Zs[32][257]; float Ws[4][257]; float red[4][32]; } d;
    } sm;

    int tid = threadIdx.x, wid = tid >> 5, lane = tid & 31;
    int bid = blockIdx.x;
    int w3 = wid & 3, kh = wid >> 2;

    for (int t = 0; t < TT; t++) {
        const float* u_prev = g_uall + (size_t)(t - 1) * BB * HH;   // unused at t=0
        const float* h_prev = g_h[t & 1];
        float*       h_cur  = g_h[(t + 1) & 1];

        // ---- Phase A: gates = G_E[t] + W_U u_prev + W_hh h_prev + bias; LSTM ----
        {
            float a0 = 0.f, a1 = 0.f, a2 = 0.f, a3 = 0.f;
            // prefetch registers
            float4 pz0, pz1, pw;
            int zb0 = tid >> 4, zc0 = (tid & 15) * 4;
            int zb1 = (256 + tid) >> 4, zc1 = ((256 + tid) & 15) * 4;
            int wp = tid >> 5, wk = (tid & 31) * 2;

            auto loadA = [&](int kt) {
                if (kt < 8) {
                    int kg0 = kt * 64;
                    if (t == 0) {
                        pz0 = make_float4(0.f, 0.f, 0.f, 0.f);
                        pz1 = make_float4(0.f, 0.f, 0.f, 0.f);
                    } else {
                        pz0 = *(const float4*)(u_prev + zb0 * HH + kg0 + zc0);
                        pz1 = *(const float4*)(u_prev + zb1 * HH + kg0 + zc1);
                    }
                } else {
                    int kg0 = (kt - 8) * 64;
                    pz0 = *(const float4*)(h_prev + zb0 * HH + kg0 + zc0);
                    pz1 = *(const float4*)(h_prev + zb1 * HH + kg0 + zc1);
                }
                pw = *(const float4*)(g_W4p + (size_t)(bid * 8 + wp) * KU + kt * 64 + wk);
            };

            loadA(0);
            for (int kt = 0; kt < 16; kt++) {
                // store staged regs
                {
                    float* zr = &sm.a.Zs[zb0][zc0];
                    zr[0] = pz0.x; zr[1] = pz0.y; zr[2] = pz0.z; zr[3] = pz0.w;
                    float* zr1 = &sm.a.Zs[zb1][zc1];
                    zr1[0] = pz1.x; zr1[1] = pz1.y; zr1[2] = pz1.z; zr1[3] = pz1.w;
                    sm.a.Wp[wk][wp]     = make_float2(pw.x, pw.y);
                    sm.a.Wp[wk + 1][wp] = make_float2(pw.z, pw.w);
                }
                __syncthreads();
                if (kt < 15) loadA(kt + 1);   // overlaps with compute
                #pragma unroll
                for (int kk = 0; kk < 64; kk += 2) {
                    float z0 = sm.a.Zs[lane][kk], z1 = sm.a.Zs[lane][kk + 1];
                    float2 w0 = sm.a.Wp[kk][wid], w1 = sm.a.Wp[kk + 1][wid];
                    a0 += w0.x * z0; a1 += w0.y * z0;
                    a2 += w1.x * z1; a3 += w1.y * z1;
                }
                __syncthreads();
            }
            {
                int rbase = bid * 16;
                int r0 = rbase + wid, r1 = rbase + wid + 8;
                float e0 = (t == 0) ? g_c0[r0 * BB + lane] : g_wob2[r0];
                float e1 = (t == 0) ? g_c0[r1 * BB + lane] : g_wob2[r1];
                float ge0 = g_GE[((size_t)t * G4H + r0) * BB + lane];
                float ge1 = g_GE[((size_t)t * G4H + r1) * BB + lane];
                sm.a.Gs[wid][lane]     = a0 + a2 + g_b4[r0] + e0 + ge0;
                sm.a.Gs[wid + 8][lane] = a1 + a3 + g_b4[r1] + e1 + ge1;
            }
            __syncthreads();

            if (tid < 128) {
                int hl = tid >> 5, b = tid & 31;
                float gi = sm.a.Gs[4 * hl + 0][b];
                float gf = sm.a.Gs[4 * hl + 1][b];
                float gg = sm.a.Gs[4 * hl + 2][b];
                float go = sm.a.Gs[4 * hl + 3][b];
                gi = 1.f / (1.f + expf(-gi));
                gf = 1.f / (1.f + expf(-gf));
                go = 1.f / (1.f + expf(-go));
                gg = tanhf(gg);
                int h = bid * 4 + hl;
                int idx = b * HH + h;
                float c = gf * g_c[idx] + gi * gg;
                g_c[idx] = c;
                h_cur[idx] = go * tanhf(c);
            }
        }
        gsync(bid);

        // ---- Phase C: scores + softmax only (4 blocks/batch; slice-write weights) ----
        {
            int b = bid & 31;
            int slice = bid >> 5;
            for (int i = tid; i < HH; i += 256) sm.c.q[i] = h_cur[b * HH + i];
            __syncthreads();

            for (int s = wid; s < SS; s += 8) {
                const float* prow = g_P + (size_t)(b * SS + s) * HH;
                float a = 0.f;
                for (int k = lane; k < HH; k += 32) a += sm.c.q[k] * prow[k];
                #pragma unroll
                for (int off = 16; off; off >>= 1) a += __shfl_down_sync(0xffffffffu, a, off);
                if (lane == 0) sm.c.sc[s] = a + g_q0[b * SS + s];
            }
            __syncthreads();

            if (wid == 0) {
                float m = -1e30f;
                for (int s = lane; s < SS; s += 32) m = fmaxf(m, sm.c.sc[s]);
                #pragma unroll
                for (int off = 16; off; off >>= 1) m = fmaxf(m, __shfl_xor_sync(0xffffffffu, m, off));
                float sum = 0.f;
                for (int s = lane; s < SS; s += 32) {
                    float e = expf(sm.c.sc[s] - m); sm.c.sc[s] = e; sum += e;
                }
                #pragma unroll
                for (int off = 16; off; off >>= 1) sum += __shfl_xor_sync(0xffffffffu, sum, off);
                float inv = 1.f / sum;
                for (int s = lane; s < SS; s += 32) sm.c.sc[s] *= inv;
            }
            __syncthreads();

            if (tid < 25) {
                int s = slice * 25 + tid;
                g_w[s * BB + b] = sm.c.sc[s];
            }
        }
        gsync(bid);

        // ---- Phase D1: u = tanh(Wo1_h.h + sum_s w*M2 + bo1); 4 rows/block ----
        {
            int r0 = bid * 4;
            float acc = 0.f;
            float4 ph[8], pwo;
            int hr = tid >> 6, hc = (tid & 63) * 4;

            auto loadD = [&](int stg) {
                int koff = stg * 256;
                #pragma unroll
                for (int u2 = 0; u2 < 8; u2++) {
                    int slot = u2 * 256 + tid;
                    int b = slot >> 6, c4 = (slot & 63) * 4;
                    ph[u2] = *(const float4*)(h_cur + b * HH + koff + c4);
                }
                pwo = *(const float4*)(Wo1 + (size_t)(r0 + hr) * (2 * HH) + koff + hc);
            };

            loadD(0);
            #pragma unroll
            for (int stg = 0; stg < 2; stg++) {
                #pragma unroll
                for (int u2 = 0; u2 < 8; u2++) {
                    int slot = u2 * 256 + tid;
                    int b = slot >> 6, c4 = (slot & 63) * 4;
                    float* zr = &sm.d.Zs[b][c4];
                    zr[0] = ph[u2].x; zr[1] = ph[u2].y; zr[2] = ph[u2].z; zr[3] = ph[u2].w;
                }
                {
                    float* wr = &sm.d.Ws[hr][hc];
                    wr[0] = pwo.x; wr[1] = pwo.y; wr[2] = pwo.z; wr[3] = pwo.w;
                }
                __syncthreads();
                if (stg == 0) loadD(1);       // overlaps with compute
                int kl = kh * 128;
                float pa = 0.f, pb = 0.f;
                #pragma unroll
                for (int kk = 0; kk < 128; kk += 2) {
                    pa += sm.d.Ws[w3][kl + kk]     * sm.d.Zs[lane][kl + kk];
                    pb += sm.d.Ws[w3][kl + kk + 1] * sm.d.Zs[lane][kl + kk + 1];
                }
                acc += pa + pb;
                __syncthreads();
            }
            // kh=0 warps add the attention-context contribution via M2
            if (kh == 0) {
                int r = r0 + w3;
                float sa = 0.f, sb = 0.f;
                #pragma unroll 2
                for (int s = 0; s < SS; s += 2) {
                    sa += g_w[s * BB + lane] * g_M2[((size_t)s * HH + r) * BB + lane];
                    sb += g_w[(s + 1) * BB + lane] * g_M2[((size_t)(s + 1) * HH + r) * BB + lane];
                }
                acc += sa + sb;
            }
            if (kh == 1) sm.d.red[w3][lane] = acc;
            __syncthreads();
            if (kh == 0) {
                int r = r0 + w3;
                float tot = acc + sm.d.red[w3][lane] + bo1[r];
                g_uall[((size_t)t * BB + lane) * HH + r] = tanhf(tot);
            }
        }
        gsync(bid);
    }
}

// ---------------- out = uall(2048,512) @ Wo2(512,512)^T + bo2 ----------------
__global__ void __launch_bounds__(256) out_gemm(const float* __restrict__ Wo2,
                                                const float* __restrict__ bo2)
{
    __shared__ float As[16][68];
    __shared__ float Bs[16][68];
    int tid = threadIdx.x;
    int m0 = blockIdx.y * 64, e0 = blockIdx.x * 64;
    int tx = tid & 15, ty = tid >> 4;

    float acc[4][4];
    #pragma unroll
    for (int i = 0; i < 4; i++)
        #pragma unroll
        for (int j = 0; j < 4; j++) acc[i][j] = 0.f;

    for (int k0 = 0; k0 < HH; k0 += 16) {
        int row = tid >> 2, kq = (tid & 3) * 4;
        float4 va = *(const float4*)(g_uall + (size_t)(m0 + row) * HH + k0 + kq);
        As[kq][row] = va.x; As[kq + 1][row] = va.y;
        As[kq + 2][row] = va.z; As[kq + 3][row] = va.w;
        float4 vb = *(const float4*)(Wo2 + (size_t)(e0 + row) * HH + k0 + kq);
        Bs[kq][row] = vb.x; Bs[kq + 1][row] = vb.y;
        Bs[kq + 2][row] = vb.z; Bs[kq + 3][row] = vb.w;
        __syncthreads();
        #pragma unroll
        for (int k = 0; k < 16; k++) {
            float a[4], b[4];
            #pragma unroll
            for (int i = 0; i < 4; i++) a[i] = As[k][ty * 4 + i];
            #pragma unroll
            for (int i = 0; i < 4; i++) b[i] = Bs[k][tx * 4 + i];
            #pragma unroll
            for (int i = 0; i < 4; i++)
                #pragma unroll
                for (int j = 0; j < 4; j++) acc[i][j] += a[i] * b[j];
        }
        __syncthreads();
    }
    #pragma unroll
    for (int i = 0; i < 4; i++)
        #pragma unroll
        for (int j = 0; j < 4; j++)
            g_out[(size_t)(m0 + ty * 4 + i) * EE + e0 + tx * 4 + j] =
                acc[i][j] + bo2[e0 + tx * 4 + j];
}

// ---------------- HMMA logits GEMM (cp.async double-buffered) ----------------
#define SPAD 72
#define TILE_B (128 * SPAD * 2)
__global__ void __launch_bounds__(256) logits_mma(float* __restrict__ outp)
{
    extern __shared__ __align__(16) unsigned char dynsm[];

    int tid = threadIdx.x, lane = tid & 31, wid = tid >> 5;
    int wm = wid >> 2;
    int wn = wid & 3;
    int mblk = blockIdx.x * 128;
    int nblk = blockIdx.y * 128;

    uint32_t sbase = smem_u32(dynsm);
    uint32_t aoff = (uint32_t)((wm * 64 + (lane & 15)) * SPAD * 2 + (lane >> 4) * 16);
    uint32_t boff = (uint32_t)((wn * 32 + (lane & 15)) * SPAD * 2 + (lane >> 4) * 16);

    auto issue = [&](int c) {
        int pass = c >> 3;
        int kb = (c & 7) * 64;
        const unsigned short* Ap = (pass == 2) ? g_Al : g_Ah;
        const unsigned short* Bp = (pass == 1) ? g_Bl : g_Bh;
        uint32_t dA = sbase + (uint32_t)(c & 1) * (2 * TILE_B);
        uint32_t dB = dA + TILE_B;
        #pragma unroll
        for (int u = 0; u < 4; u++) {
            int unit = u * 256 + tid;
            int row = unit >> 3, seg = unit & 7;
            uint32_t so = (uint32_t)(row * (SPAD * 2) + seg * 16);
            cp_async16(dA + so, Ap + (size_t)(mblk + row) * 512 + kb + seg * 8);
            cp_async16(dB + so, Bp + (size_t)(nblk + row) * 512 + kb + seg * 8);
        }
        asm volatile("cp.async.commit_group;" ::: "memory");
    };

    float acc[4][4][4];
    #pragma unroll
    for (int i = 0; i < 4; i++)
        #pragma unroll
        for (int j = 0; j < 4; j++)
            #pragma unroll
            for (int k = 0; k < 4; k++) acc[i][j][k] = 0.f;

    issue(0);
    for (int c = 0; c < 24; c++) {
        if (c < 23) {
            issue(c + 1);
            asm volatile("cp.async.wait_group 1;" ::: "memory");
        } else {
            asm volatile("cp.async.wait_group 0;" ::: "memory");
        }
        __syncthreads();

        uint32_t abase = sbase + (uint32_t)(c & 1) * (2 * TILE_B) + aoff;
        uint32_t bbase = sbase + (uint32_t)(c & 1) * (2 * TILE_B) + TILE_B + boff;
        #pragma unroll
        for (int ks = 0; ks < 4; ks++) {
            uint32_t afr[4][4];
            #pragma unroll
            for (int mf = 0; mf < 4; mf++)
                ldm_x4(afr[mf], abase + (uint32_t)(mf * 16 * SPAD * 2 + ks * 32));
            uint32_t bfr[2][4];
            #pragma unroll
            for (int g = 0; g < 2; g++)
                ldm_x4(bfr[g], bbase + (uint32_t)(g * 16 * SPAD * 2 + ks * 32));
            #pragma unroll
            for (int mf = 0; mf < 4; mf++)
                #pragma unroll
                for (int nf = 0; nf < 4; nf++)
                    mma_bf16(acc[mf][nf], afr[mf],
                             bfr[nf >> 1][nf & 1], bfr[nf >> 1][(nf & 1) + 2]);
        }
        __syncthreads();
    }

    #pragma unroll
    for (int mf = 0; mf < 4; mf++) {
        int r0 = mblk + wm * 64 + mf * 16 + (lane >> 2);
        #pragma unroll
        for (int half = 0; half < 2; half++) {
            int r = r0 + half * 8;
            int tt = r >> 5, b2 = r & 31;
            float* orow = outp + (size_t)(b2 * TT + tt) * VV + nblk + wn * 32 + (lane & 3) * 2;
            #pragma unroll
            for (int nf = 0; nf < 4; nf++) {
                float2 v = make_float2(acc[mf][nf][2 * half], acc[mf][nf][2 * half + 1]);
                *(float2*)(orow + nf * 8) = v;
            }
        }
    }
}

// ---------------- host launch ----------------
extern "C" void kernel_launch(void* const* d_in, const int* in_sizes, int n_in,
                              void* d_out, int out_size)
{
    const float* src_memory  = (const float*)d_in[0];
    const void*  src_mask    = d_in[1];
    const float* init_hidden = (const float*)d_in[2];
    const float* init_cell   = (const float*)d_in[3];
    const float* init_output = (const float*)d_in[4];
    const void*  trg         = d_in[5];
    const float* emb         = (const float*)d_in[6];
    const float* W_ih        = (const float*)d_in[7];
    const float* W_hh        = (const float*)d_in[8];
    const float* b_ih        = (const float*)d_in[9];
    const float* b_hh        = (const float*)d_in[10];
    const float* Wq          = (const float*)d_in[11];
    const float* bq          = (const float*)d_in[12];
    const float* Wb          = (const float*)d_in[13];
    const float* bbias       = (const float*)d_in[14];
    const float* Wo1         = (const float*)d_in[15];
    const float* bo1         = (const float*)d_in[16];
    const float* Wo2         = (const float*)d_in[17];
    const float* bo2         = (const float*)d_in[18];

    float *p_out;
    unsigned short *p_Bh, *p_Bl, *p_Ah, *p_Al;
    cudaGetSymbolAddress((void**)&p_out, g_out);
    cudaGetSymbolAddress((void**)&p_Bh,  g_Bh);
    cudaGetSymbolAddress((void**)&p_Bl,  g_Bl);
    cudaGetSymbolAddress((void**)&p_Ah,  g_Ah);
    cudaGetSymbolAddress((void**)&p_Al,  g_Al);

    cudaFuncSetAttribute(logits_mma, cudaFuncAttributeMaxDynamicSharedMemorySize,
                         4 * TILE_B);

    // #1
    prep1<<<2369, 256>>>((const int*)trg, (const int*)src_mask, init_hidden, init_cell,
                         Wq, Wb, bq, bbias, W_ih, W_hh, b_ih, b_hh, init_output, bo2);
    // #2
    prep2<<<2480, 256>>>(src_memory, src_mask, W_ih, Wo2, Wo1, emb, trg);
    // #3
    {
        int n4 = (VV * EE) / 4;
        conv_split<<<(n4 + 255) / 256, 256>>>(emb, p_Bh, p_Bl, n4);
    }
    // #4 — profiled by ncu (-s 5 -c 1)
    decoder_loop<<<NBLK, 256>>>(Wo1, bo1);
    // #5
    out_gemm<<<dim3(EE / 64, (TT * BB) / 64), 256>>>(Wo2, bo2);
    // #6
    {
        int n4 = (TT * BB * EE) / 4;
        conv_split<<<(n4 + 255) / 256, 256>>>(p_out, p_Ah, p_Al, n4);
    }
    // #7
    logits_mma<<<dim3(16, 250), 256, 4 * TILE_B>>>((float*)d_out);
}

// round 12
// speedup vs baseline: 2.5201x; 1.0048x over previous
#include <cuda_runtime.h>
#include <cuda_bf16.h>
#include <math.h>
#include <stdint.h>

// Problem dims
#define BB  32
#define SS  100
#define TT  64
#define HH  512
#define EE  512
#define VV  32000
#define G4H 2048
#define KU  1024     // recurrent gate K: H (u) + H (h); emb part precomputed
#define NBLK 128

// ---------------- device scratch ----------------
__device__ float2 g_W4p[1024 * KU];  // paired gate weights [pair][k2]: k2<512 W_U, else W_hh
__device__ float g_b4[G4H];
__device__ float g_GE[(size_t)TT * G4H * BB]; // [t][rr][b] = W_E . emb[token[b,t]]
__device__ float g_c0[G4H * BB];     // W_O @ init_output (t=0 bias), [rr][b]
__device__ float g_wob2[G4H];        // W_O @ bo2 (t>0 bias)
__device__ float g_Wqb[HH * HH];     // Wb @ Wq
__device__ float g_bqb[HH];          // Wb @ bq + bb
__device__ float g_P[BB * SS * HH];  // mem @ Wqb
__device__ float g_q0[BB * SS];      // bqb.mem with mask folded
__device__ float g_M2[(size_t)SS * HH * BB]; // [s][r][b] = Wo1_ctx . mem[b,s]
__device__ float g_w[SS * BB];       // RAW masked scores [s][b] (softmax deferred to D1)
__device__ float g_h[2][BB * HH];
__device__ float g_c[BB * HH];
__device__ float g_uall[TT * BB * HH];
__device__ float g_out[TT * BB * EE];
__device__ int   g_trg64;
__device__ int   g_maskty;

// tree barrier state
__device__ volatile unsigned g_leaf[8];
__device__ volatile unsigned g_root;
__device__ volatile unsigned g_gen;

__device__ unsigned short g_Bh[(size_t)VV * EE];
__device__ unsigned short g_Bl[(size_t)VV * EE];
__device__ unsigned short g_Ah[(size_t)TT * BB * EE];
__device__ unsigned short g_Al[(size_t)TT * BB * EE];

// dynamic smem layout for decoder_loop
#define WP_OFF   0                    // float2[1024*8] = 64KB, index k*8+pair
#define WO1_OFF  65536                // float[4*512]   = 8KB
#define PH_OFF   73728                // phase union
#define DSM_TOTAL (73728 + 33408)     // + max(A:18752, C:2048, D:33408)

// ---------------- helpers ----------------
__device__ __forceinline__ uint32_t smem_u32(const void* p) {
    uint32_t a;
    asm("{ .reg .u64 t; cvta.to.shared.u64 t, %1; cvt.u32.u64 %0, t; }" : "=r"(a) : "l"(p));
    return a;
}
__device__ __forceinline__ void ldm_x4(uint32_t* r, uint32_t addr) {
    asm volatile("ldmatrix.sync.aligned.m8n8.x4.shared.b16 {%0,%1,%2,%3}, [%4];"
                 : "=r"(r[0]), "=r"(r[1]), "=r"(r[2]), "=r"(r[3]) : "r"(addr));
}
__device__ __forceinline__ void mma_bf16(float* d, const uint32_t* a, uint32_t b0, uint32_t b1) {
    asm volatile(
        "mma.sync.aligned.m16n8k16.row.col.f32.bf16.bf16.f32 "
        "{%0,%1,%2,%3}, {%4,%5,%6,%7}, {%8,%9}, {%0,%1,%2,%3};"
        : "+f"(d[0]), "+f"(d[1]), "+f"(d[2]), "+f"(d[3])
        : "r"(a[0]), "r"(a[1]), "r"(a[2]), "r"(a[3]), "r"(b0), "r"(b1));
}
__device__ __forceinline__ void cp_async16(uint32_t smem_dst, const void* gsrc) {
    asm volatile("cp.async.cg.shared.global [%0], [%1], 16;"
                 :: "r"(smem_dst), "l"(gsrc) : "memory");
}

// two-level tree barrier (proven R11)
__device__ __forceinline__ void gsync(int bid) {
    __syncthreads();
    if (threadIdx.x == 0) {
        unsigned gen = g_gen;
        __threadfence();
        int lf = bid & 7;
        if (atomicAdd((unsigned*)&g_leaf[lf], 1u) == 15) {
            g_leaf[lf] = 0;
            if (atomicAdd((unsigned*)&g_root, 1u) == 7) {
                g_root = 0;
                __threadfence();
                g_gen = gen + 1;
            } else {
                while (g_gen == gen) __nanosleep(20);
            }
        } else {
            while (g_gen == gen) __nanosleep(20);
        }
        __threadfence();
    }
    __syncthreads();
}

__device__ __forceinline__ int jmap(int rr) { return (rr & 3) * HH + (rr >> 2); }

// ---------------- prep1 ----------------
// blocks: [0] detect+init | [1,1025) wqb | [1025,1281) c0 | [1281,1345) wob2 | [1345,2369) w4 hh pairs
__global__ void __launch_bounds__(256) prep1(
    const int* __restrict__ trg_w, const int* __restrict__ mask_w,
    const float* __restrict__ ih, const float* __restrict__ ic,
    const float* __restrict__ Wq, const float* __restrict__ Wb,
    const float* __restrict__ bq, const float* __restrict__ bbias,
    const float* __restrict__ Wih, const float* __restrict__ Whh,
    const float* __restrict__ bih, const float* __restrict__ bhh,
    const float* __restrict__ init_output, const float* __restrict__ bo2)
{
    int bid = blockIdx.x, tid = threadIdx.x;
    int wid = tid >> 5, lane = tid & 31;

    if (bid == 0) {
        __shared__ int s_odd_nz, s_bin, s_f32;
        if (tid == 0) { s_odd_nz = 0; s_bin = 1; s_f32 = 1; }
        __syncthreads();
        for (int i = tid; i < (BB * TT) / 2; i += 256)
            if (trg_w[2 * i + 1] != 0) atomicOr(&s_odd_nz, 1);
        for (int i = tid; i < (BB * SS) / 4; i += 256) {
            int v = mask_w[i];
            if (v != 0 && v != 1)           atomicAnd(&s_bin, 0);
            if (v != 0 && v != 0x3f800000)  atomicAnd(&s_f32, 0);
        }
        for (int i = tid; i < BB * HH; i += 256) { g_h[0][i] = ih[i]; g_c[i] = ic[i]; }
        __syncthreads();
        if (tid == 0) {
            g_trg64 = s_odd_nz ? 0 : 1;
            g_maskty = s_bin ? 1 : (s_f32 ? 2 : 0);
        }
    } else if (bid < 1025) {
        int idx = bid - 1;
        int by = idx >> 5, bx = idx & 31;
        int ty = tid >> 4, tx = tid & 15;
        int r = by * 16 + ty, c = bx * 16 + tx;
        float acc = 0.f;
        for (int k = 0; k < HH; k++) acc += Wb[r * HH + k] * Wq[k * HH + c];
        g_Wqb[r * HH + c] = acc;
        if (bx == 0 && tx == 0) {
            float a = bbias[r];
            for (int k = 0; k < HH; k++) a += Wb[r * HH + k] * bq[k];
            g_bqb[r] = a;
        }
    } else if (bid < 1281) {
        int idx = bid - 1025;
        int rr = idx * 8 + wid;
        int j = jmap(rr);
        const float* wrow = Wih + (size_t)j * (2 * EE) + EE;
        for (int b = 0; b < BB; b++) {
            const float* io = init_output + (size_t)b * EE;
            float a = 0.f;
            for (int e = lane; e < EE; e += 32) a += wrow[e] * io[e];
            #pragma unroll
            for (int off = 16; off; off >>= 1) a += __shfl_down_sync(0xffffffffu, a, off);
            if (lane == 0) g_c0[rr * BB + b] = a;
        }
    } else if (bid < 1345) {
        int idx = bid - 1281;
        for (int q = 0; q < 4; q++) {
            int rr = idx * 32 + wid * 4 + q;
            int j = jmap(rr);
            const float* wrow = Wih + (size_t)j * (2 * EE) + EE;
            float a = 0.f;
            for (int e = lane; e < EE; e += 32) a += wrow[e] * bo2[e];
            #pragma unroll
            for (int off = 16; off; off >>= 1) a += __shfl_down_sync(0xffffffffu, a, off);
            if (lane == 0) g_wob2[rr] = a;
        }
    } else {
        int pi = bid - 1345;
        int bq2 = pi >> 3, w = pi & 7;
        int rrA = bq2 * 16 + w, rrB = rrA + 8;
        int jA = jmap(rrA), jB = jmap(rrB);
        for (int k = tid; k < HH; k += 256) {
            float a  = Whh[(size_t)jA * HH + k];
            float bv = Whh[(size_t)jB * HH + k];
            g_W4p[(size_t)pi * KU + 512 + k] = make_float2(a, bv);
        }
        if (tid == 0) g_b4[rrA] = bih[jA] + bhh[jA];
        if (tid == 1) g_b4[rrB] = bih[jB] + bhh[jB];
    }
}

// ---------------- prep2 ----------------
// blocks: [0,400) P | [400,800) q0 | [800,1056) W_U | [1056,1456) M2 | [1456,2480) G_E
__global__ void __launch_bounds__(256) prep2(
    const float* __restrict__ mem, const void* __restrict__ mask_raw,
    const float* __restrict__ Wih, const float* __restrict__ Wo2,
    const float* __restrict__ Wo1, const float* __restrict__ emb,
    const void* __restrict__ trg_raw)
{
    __shared__ float As[16][68];
    __shared__ float Bs[16][68];
    __shared__ int tokbuf[64];
    int bid = blockIdx.x, tid = threadIdx.x;

    if (bid < 400) {
        int m0 = (bid >> 3) * 64, j0 = (bid & 7) * 64;
        int tx = tid & 15, ty = tid >> 4;
        float acc[4][4];
        #pragma unroll
        for (int i = 0; i < 4; i++)
            #pragma unroll
            for (int j = 0; j < 4; j++) acc[i][j] = 0.f;
        for (int k0 = 0; k0 < HH; k0 += 16) {
            int row = tid >> 2, kq = (tid & 3) * 4;
            float4 va = *(const float4*)(mem + (size_t)(m0 + row) * HH + k0 + kq);
            As[kq][row] = va.x; As[kq + 1][row] = va.y;
            As[kq + 2][row] = va.z; As[kq + 3][row] = va.w;
            int kr = tid >> 4, jq = (tid & 15) * 4;
            float4 vb = *(const float4*)(g_Wqb + (size_t)(k0 + kr) * HH + j0 + jq);
            *(float4*)&Bs[kr][jq] = vb;
            __syncthreads();
            #pragma unroll
            for (int k = 0; k < 16; k++) {
                float a[4], b[4];
                #pragma unroll
                for (int i = 0; i < 4; i++) a[i] = As[k][ty * 4 + i];
                #pragma unroll
                for (int i = 0; i < 4; i++) b[i] = Bs[k][tx * 4 + i];
                #pragma unroll
                for (int i = 0; i < 4; i++)
                    #pragma unroll
                    for (int j = 0; j < 4; j++) acc[i][j] += a[i] * b[j];
            }
            __syncthreads();
        }
        #pragma unroll
        for (int i = 0; i < 4; i++)
            #pragma unroll
            for (int j = 0; j < 4; j++)
                g_P[(size_t)(m0 + ty * 4 + i) * HH + j0 + tx * 4 + j] = acc[i][j];
    } else if (bid < 800) {
        int m = (bid - 400) * 8 + (tid >> 5);
        int l = tid & 31;
        if (m < BB * SS) {
            float a = 0.f;
            for (int k = l; k < HH; k += 32) a += g_bqb[k] * mem[(size_t)m * HH + k];
            #pragma unroll
            for (int off = 16; off; off >>= 1) a += __shfl_down_sync(0xffffffffu, a, off);
            if (l == 0) {
                int mty = g_maskty;
                bool mv;
                if      (mty == 0) mv = ((const unsigned char*)mask_raw)[m] != 0;
                else if (mty == 1) mv = ((const int*)mask_raw)[m] != 0;
                else               mv = ((const float*)mask_raw)[m] != 0.0f;
                g_q0[m] = mv ? a : -1e9f;
            }
        }
    } else if (bid < 1056) {
        int idx = bid - 800;
        int r0 = (idx >> 3) * 64, h0 = (idx & 7) * 64;
        int tx = tid & 15, ty = tid >> 4;
        float acc[4][4];
        #pragma unroll
        for (int i = 0; i < 4; i++)
            #pragma unroll
            for (int j = 0; j < 4; j++) acc[i][j] = 0.f;
        for (int k0 = 0; k0 < EE; k0 += 16) {
            int row = tid >> 2, kq = (tid & 3) * 4;
            int j = jmap(r0 + row);
            float4 va = *(const float4*)(Wih + (size_t)j * (2 * EE) + EE + k0 + kq);
            As[kq][row] = va.x; As[kq + 1][row] = va.y;
            As[kq + 2][row] = va.z; As[kq + 3][row] = va.w;
            int kr = tid >> 4, jq = (tid & 15) * 4;
            float4 vb = *(const float4*)(Wo2 + (size_t)(k0 + kr) * HH + h0 + jq);
            *(float4*)&Bs[kr][jq] = vb;
            __syncthreads();
            #pragma unroll
            for (int k = 0; k < 16; k++) {
                float a[4], b[4];
                #pragma unroll
                for (int i = 0; i < 4; i++) a[i] = As[k][ty * 4 + i];
                #pragma unroll
                for (int i = 0; i < 4; i++) b[i] = Bs[k][tx * 4 + i];
                #pragma unroll
                for (int i = 0; i < 4; i++)
                    #pragma unroll
                    for (int jj = 0; jj < 4; jj++) acc[i][jj] += a[i] * b[jj];
            }
            __syncthreads();
        }
        #pragma unroll
        for (int i = 0; i < 4; i++) {
            int rr = r0 + ty * 4 + i;
            size_t pbase = ((size_t)((rr >> 4) * 8 + (rr & 7)) * KU);
            int half = (rr >> 3) & 1;
            #pragma unroll
            for (int jj = 0; jj < 4; jj++) {
                int h = h0 + tx * 4 + jj;
                ((float*)g_W4p)[(pbase + h) * 2 + half] = acc[i][jj];
            }
        }
    } else if (bid < 1456) {
        int idx = bid - 1056;
        int m0 = (idx >> 3) * 64, r0j = (idx & 7) * 64;
        int tx = tid & 15, ty = tid >> 4;
        float acc[4][4];
        #pragma unroll
        for (int i = 0; i < 4; i++)
            #pragma unroll
            for (int j = 0; j < 4; j++) acc[i][j] = 0.f;
        for (int k0 = 0; k0 < HH; k0 += 16) {
            int row = tid >> 2, kq = (tid & 3) * 4;
            float4 va = *(const float4*)(mem + (size_t)(m0 + row) * HH + k0 + kq);
            As[kq][row] = va.x; As[kq + 1][row] = va.y;
            As[kq + 2][row] = va.z; As[kq + 3][row] = va.w;
            float4 vb = *(const float4*)(Wo1 + (size_t)(r0j + row) * (2 * HH) + HH + k0 + kq);
            Bs[kq][row] = vb.x; Bs[kq + 1][row] = vb.y;
            Bs[kq + 2][row] = vb.z; Bs[kq + 3][row] = vb.w;
            __syncthreads();
            #pragma unroll
            for (int k = 0; k < 16; k++) {
                float a[4], b[4];
                #pragma unroll
                for (int i = 0; i < 4; i++) a[i] = As[k][ty * 4 + i];
                #pragma unroll
                for (int i = 0; i < 4; i++) b[i] = Bs[k][tx * 4 + i];
                #pragma unroll
                for (int i = 0; i < 4; i++)
                    #pragma unroll
                    for (int j = 0; j < 4; j++) acc[i][j] += a[i] * b[j];
            }
            __syncthreads();
        }
        #pragma unroll
        for (int i = 0; i < 4; i++) {
            int m = m0 + ty * 4 + i;
            int b = m / SS, s = m - b * SS;
            #pragma unroll
            for (int j = 0; j < 4; j++) {
                int r = r0j + tx * 4 + j;
                g_M2[((size_t)s * HH + r) * BB + b] = acc[i][j];
            }
        }
    } else {
        int idx = bid - 1456;
        int m0 = (idx >> 5) * 64, rr0 = (idx & 31) * 64;
        int tx = tid & 15, ty = tid >> 4;
        if (tid < 64) {
            int m = m0 + tid;
            int t = m >> 5, b = m & 31;
            long long v;
            if (g_trg64) v = ((const long long*)trg_raw)[b * TT + t];
            else         v = ((const int*)trg_raw)[b * TT + t];
            int tk = (int)v;
            if (tk < 0) tk = 0;
            if (tk >= VV) tk = VV - 1;
            tokbuf[tid] = tk;
        }
        __syncthreads();
        float acc[4][4];
        #pragma unroll
        for (int i = 0; i < 4; i++)
            #pragma unroll
            for (int j = 0; j < 4; j++) acc[i][j] = 0.f;
        for (int k0 = 0; k0 < EE; k0 += 16) {
            int row = tid >> 2, kq = (tid & 3) * 4;
            float4 va = *(const float4*)(emb + (size_t)tokbuf[row] * EE + k0 + kq);
            As[kq][row] = va.x; As[kq + 1][row] = va.y;
            As[kq + 2][row] = va.z; As[kq + 3][row] = va.w;
            float4 vb = *(const float4*)(Wih + (size_t)jmap(rr0 + row) * (2 * EE) + k0 + kq);
            Bs[kq][row] = vb.x; Bs[kq + 1][row] = vb.y;
            Bs[kq + 2][row] = vb.z; Bs[kq + 3][row] = vb.w;
            __syncthreads();
            #pragma unroll
            for (int k = 0; k < 16; k++) {
                float a[4], b[4];
                #pragma unroll
                for (int i = 0; i < 4; i++) a[i] = As[k][ty * 4 + i];
                #pragma unroll
                for (int i = 0; i < 4; i++) b[i] = Bs[k][tx * 4 + i];
                #pragma unroll
                for (int i = 0; i < 4; i++)
                    #pragma unroll
                    for (int j = 0; j < 4; j++) acc[i][j] += a[i] * b[j];
            }
            __syncthreads();
        }
        #pragma unroll
        for (int i = 0; i < 4; i++) {
            int m = m0 + ty * 4 + i;
            int t = m >> 5, b = m & 31;
            #pragma unroll
            for (int j = 0; j < 4; j++) {
                int rr = rr0 + tx * 4 + j;
                g_GE[((size_t)t * G4H + rr) * BB + b] = acc[i][j];
            }
        }
    }
}

// split fp32 -> bf16 hi + lo
__global__ void conv_split(const float* __restrict__ src,
                           unsigned short* __restrict__ hi,
                           unsigned short* __restrict__ lo, int n4) {
    int i = blockIdx.x * 256 + threadIdx.x;
    if (i >= n4) return;
    float4 v = ((const float4*)src)[i];
    __nv_bfloat16 h0 = __float2bfloat16(v.x);
    __nv_bfloat16 h1 = __float2bfloat16(v.y);
    __nv_bfloat16 h2 = __float2bfloat16(v.z);
    __nv_bfloat16 h3 = __float2bfloat16(v.w);
    __nv_bfloat16 l0 = __float2bfloat16(v.x - __bfloat162float(h0));
    __nv_bfloat16 l1 = __float2bfloat16(v.y - __bfloat162float(h1));
    __nv_bfloat16 l2 = __float2bfloat16(v.z - __bfloat162float(h2));
    __nv_bfloat16 l3 = __float2bfloat16(v.w - __bfloat162float(h3));
    __nv_bfloat162* H = (__nv_bfloat162*)hi;
    __nv_bfloat162* L = (__nv_bfloat162*)lo;
    H[2 * i]     = __halves2bfloat162(h0, h1);
    H[2 * i + 1] = __halves2bfloat162(h2, h3);
    L[2 * i]     = __halves2bfloat162(l0, l1);
    L[2 * i + 1] = __halves2bfloat162(l2, l3);
}

// ---------------- persistent decoder loop (weights resident in smem) ----------------
__global__ void __launch_bounds__(256) decoder_loop(
    const float* __restrict__ Wo1, const float* __restrict__ bo1)
{
    extern __shared__ __align__(16) char dsm[];
    float2* Wp   = (float2*)(dsm + WP_OFF);        // [k*8 + pair]
    float*  Wo1s = (float*)(dsm + WO1_OFF);        // [r*512 + k]
    float*  Za   = (float*)(dsm + PH_OFF);         // A: [2][32][65]
    float*  Gs   = (float*)(dsm + PH_OFF + 16640); // A: [16][33]
    float*  qs   = (float*)(dsm + PH_OFF);         // C: [512]
    float*  Zd   = (float*)(dsm + PH_OFF);         // D: [32][257]
    float*  red  = (float*)(dsm + PH_OFF + 32896); // D: [4][32]

    int tid = threadIdx.x, wid = tid >> 5, lane = tid & 31;
    int bid = blockIdx.x;
    int w3 = wid & 3, kh = wid >> 2;

    // persistent weight loads (once per kernel)
    for (int i = tid; i < 8192; i += 256) {        // Wp: p-major global (coalesced k)
        int p = i >> 10, k = i & 1023;
        Wp[k * 8 + p] = g_W4p[(size_t)(bid * 8 + p) * KU + k];
    }
    for (int i = tid; i < 2048; i += 256) {        // Wo1 h-rows
        int r = i >> 9, k = i & 511;
        Wo1s[r * 512 + k] = Wo1[(size_t)(bid * 4 + r) * (2 * HH) + k];
    }
    __syncthreads();

    for (int t = 0; t < TT; t++) {
        const float* u_prev = g_uall + (size_t)(t - 1) * BB * HH;   // unused at t=0
        const float* h_prev = g_h[t & 1];
        float*       h_cur  = g_h[(t + 1) & 1];

        // ---- Phase A: gates = G_E[t] + W_U u_prev + W_hh h_prev + bias; LSTM ----
        {
            float a0 = 0.f, a1 = 0.f, a2 = 0.f, a3 = 0.f;
            float4 pz0, pz1;
            int zb0 = tid >> 4, zc0 = (tid & 15) * 4;
            int zb1 = (256 + tid) >> 4, zc1 = ((256 + tid) & 15) * 4;

            auto loadA = [&](int kt) {
                if (kt < 8) {
                    int kg0 = kt * 64;
                    if (t == 0) {
                        pz0 = make_float4(0.f, 0.f, 0.f, 0.f);
                        pz1 = make_float4(0.f, 0.f, 0.f, 0.f);
                    } else {
                        pz0 = *(const float4*)(u_prev + zb0 * HH + kg0 + zc0);
                        pz1 = *(const float4*)(u_prev + zb1 * HH + kg0 + zc1);
                    }
                } else {
                    int kg0 = (kt - 8) * 64;
                    pz0 = *(const float4*)(h_prev + zb0 * HH + kg0 + zc0);
                    pz1 = *(const float4*)(h_prev + zb1 * HH + kg0 + zc1);
                }
            };

            loadA(0);
            for (int kt = 0; kt < 16; kt++) {
                {   // store staged regs into buf (kt&1)
                    float* z0 = Za + (kt & 1) * 2080 + zb0 * 65 + zc0;
                    z0[0] = pz0.x; z0[1] = pz0.y; z0[2] = pz0.z; z0[3] = pz0.w;
                    float* z1 = Za + (kt & 1) * 2080 + zb1 * 65 + zc1;
                    z1[0] = pz1.x; z1[1] = pz1.y; z1[2] = pz1.z; z1[3] = pz1.w;
                }
                __syncthreads();
                if (kt < 15) loadA(kt + 1);        // L2 latency overlaps compute
                const float* zrow = Za + (kt & 1) * 2080 + lane * 65;
                const float2* wcol = Wp + (size_t)kt * 64 * 8 + wid;
                #pragma unroll
                for (int kk = 0; kk < 64; kk += 2) {
                    float z0 = zrow[kk], z1 = zrow[kk + 1];
                    float2 w0 = wcol[kk * 8], w1 = wcol[(kk + 1) * 8];
                    a0 += w0.x * z0; a1 += w0.y * z0;
                    a2 += w1.x * z1; a3 += w1.y * z1;
                }
            }
            __syncthreads();
            {
                int rbase = bid * 16;
                int r0 = rbase + wid, r1 = rbase + wid + 8;
                float e0 = (t == 0) ? g_c0[r0 * BB + lane] : g_wob2[r0];
                float e1 = (t == 0) ? g_c0[r1 * BB + lane] : g_wob2[r1];
                float ge0 = g_GE[((size_t)t * G4H + r0) * BB + lane];
                float ge1 = g_GE[((size_t)t * G4H + r1) * BB + lane];
                Gs[wid * 33 + lane]       = a0 + a2 + g_b4[r0] + e0 + ge0;
                Gs[(wid + 8) * 33 + lane] = a1 + a3 + g_b4[r1] + e1 + ge1;
            }
            __syncthreads();

            if (tid < 128) {
                int hl = tid >> 5, b = tid & 31;
                float gi = Gs[(4 * hl + 0) * 33 + b];
                float gf = Gs[(4 * hl + 1) * 33 + b];
                float gg = Gs[(4 * hl + 2) * 33 + b];
                float go = Gs[(4 * hl + 3) * 33 + b];
                gi = 1.f / (1.f + expf(-gi));
                gf = 1.f / (1.f + expf(-gf));
                go = 1.f / (1.f + expf(-go));
                gg = tanhf(gg);
                int h = bid * 4 + hl;
                int idx = b * HH + h;
                float c = gf * g_c[idx] + gi * gg;
                g_c[idx] = c;
                h_cur[idx] = go * tanhf(c);
            }
        }
        gsync(bid);

        // ---- Phase C: raw scores only, 25 per block (softmax deferred to D1) ----
        {
            int b = bid & 31;
            int slice = bid >> 5;
            for (int i = tid; i < HH; i += 256) qs[i] = h_cur[b * HH + i];
            __syncthreads();

            int s0 = slice * 25;
            for (int s = s0 + wid; s < s0 + 25; s += 8) {
                const float* prow = g_P + (size_t)(b * SS + s) * HH;
                float a = 0.f;
                for (int k = lane; k < HH; k += 32) a += qs[k] * prow[k];
                #pragma unroll
                for (int off = 16; off; off >>= 1) a += __shfl_down_sync(0xffffffffu, a, off);
                if (lane == 0) g_w[s * BB + b] = a + g_q0[b * SS + s];
            }
        }
        gsync(bid);

        // ---- Phase D1: u = tanh(Wo1_h.h + softmax-ctx via M2 + bo1) ----
        {
            int r0 = bid * 4;
            float acc = 0.f;
            float4 ph4[8];
            auto loadD = [&](int stg) {
                int koff = stg * 256;
                #pragma unroll
                for (int u2 = 0; u2 < 8; u2++) {
                    int slot = u2 * 256 + tid;
                    int b = slot >> 6, c4 = (slot & 63) * 4;
                    ph4[u2] = *(const float4*)(h_cur + b * HH + koff + c4);
                }
            };

            loadD(0);
            #pragma unroll
            for (int stg = 0; stg < 2; stg++) {
                #pragma unroll
                for (int u2 = 0; u2 < 8; u2++) {
                    int slot = u2 * 256 + tid;
                    int b = slot >> 6, c4 = (slot & 63) * 4;
                    float* zr = Zd + b * 257 + c4;
                    zr[0] = ph4[u2].x; zr[1] = ph4[u2].y; zr[2] = ph4[u2].z; zr[3] = ph4[u2].w;
                }
                __syncthreads();
                if (stg == 0) loadD(1);
                int kl = kh * 128;
                const float* wr = Wo1s + w3 * 512 + stg * 256 + kl;
                const float* zr = Zd + lane * 257 + kl;
                float pa = 0.f, pb = 0.f;
                #pragma unroll
                for (int kk = 0; kk < 128; kk += 2) {
                    pa += wr[kk]     * zr[kk];
                    pb += wr[kk + 1] * zr[kk + 1];
                }
                acc += pa + pb;
                __syncthreads();
            }
            // kh==0 warps: softmax + context via M2 (linear in exp, divide once)
            if (kh == 0) {
                int r = r0 + w3;
                float m = -1e30f;
                #pragma unroll 4
                for (int s = 0; s < SS; s++) m = fmaxf(m, g_w[s * BB + lane]);
                float sum = 0.f, ctx = 0.f;
                #pragma unroll 2
                for (int s = 0; s < SS; s++) {
                    float e = expf(g_w[s * BB + lane] - m);
                    sum += e;
                    ctx += e * g_M2[((size_t)s * HH + r) * BB + lane];
                }
                acc += ctx / sum;
            }
            if (kh == 1) red[w3 * 32 + lane] = acc;
            __syncthreads();
            if (kh == 0) {
                int r = r0 + w3;
                float tot = acc + red[w3 * 32 + lane] + bo1[r];
                g_uall[((size_t)t * BB + lane) * HH + r] = tanhf(tot);
            }
        }
        gsync(bid);
    }
}

// ---------------- out = uall(2048,512) @ Wo2(512,512)^T + bo2 ----------------
__global__ void __launch_bounds__(256) out_gemm(const float* __restrict__ Wo2,
                                                const float* __restrict__ bo2)
{
    __shared__ float As[16][68];
    __shared__ float Bs[16][68];
    int tid = threadIdx.x;
    int m0 = blockIdx.y * 64, e0 = blockIdx.x * 64;
    int tx = tid & 15, ty = tid >> 4;

    float acc[4][4];
    #pragma unroll
    for (int i = 0; i < 4; i++)
        #pragma unroll
        for (int j = 0; j < 4; j++) acc[i][j] = 0.f;

    for (int k0 = 0; k0 < HH; k0 += 16) {
        int row = tid >> 2, kq = (tid & 3) * 4;
        float4 va = *(const float4*)(g_uall + (size_t)(m0 + row) * HH + k0 + kq);
        As[kq][row] = va.x; As[kq + 1][row] = va.y;
        As[kq + 2][row] = va.z; As[kq + 3][row] = va.w;
        float4 vb = *(const float4*)(Wo2 + (size_t)(e0 + row) * HH + k0 + kq);
        Bs[kq][row] = vb.x; Bs[kq + 1][row] = vb.y;
        Bs[kq + 2][row] = vb.z; Bs[kq + 3][row] = vb.w;
        __syncthreads();
        #pragma unroll
        for (int k = 0; k < 16; k++) {
            float a[4], b[4];
            #pragma unroll
            for (int i = 0; i < 4; i++) a[i] = As[k][ty * 4 + i];
            #pragma unroll
            for (int i = 0; i < 4; i++) b[i] = Bs[k][tx * 4 + i];
            #pragma unroll
            for (int i = 0; i < 4; i++)
                #pragma unroll
                for (int j = 0; j < 4; j++) acc[i][j] += a[i] * b[j];
        }
        __syncthreads();
    }
    #pragma unroll
    for (int i = 0; i < 4; i++)
        #pragma unroll
        for (int j = 0; j < 4; j++)
            g_out[(size_t)(m0 + ty * 4 + i) * EE + e0 + tx * 4 + j] =
                acc[i][j] + bo2[e0 + tx * 4 + j];
}

// ---------------- HMMA logits GEMM (cp.async double-buffered) ----------------
#define SPAD 72
#define TILE_B (128 * SPAD * 2)
__global__ void __launch_bounds__(256) logits_mma(float* __restrict__ outp)
{
    extern __shared__ __align__(16) unsigned char dynsm[];

    int tid = threadIdx.x, lane = tid & 31, wid = tid >> 5;
    int wm = wid >> 2;
    int wn = wid & 3;
    int mblk = blockIdx.x * 128;
    int nblk = blockIdx.y * 128;

    uint32_t sbase = smem_u32(dynsm);
    uint32_t aoff = (uint32_t)((wm * 64 + (lane & 15)) * SPAD * 2 + (lane >> 4) * 16);
    uint32_t boff = (uint32_t)((wn * 32 + (lane & 15)) * SPAD * 2 + (lane >> 4) * 16);

    auto issue = [&](int c) {
        int pass = c >> 3;
        int kb = (c & 7) * 64;
        const unsigned short* Ap = (pass == 2) ? g_Al : g_Ah;
        const unsigned short* Bp = (pass == 1) ? g_Bl : g_Bh;
        uint32_t dA = sbase + (uint32_t)(c & 1) * (2 * TILE_B);
        uint32_t dB = dA + TILE_B;
        #pragma unroll
        for (int u = 0; u < 4; u++) {
            int unit = u * 256 + tid;
            int row = unit >> 3, seg = unit & 7;
            uint32_t so = (uint32_t)(row * (SPAD * 2) + seg * 16);
            cp_async16(dA + so, Ap + (size_t)(mblk + row) * 512 + kb + seg * 8);
            cp_async16(dB + so, Bp + (size_t)(nblk + row) * 512 + kb + seg * 8);
        }
        asm volatile("cp.async.commit_group;" ::: "memory");
    };

    float acc[4][4][4];
    #pragma unroll
    for (int i = 0; i < 4; i++)
        #pragma unroll
        for (int j = 0; j < 4; j++)
            #pragma unroll
            for (int k = 0; k < 4; k++) acc[i][j][k] = 0.f;

    issue(0);
    for (int c = 0; c < 24; c++) {
        if (c < 23) {
            issue(c + 1);
            asm volatile("cp.async.wait_group 1;" ::: "memory");
        } else {
            asm volatile("cp.async.wait_group 0;" ::: "memory");
        }
        __syncthreads();

        uint32_t abase = sbase + (uint32_t)(c & 1) * (2 * TILE_B) + aoff;
        uint32_t bbase = sbase + (uint32_t)(c & 1) * (2 * TILE_B) + TILE_B + boff;
        #pragma unroll
        for (int ks = 0; ks < 4; ks++) {
            uint32_t afr[4][4];
            #pragma unroll
            for (int mf = 0; mf < 4; mf++)
                ldm_x4(afr[mf], abase + (uint32_t)(mf * 16 * SPAD * 2 + ks * 32));
            uint32_t bfr[2][4];
            #pragma unroll
            for (int g = 0; g < 2; g++)
                ldm_x4(bfr[g], bbase + (uint32_t)(g * 16 * SPAD * 2 + ks * 32));
            #pragma unroll
            for (int mf = 0; mf < 4; mf++)
                #pragma unroll
                for (int nf = 0; nf < 4; nf++)
                    mma_bf16(acc[mf][nf], afr[mf],
                             bfr[nf >> 1][nf & 1], bfr[nf >> 1][(nf & 1) + 2]);
        }
        __syncthreads();
    }

    #pragma unroll
    for (int mf = 0; mf < 4; mf++) {
        int r0 = mblk + wm * 64 + mf * 16 + (lane >> 2);
        #pragma unroll
        for (int half = 0; half < 2; half++) {
            int r = r0 + half * 8;
            int tt = r >> 5, b2 = r & 31;
            float* orow = outp + (size_t)(b2 * TT + tt) * VV + nblk + wn * 32 + (lane & 3) * 2;
            #pragma unroll
            for (int nf = 0; nf < 4; nf++) {
                float2 v = make_float2(acc[mf][nf][2 * half], acc[mf][nf][2 * half + 1]);
                *(float2*)(orow + nf * 8) = v;
            }
        }
    }
}

// ---------------- host launch ----------------
extern "C" void kernel_launch(void* const* d_in, const int* in_sizes, int n_in,
                              void* d_out, int out_size)
{
    const float* src_memory  = (const float*)d_in[0];
    const void*  src_mask    = d_in[1];
    const float* init_hidden = (const float*)d_in[2];
    const float* init_cell   = (const float*)d_in[3];
    const float* init_output = (const float*)d_in[4];
    const void*  trg         = d_in[5];
    const float* emb         = (const float*)d_in[6];
    const float* W_ih        = (const float*)d_in[7];
    const float* W_hh        = (const float*)d_in[8];
    const float* b_ih        = (const float*)d_in[9];
    const float* b_hh        = (const float*)d_in[10];
    const float* Wq          = (const float*)d_in[11];
    const float* bq          = (const float*)d_in[12];
    const float* Wb          = (const float*)d_in[13];
    const float* bbias       = (const float*)d_in[14];
    const float* Wo1         = (const float*)d_in[15];
    const float* bo1         = (const float*)d_in[16];
    const float* Wo2         = (const float*)d_in[17];
    const float* bo2         = (const float*)d_in[18];

    float *p_out;
    unsigned short *p_Bh, *p_Bl, *p_Ah, *p_Al;
    cudaGetSymbolAddress((void**)&p_out, g_out);
    cudaGetSymbolAddress((void**)&p_Bh,  g_Bh);
    cudaGetSymbolAddress((void**)&p_Bl,  g_Bl);
    cudaGetSymbolAddress((void**)&p_Ah,  g_Ah);
    cudaGetSymbolAddress((void**)&p_Al,  g_Al);

    cudaFuncSetAttribute(logits_mma, cudaFuncAttributeMaxDynamicSharedMemorySize,
                         4 * TILE_B);
    cudaFuncSetAttribute(decoder_loop, cudaFuncAttributeMaxDynamicSharedMemorySize,
                         DSM_TOTAL);

    // #1
    prep1<<<2369, 256>>>((const int*)trg, (const int*)src_mask, init_hidden, init_cell,
                         Wq, Wb, bq, bbias, W_ih, W_hh, b_ih, b_hh, init_output, bo2);
    // #2
    prep2<<<2480, 256>>>(src_memory, src_mask, W_ih, Wo2, Wo1, emb, trg);
    // #3
    {
        int n4 = (VV * EE) / 4;
        conv_split<<<(n4 + 255) / 256, 256>>>(emb, p_Bh, p_Bl, n4);
    }
    // #4 — profiled by ncu (-s 5 -c 1)
    decoder_loop<<<NBLK, 256, DSM_TOTAL>>>(Wo1, bo1);
    // #5
    out_gemm<<<dim3(EE / 64, (TT * BB) / 64), 256>>>(Wo2, bo2);
    // #6
    {
        int n4 = (TT * BB * EE) / 4;
        conv_split<<<(n4 + 255) / 256, 256>>>(p_out, p_Ah, p_Al, n4);
    }
    // #7
    logits_mma<<<dim3(16, 250), 256, 4 * TILE_B>>>((float*)d_out);
}

// round 13
// speedup vs baseline: 2.6749x; 1.0614x over previous
#include <cuda_runtime.h>
#include <cuda_bf16.h>
#include <math.h>
#include <stdint.h>

// Problem dims
#define BB  32
#define SS  100
#define TT  64
#define HH  512
#define EE  512
#define VV  32000
#define G4H 2048
#define KU  1024     // recurrent gate K: H (u) + H (h); emb part precomputed
#define NBLK 128

// ---------------- device scratch ----------------
__device__ float2 g_W4p[1024 * KU];  // paired gate weights [pair][k2]: k2<512 W_U, else W_hh
__device__ float g_b4[G4H];
__device__ float g_GE[(size_t)TT * G4H * BB]; // [t][rr][b] = W_E . emb[token[b,t]]
__device__ float g_c0[G4H * BB];     // W_O @ init_output (t=0 bias), [rr][b]
__device__ float g_wob2[G4H];        // W_O @ bo2 (t>0 bias)
__device__ float g_Wqb[HH * HH];     // Wb @ Wq
__device__ float g_bqb[HH];          // Wb @ bq + bb
__device__ float g_P[BB * SS * HH];  // mem @ Wqb
__device__ float g_q0[BB * SS];      // bqb.mem with mask folded
__device__ float g_M2[(size_t)SS * HH * BB]; // [s][r][b] = Wo1_ctx . mem[b,s]
__device__ float g_w[SS * BB];       // RAW masked scores [s][b] (softmax deferred)
__device__ float g_h[2][BB * HH];
__device__ float g_c[BB * HH];
__device__ float g_uall[TT * BB * HH];
__device__ float g_out[TT * BB * EE];
__device__ int   g_trg64;
__device__ int   g_maskty;

// monotonic two-level barrier counters + score flag (reset each replay in prep1)
__device__ volatile unsigned g_leafc[8];
__device__ volatile unsigned g_rootc;
__device__ volatile unsigned g_scnt;

__device__ unsigned short g_Bh[(size_t)VV * EE];
__device__ unsigned short g_Bl[(size_t)VV * EE];
__device__ unsigned short g_Ah[(size_t)TT * BB * EE];
__device__ unsigned short g_Al[(size_t)TT * BB * EE];

// dynamic smem layout for decoder_loop
#define WP_OFF   0                    // float2[1024*8] = 64KB, index k*8+pair
#define WO1_OFF  65536                // float[4*512]   = 8KB
#define PH_OFF   73728                // phase union
#define DSM_TOTAL (73728 + 33408)     // + max(A:18752, D:33408)

// ---------------- helpers ----------------
__device__ __forceinline__ uint32_t smem_u32(const void* p) {
    uint32_t a;
    asm("{ .reg .u64 t; cvta.to.shared.u64 t, %1; cvt.u32.u64 %0, t; }" : "=r"(a) : "l"(p));
    return a;
}
__device__ __forceinline__ void ldm_x4(uint32_t* r, uint32_t addr) {
    asm volatile("ldmatrix.sync.aligned.m8n8.x4.shared.b16 {%0,%1,%2,%3}, [%4];"
                 : "=r"(r[0]), "=r"(r[1]), "=r"(r[2]), "=r"(r[3]) : "r"(addr));
}
__device__ __forceinline__ void mma_bf16(float* d, const uint32_t* a, uint32_t b0, uint32_t b1) {
    asm volatile(
        "mma.sync.aligned.m16n8k16.row.col.f32.bf16.bf16.f32 "
        "{%0,%1,%2,%3}, {%4,%5,%6,%7}, {%8,%9}, {%0,%1,%2,%3};"
        : "+f"(d[0]), "+f"(d[1]), "+f"(d[2]), "+f"(d[3])
        : "r"(a[0]), "r"(a[1]), "r"(a[2]), "r"(a[3]), "r"(b0), "r"(b1));
}
__device__ __forceinline__ void cp_async16(uint32_t smem_dst, const void* gsrc) {
    asm volatile("cp.async.cg.shared.global [%0], [%1], 16;"
                 :: "r"(smem_dst), "l"(gsrc) : "memory");
}

// monotonic two-level barrier: leaf atomic + root atomic; spin on root value.
// No release write, no reset (counters monotonic within a replay).
__device__ __forceinline__ void gsync2(int bid, unsigned seq) {
    __syncthreads();
    if (threadIdx.x == 0) {
        __threadfence();
        int lf = bid & 7;
        unsigned v = atomicAdd((unsigned*)&g_leafc[lf], 1u) + 1u;
        if (v == seq * 16u) atomicAdd((unsigned*)&g_rootc, 1u);
        unsigned tgt = seq * 8u;
        while (g_rootc < tgt) __nanosleep(20);
        __threadfence();
    }
    __syncthreads();
}

__device__ __forceinline__ int jmap(int rr) { return (rr & 3) * HH + (rr >> 2); }

// ---------------- prep1 ----------------
// blocks: [0] detect+init+ctr-reset | [1,1025) wqb | [1025,1281) c0 | [1281,1345) wob2 | [1345,2369) w4 hh
__global__ void __launch_bounds__(256) prep1(
    const int* __restrict__ trg_w, const int* __restrict__ mask_w,
    const float* __restrict__ ih, const float* __restrict__ ic,
    const float* __restrict__ Wq, const float* __restrict__ Wb,
    const float* __restrict__ bq, const float* __restrict__ bbias,
    const float* __restrict__ Wih, const float* __restrict__ Whh,
    const float* __restrict__ bih, const float* __restrict__ bhh,
    const float* __restrict__ init_output, const float* __restrict__ bo2)
{
    int bid = blockIdx.x, tid = threadIdx.x;
    int wid = tid >> 5, lane = tid & 31;

    if (bid == 0) {
        __shared__ int s_odd_nz, s_bin, s_f32;
        if (tid == 0) {
            s_odd_nz = 0; s_bin = 1; s_f32 = 1;
            // reset decoder_loop sync state for this replay
            for (int i = 0; i < 8; i++) g_leafc[i] = 0;
            g_rootc = 0;
            g_scnt = 0;
        }
        __syncthreads();
        for (int i = tid; i < (BB * TT) / 2; i += 256)
            if (trg_w[2 * i + 1] != 0) atomicOr(&s_odd_nz, 1);
        for (int i = tid; i < (BB * SS) / 4; i += 256) {
            int v = mask_w[i];
            if (v != 0 && v != 1)           atomicAnd(&s_bin, 0);
            if (v != 0 && v != 0x3f800000)  atomicAnd(&s_f32, 0);
        }
        for (int i = tid; i < BB * HH; i += 256) { g_h[0][i] = ih[i]; g_c[i] = ic[i]; }
        __syncthreads();
        if (tid == 0) {
            g_trg64 = s_odd_nz ? 0 : 1;
            g_maskty = s_bin ? 1 : (s_f32 ? 2 : 0);
        }
    } else if (bid < 1025) {
        int idx = bid - 1;
        int by = idx >> 5, bx = idx & 31;
        int ty = tid >> 4, tx = tid & 15;
        int r = by * 16 + ty, c = bx * 16 + tx;
        float acc = 0.f;
        for (int k = 0; k < HH; k++) acc += Wb[r * HH + k] * Wq[k * HH + c];
        g_Wqb[r * HH + c] = acc;
        if (bx == 0 && tx == 0) {
            float a = bbias[r];
            for (int k = 0; k < HH; k++) a += Wb[r * HH + k] * bq[k];
            g_bqb[r] = a;
        }
    } else if (bid < 1281) {
        int idx = bid - 1025;
        int rr = idx * 8 + wid;
        int j = jmap(rr);
        const float* wrow = Wih + (size_t)j * (2 * EE) + EE;
        for (int b = 0; b < BB; b++) {
            const float* io = init_output + (size_t)b * EE;
            float a = 0.f;
            for (int e = lane; e < EE; e += 32) a += wrow[e] * io[e];
            #pragma unroll
            for (int off = 16; off; off >>= 1) a += __shfl_down_sync(0xffffffffu, a, off);
            if (lane == 0) g_c0[rr * BB + b] = a;
        }
    } else if (bid < 1345) {
        int idx = bid - 1281;
        for (int q = 0; q < 4; q++) {
            int rr = idx * 32 + wid * 4 + q;
            int j = jmap(rr);
            const float* wrow = Wih + (size_t)j * (2 * EE) + EE;
            float a = 0.f;
            for (int e = lane; e < EE; e += 32) a += wrow[e] * bo2[e];
            #pragma unroll
            for (int off = 16; off; off >>= 1) a += __shfl_down_sync(0xffffffffu, a, off);
            if (lane == 0) g_wob2[rr] = a;
        }
    } else {
        int pi = bid - 1345;
        int bq2 = pi >> 3, w = pi & 7;
        int rrA = bq2 * 16 + w, rrB = rrA + 8;
        int jA = jmap(rrA), jB = jmap(rrB);
        for (int k = tid; k < HH; k += 256) {
            float a  = Whh[(size_t)jA * HH + k];
            float bv = Whh[(size_t)jB * HH + k];
            g_W4p[(size_t)pi * KU + 512 + k] = make_float2(a, bv);
        }
        if (tid == 0) g_b4[rrA] = bih[jA] + bhh[jA];
        if (tid == 1) g_b4[rrB] = bih[jB] + bhh[jB];
    }
}

// ---------------- prep2 ----------------
// blocks: [0,400) P | [400,800) q0 | [800,1056) W_U | [1056,1456) M2 | [1456,2480) G_E
__global__ void __launch_bounds__(256) prep2(
    const float* __restrict__ mem, const void* __restrict__ mask_raw,
    const float* __restrict__ Wih, const float* __restrict__ Wo2,
    const float* __restrict__ Wo1, const float* __restrict__ emb,
    const void* __restrict__ trg_raw)
{
    __shared__ float As[16][68];
    __shared__ float Bs[16][68];
    __shared__ int tokbuf[64];
    int bid = blockIdx.x, tid = threadIdx.x;

    if (bid < 400) {
        int m0 = (bid >> 3) * 64, j0 = (bid & 7) * 64;
        int tx = tid & 15, ty = tid >> 4;
        float acc[4][4];
        #pragma unroll
        for (int i = 0; i < 4; i++)
            #pragma unroll
            for (int j = 0; j < 4; j++) acc[i][j] = 0.f;
        for (int k0 = 0; k0 < HH; k0 += 16) {
            int row = tid >> 2, kq = (tid & 3) * 4;
            float4 va = *(const float4*)(mem + (size_t)(m0 + row) * HH + k0 + kq);
            As[kq][row] = va.x; As[kq + 1][row] = va.y;
            As[kq + 2][row] = va.z; As[kq + 3][row] = va.w;
            int kr = tid >> 4, jq = (tid & 15) * 4;
            float4 vb = *(const float4*)(g_Wqb + (size_t)(k0 + kr) * HH + j0 + jq);
            *(float4*)&Bs[kr][jq] = vb;
            __syncthreads();
            #pragma unroll
            for (int k = 0; k < 16; k++) {
                float a[4], b[4];
                #pragma unroll
                for (int i = 0; i < 4; i++) a[i] = As[k][ty * 4 + i];
                #pragma unroll
                for (int i = 0; i < 4; i++) b[i] = Bs[k][tx * 4 + i];
                #pragma unroll
                for (int i = 0; i < 4; i++)
                    #pragma unroll
                    for (int j = 0; j < 4; j++) acc[i][j] += a[i] * b[j];
            }
            __syncthreads();
        }
        #pragma unroll
        for (int i = 0; i < 4; i++)
            #pragma unroll
            for (int j = 0; j < 4; j++)
                g_P[(size_t)(m0 + ty * 4 + i) * HH + j0 + tx * 4 + j] = acc[i][j];
    } else if (bid < 800) {
        int m = (bid - 400) * 8 + (tid >> 5);
        int l = tid & 31;
        if (m < BB * SS) {
            float a = 0.f;
            for (int k = l; k < HH; k += 32) a += g_bqb[k] * mem[(size_t)m * HH + k];
            #pragma unroll
            for (int off = 16; off; off >>= 1) a += __shfl_down_sync(0xffffffffu, a, off);
            if (l == 0) {
                int mty = g_maskty;
                bool mv;
                if      (mty == 0) mv = ((const unsigned char*)mask_raw)[m] != 0;
                else if (mty == 1) mv = ((const int*)mask_raw)[m] != 0;
                else               mv = ((const float*)mask_raw)[m] != 0.0f;
                g_q0[m] = mv ? a : -1e9f;
            }
        }
    } else if (bid < 1056) {
        int idx = bid - 800;
        int r0 = (idx >> 3) * 64, h0 = (idx & 7) * 64;
        int tx = tid & 15, ty = tid >> 4;
        float acc[4][4];
        #pragma unroll
        for (int i = 0; i < 4; i++)
            #pragma unroll
            for (int j = 0; j < 4; j++) acc[i][j] = 0.f;
        for (int k0 = 0; k0 < EE; k0 += 16) {
            int row = tid >> 2, kq = (tid & 3) * 4;
            int j = jmap(r0 + row);
            float4 va = *(const float4*)(Wih + (size_t)j * (2 * EE) + EE + k0 + kq);
            As[kq][row] = va.x; As[kq + 1][row] = va.y;
            As[kq + 2][row] = va.z; As[kq + 3][row] = va.w;
            int kr = tid >> 4, jq = (tid & 15) * 4;
            float4 vb = *(const float4*)(Wo2 + (size_t)(k0 + kr) * HH + h0 + jq);
            *(float4*)&Bs[kr][jq] = vb;
            __syncthreads();
            #pragma unroll
            for (int k = 0; k < 16; k++) {
                float a[4], b[4];
                #pragma unroll
                for (int i = 0; i < 4; i++) a[i] = As[k][ty * 4 + i];
                #pragma unroll
                for (int i = 0; i < 4; i++) b[i] = Bs[k][tx * 4 + i];
                #pragma unroll
                for (int i = 0; i < 4; i++)
                    #pragma unroll
                    for (int jj = 0; jj < 4; jj++) acc[i][jj] += a[i] * b[jj];
            }
            __syncthreads();
        }
        #pragma unroll
        for (int i = 0; i < 4; i++) {
            int rr = r0 + ty * 4 + i;
            size_t pbase = ((size_t)((rr >> 4) * 8 + (rr & 7)) * KU);
            int half = (rr >> 3) & 1;
            #pragma unroll
            for (int jj = 0; jj < 4; jj++) {
                int h = h0 + tx * 4 + jj;
                ((float*)g_W4p)[(pbase + h) * 2 + half] = acc[i][jj];
            }
        }
    } else if (bid < 1456) {
        int idx = bid - 1056;
        int m0 = (idx >> 3) * 64, r0j = (idx & 7) * 64;
        int tx = tid & 15, ty = tid >> 4;
        float acc[4][4];
        #pragma unroll
        for (int i = 0; i < 4; i++)
            #pragma unroll
            for (int j = 0; j < 4; j++) acc[i][j] = 0.f;
        for (int k0 = 0; k0 < HH; k0 += 16) {
            int row = tid >> 2, kq = (tid & 3) * 4;
            float4 va = *(const float4*)(mem + (size_t)(m0 + row) * HH + k0 + kq);
            As[kq][row] = va.x; As[kq + 1][row] = va.y;
            As[kq + 2][row] = va.z; As[kq + 3][row] = va.w;
            float4 vb = *(const float4*)(Wo1 + (size_t)(r0j + row) * (2 * HH) + HH + k0 + kq);
            Bs[kq][row] = vb.x; Bs[kq + 1][row] = vb.y;
            Bs[kq + 2][row] = vb.z; Bs[kq + 3][row] = vb.w;
            __syncthreads();
            #pragma unroll
            for (int k = 0; k < 16; k++) {
                float a[4], b[4];
                #pragma unroll
                for (int i = 0; i < 4; i++) a[i] = As[k][ty * 4 + i];
                #pragma unroll
                for (int i = 0; i < 4; i++) b[i] = Bs[k][tx * 4 + i];
                #pragma unroll
                for (int i = 0; i < 4; i++)
                    #pragma unroll
                    for (int j = 0; j < 4; j++) acc[i][j] += a[i] * b[j];
            }
            __syncthreads();
        }
        #pragma unroll
        for (int i = 0; i < 4; i++) {
            int m = m0 + ty * 4 + i;
            int b = m / SS, s = m - b * SS;
            #pragma unroll
            for (int j = 0; j < 4; j++) {
                int r = r0j + tx * 4 + j;
                g_M2[((size_t)s * HH + r) * BB + b] = acc[i][j];
            }
        }
    } else {
        int idx = bid - 1456;
        int m0 = (idx >> 5) * 64, rr0 = (idx & 31) * 64;
        int tx = tid & 15, ty = tid >> 4;
        if (tid < 64) {
            int m = m0 + tid;
            int t = m >> 5, b = m & 31;
            long long v;
            if (g_trg64) v = ((const long long*)trg_raw)[b * TT + t];
            else         v = ((const int*)trg_raw)[b * TT + t];
            int tk = (int)v;
            if (tk < 0) tk = 0;
            if (tk >= VV) tk = VV - 1;
            tokbuf[tid] = tk;
        }
        __syncthreads();
        float acc[4][4];
        #pragma unroll
        for (int i = 0; i < 4; i++)
            #pragma unroll
            for (int j = 0; j < 4; j++) acc[i][j] = 0.f;
        for (int k0 = 0; k0 < EE; k0 += 16) {
            int row = tid >> 2, kq = (tid & 3) * 4;
            float4 va = *(const float4*)(emb + (size_t)tokbuf[row] * EE + k0 + kq);
            As[kq][row] = va.x; As[kq + 1][row] = va.y;
            As[kq + 2][row] = va.z; As[kq + 3][row] = va.w;
            float4 vb = *(const float4*)(Wih + (size_t)jmap(rr0 + row) * (2 * EE) + k0 + kq);
            Bs[kq][row] = vb.x; Bs[kq + 1][row] = vb.y;
            Bs[kq + 2][row] = vb.z; Bs[kq + 3][row] = vb.w;
            __syncthreads();
            #pragma unroll
            for (int k = 0; k < 16; k++) {
                float a[4], b[4];
                #pragma unroll
                for (int i = 0; i < 4; i++) a[i] = As[k][ty * 4 + i];
                #pragma unroll
                for (int i = 0; i < 4; i++) b[i] = Bs[k][tx * 4 + i];
                #pragma unroll
                for (int i = 0; i < 4; i++)
                    #pragma unroll
                    for (int j = 0; j < 4; j++) acc[i][j] += a[i] * b[j];
            }
            __syncthreads();
        }
        #pragma unroll
        for (int i = 0; i < 4; i++) {
            int m = m0 + ty * 4 + i;
            int t = m >> 5, b = m & 31;
            #pragma unroll
            for (int j = 0; j < 4; j++) {
                int rr = rr0 + tx * 4 + j;
                g_GE[((size_t)t * G4H + rr) * BB + b] = acc[i][j];
            }
        }
    }
}

// split fp32 -> bf16 hi + lo
__global__ void conv_split(const float* __restrict__ src,
                           unsigned short* __restrict__ hi,
                           unsigned short* __restrict__ lo, int n4) {
    int i = blockIdx.x * 256 + threadIdx.x;
    if (i >= n4) return;
    float4 v = ((const float4*)src)[i];
    __nv_bfloat16 h0 = __float2bfloat16(v.x);
    __nv_bfloat16 h1 = __float2bfloat16(v.y);
    __nv_bfloat16 h2 = __float2bfloat16(v.z);
    __nv_bfloat16 h3 = __float2bfloat16(v.w);
    __nv_bfloat16 l0 = __float2bfloat16(v.x - __bfloat162float(h0));
    __nv_bfloat16 l1 = __float2bfloat16(v.y - __bfloat162float(h1));
    __nv_bfloat16 l2 = __float2bfloat16(v.z - __bfloat162float(h2));
    __nv_bfloat16 l3 = __float2bfloat16(v.w - __bfloat162float(h3));
    __nv_bfloat162* H = (__nv_bfloat162*)hi;
    __nv_bfloat162* L = (__nv_bfloat162*)lo;
    H[2 * i]     = __halves2bfloat162(h0, h1);
    H[2 * i + 1] = __halves2bfloat162(h2, h3);
    L[2 * i]     = __halves2bfloat162(l0, l1);
    L[2 * i + 1] = __halves2bfloat162(l2, l3);
}

// ---------------- persistent decoder loop (2 barriers/step + soft score flag) ----------------
__global__ void __launch_bounds__(256) decoder_loop(
    const float* __restrict__ Wo1, const float* __restrict__ bo1)
{
    extern __shared__ __align__(16) char dsm[];
    float2* Wp   = (float2*)(dsm + WP_OFF);        // [k*8 + pair]
    float*  Wo1s = (float*)(dsm + WO1_OFF);        // [r*512 + k]
    float*  Za   = (float*)(dsm + PH_OFF);         // A: [2][32][65]
    float*  Gs   = (float*)(dsm + PH_OFF + 16640); // A: [16][33]
    float*  Zd   = (float*)(dsm + PH_OFF);         // D: [32][257]
    float*  red  = (float*)(dsm + PH_OFF + 32896); // D: [4][32]

    int tid = threadIdx.x, wid = tid >> 5, lane = tid & 31;
    int bid = blockIdx.x;
    int w3 = wid & 3, kh = wid >> 2;
    unsigned seq = 0;

    // persistent weight loads (once per kernel)
    for (int i = tid; i < 8192; i += 256) {
        int p = i >> 10, k = i & 1023;
        Wp[k * 8 + p] = g_W4p[(size_t)(bid * 8 + p) * KU + k];
    }
    for (int i = tid; i < 2048; i += 256) {
        int r = i >> 9, k = i & 511;
        Wo1s[r * 512 + k] = Wo1[(size_t)(bid * 4 + r) * (2 * HH) + k];
    }
    __syncthreads();

    for (int t = 0; t < TT; t++) {
        const float* u_prev = g_uall + (size_t)(t - 1) * BB * HH;   // unused at t=0
        const float* h_prev = g_h[t & 1];
        float*       h_cur  = g_h[(t + 1) & 1];

        // ---- Phase A: gates = G_E[t] + W_U u_prev + W_hh h_prev + bias; LSTM ----
        {
            float a0 = 0.f, a1 = 0.f, a2 = 0.f, a3 = 0.f;
            float4 pz0, pz1;
            int zb0 = tid >> 4, zc0 = (tid & 15) * 4;
            int zb1 = (256 + tid) >> 4, zc1 = ((256 + tid) & 15) * 4;

            auto loadA = [&](int kt) {
                if (kt < 8) {
                    int kg0 = kt * 64;
                    if (t == 0) {
                        pz0 = make_float4(0.f, 0.f, 0.f, 0.f);
                        pz1 = make_float4(0.f, 0.f, 0.f, 0.f);
                    } else {
                        pz0 = *(const float4*)(u_prev + zb0 * HH + kg0 + zc0);
                        pz1 = *(const float4*)(u_prev + zb1 * HH + kg0 + zc1);
                    }
                } else {
                    int kg0 = (kt - 8) * 64;
                    pz0 = *(const float4*)(h_prev + zb0 * HH + kg0 + zc0);
                    pz1 = *(const float4*)(h_prev + zb1 * HH + kg0 + zc1);
                }
            };

            loadA(0);
            for (int kt = 0; kt < 16; kt++) {
                {
                    float* z0 = Za + (kt & 1) * 2080 + zb0 * 65 + zc0;
                    z0[0] = pz0.x; z0[1] = pz0.y; z0[2] = pz0.z; z0[3] = pz0.w;
                    float* z1 = Za + (kt & 1) * 2080 + zb1 * 65 + zc1;
                    z1[0] = pz1.x; z1[1] = pz1.y; z1[2] = pz1.z; z1[3] = pz1.w;
                }
                __syncthreads();
                if (kt < 15) loadA(kt + 1);
                const float* zrow = Za + (kt & 1) * 2080 + lane * 65;
                const float2* wcol = Wp + (size_t)kt * 64 * 8 + wid;
                #pragma unroll
                for (int kk = 0; kk < 64; kk += 2) {
                    float z0 = zrow[kk], z1 = zrow[kk + 1];
                    float2 w0 = wcol[kk * 8], w1 = wcol[(kk + 1) * 8];
                    a0 += w0.x * z0; a1 += w0.y * z0;
                    a2 += w1.x * z1; a3 += w1.y * z1;
                }
            }
            __syncthreads();
            {
                int rbase = bid * 16;
                int r0 = rbase + wid, r1 = rbase + wid + 8;
                float e0 = (t == 0) ? g_c0[r0 * BB + lane] : g_wob2[r0];
                float e1 = (t == 0) ? g_c0[r1 * BB + lane] : g_wob2[r1];
                float ge0 = g_GE[((size_t)t * G4H + r0) * BB + lane];
                float ge1 = g_GE[((size_t)t * G4H + r1) * BB + lane];
                Gs[wid * 33 + lane]       = a0 + a2 + g_b4[r0] + e0 + ge0;
                Gs[(wid + 8) * 33 + lane] = a1 + a3 + g_b4[r1] + e1 + ge1;
            }
            __syncthreads();

            if (tid < 128) {
                int hl = tid >> 5, b = tid & 31;
                float gi = Gs[(4 * hl + 0) * 33 + b];
                float gf = Gs[(4 * hl + 1) * 33 + b];
                float gg = Gs[(4 * hl + 2) * 33 + b];
                float go = Gs[(4 * hl + 3) * 33 + b];
                gi = 1.f / (1.f + expf(-gi));
                gf = 1.f / (1.f + expf(-gf));
                go = 1.f / (1.f + expf(-go));
                gg = tanhf(gg);
                int h = bid * 4 + hl;
                int idx = b * HH + h;
                float c = gf * g_c[idx] + gi * gg;
                g_c[idx] = c;
                h_cur[idx] = go * tanhf(c);
            }
        }
        seq++; gsync2(bid, seq);

        // ---- Phase CD: scores (registers, no smem) -> soft flag -> D-h GEMV -> ctx+u ----
        {
            // (1) scores: q in registers, 25 scores for batch b
            {
                int b = bid & 31;
                int slice = bid >> 5;
                float qreg[16];
                #pragma unroll
                for (int i = 0; i < 16; i++) qreg[i] = h_cur[b * HH + lane + 32 * i];
                int s0 = slice * 25;
                for (int s = s0 + wid; s < s0 + 25; s += 8) {
                    const float* prow = g_P + (size_t)(b * SS + s) * HH + lane;
                    float a = 0.f;
                    #pragma unroll
                    for (int i = 0; i < 16; i++) a += qreg[i] * prow[32 * i];
                    #pragma unroll
                    for (int off = 16; off; off >>= 1) a += __shfl_down_sync(0xffffffffu, a, off);
                    if (lane == 0) g_w[s * BB + b] = a + g_q0[b * SS + s];
                }
            }
            __syncthreads();
            if (tid == 0) {
                __threadfence();
                atomicAdd((unsigned*)&g_scnt, 1u);
            }

            // (2) D-h GEMV (hides score propagation)
            int r0 = bid * 4;
            float acc = 0.f;
            float4 ph4[8];
            auto loadD = [&](int stg) {
                int koff = stg * 256;
                #pragma unroll
                for (int u2 = 0; u2 < 8; u2++) {
                    int slot = u2 * 256 + tid;
                    int b = slot >> 6, c4 = (slot & 63) * 4;
                    ph4[u2] = *(const float4*)(h_cur + b * HH + koff + c4);
                }
            };

            loadD(0);
            #pragma unroll
            for (int stg = 0; stg < 2; stg++) {
                #pragma unroll
                for (int u2 = 0; u2 < 8; u2++) {
                    int slot = u2 * 256 + tid;
                    int b = slot >> 6, c4 = (slot & 63) * 4;
                    float* zr = Zd + b * 257 + c4;
                    zr[0] = ph4[u2].x; zr[1] = ph4[u2].y; zr[2] = ph4[u2].z; zr[3] = ph4[u2].w;
                }
                __syncthreads();
                if (stg == 0) loadD(1);
                int kl = kh * 128;
                const float* wr = Wo1s + w3 * 512 + stg * 256 + kl;
                const float* zr = Zd + lane * 257 + kl;
                float pa = 0.f, pb = 0.f;
                #pragma unroll
                for (int kk = 0; kk < 128; kk += 2) {
                    pa += wr[kk]     * zr[kk];
                    pb += wr[kk + 1] * zr[kk + 1];
                }
                acc += pa + pb;
                __syncthreads();
            }
            if (kh == 1) red[w3 * 32 + lane] = acc;

            // (3) wait for all scores (expected zero wait)
            if (tid == 0) {
                unsigned tgt = (unsigned)(t + 1) * NBLK;
                while (g_scnt < tgt) __nanosleep(20);
                __threadfence();
            }
            __syncthreads();

            // (4) softmax-ctx via M2, tanh, write u
            if (kh == 0) {
                int r = r0 + w3;
                float m = -1e30f;
                #pragma unroll 4
                for (int s = 0; s < SS; s++) m = fmaxf(m, g_w[s * BB + lane]);
                float sum = 0.f, ctx = 0.f;
                #pragma unroll 2
                for (int s = 0; s < SS; s++) {
                    float e = expf(g_w[s * BB + lane] - m);
                    sum += e;
                    ctx += e * g_M2[((size_t)s * HH + r) * BB + lane];
                }
                acc += ctx / sum;
                float tot = acc + red[w3 * 32 + lane] + bo1[r];
                g_uall[((size_t)t * BB + lane) * HH + r] = tanhf(tot);
            }
        }
        seq++; gsync2(bid, seq);
    }
}

// ---------------- out = uall(2048,512) @ Wo2(512,512)^T + bo2 ----------------
__global__ void __launch_bounds__(256) out_gemm(const float* __restrict__ Wo2,
                                                const float* __restrict__ bo2)
{
    __shared__ float As[16][68];
    __shared__ float Bs[16][68];
    int tid = threadIdx.x;
    int m0 = blockIdx.y * 64, e0 = blockIdx.x * 64;
    int tx = tid & 15, ty = tid >> 4;

    float acc[4][4];
    #pragma unroll
    for (int i = 0; i < 4; i++)
        #pragma unroll
        for (int j = 0; j < 4; j++) acc[i][j] = 0.f;

    for (int k0 = 0; k0 < HH; k0 += 16) {
        int row = tid >> 2, kq = (tid & 3) * 4;
        float4 va = *(const float4*)(g_uall + (size_t)(m0 + row) * HH + k0 + kq);
        As[kq][row] = va.x; As[kq + 1][row] = va.y;
        As[kq + 2][row] = va.z; As[kq + 3][row] = va.w;
        float4 vb = *(const float4*)(Wo2 + (size_t)(e0 + row) * HH + k0 + kq);
        Bs[kq][row] = vb.x; Bs[kq + 1][row] = vb.y;
        Bs[kq + 2][row] = vb.z; Bs[kq + 3][row] = vb.w;
        __syncthreads();
        #pragma unroll
        for (int k = 0; k < 16; k++) {
            float a[4], b[4];
            #pragma unroll
            for (int i = 0; i < 4; i++) a[i] = As[k][ty * 4 + i];
            #pragma unroll
            for (int i = 0; i < 4; i++) b[i] = Bs[k][tx * 4 + i];
            #pragma unroll
            for (int i = 0; i < 4; i++)
                #pragma unroll
                for (int j = 0; j < 4; j++) acc[i][j] += a[i] * b[j];
        }
        __syncthreads();
    }
    #pragma unroll
    for (int i = 0; i < 4; i++)
        #pragma unroll
        for (int j = 0; j < 4; j++)
            g_out[(size_t)(m0 + ty * 4 + i) * EE + e0 + tx * 4 + j] =
                acc[i][j] + bo2[e0 + tx * 4 + j];
}

// ---------------- HMMA logits GEMM (cp.async double-buffered) ----------------
#define SPAD 72
#define TILE_B (128 * SPAD * 2)
__global__ void __launch_bounds__(256) logits_mma(float* __restrict__ outp)
{
    extern __shared__ __align__(16) unsigned char dynsm[];

    int tid = threadIdx.x, lane = tid & 31, wid = tid >> 5;
    int wm = wid >> 2;
    int wn = wid & 3;
    int mblk = blockIdx.x * 128;
    int nblk = blockIdx.y * 128;

    uint32_t sbase = smem_u32(dynsm);
    uint32_t aoff = (uint32_t)((wm * 64 + (lane & 15)) * SPAD * 2 + (lane >> 4) * 16);
    uint32_t boff = (uint32_t)((wn * 32 + (lane & 15)) * SPAD * 2 + (lane >> 4) * 16);

    auto issue = [&](int c) {
        int pass = c >> 3;
        int kb = (c & 7) * 64;
        const unsigned short* Ap = (pass == 2) ? g_Al : g_Ah;
        const unsigned short* Bp = (pass == 1) ? g_Bl : g_Bh;
        uint32_t dA = sbase + (uint32_t)(c & 1) * (2 * TILE_B);
        uint32_t dB = dA + TILE_B;
        #pragma unroll
        for (int u = 0; u < 4; u++) {
            int unit = u * 256 + tid;
            int row = unit >> 3, seg = unit & 7;
            uint32_t so = (uint32_t)(row * (SPAD * 2) + seg * 16);
            cp_async16(dA + so, Ap + (size_t)(mblk + row) * 512 + kb + seg * 8);
            cp_async16(dB + so, Bp + (size_t)(nblk + row) * 512 + kb + seg * 8);
        }
        asm volatile("cp.async.commit_group;" ::: "memory");
    };

    float acc[4][4][4];
    #pragma unroll
    for (int i = 0; i < 4; i++)
        #pragma unroll
        for (int j = 0; j < 4; j++)
            #pragma unroll
            for (int k = 0; k < 4; k++) acc[i][j][k] = 0.f;

    issue(0);
    for (int c = 0; c < 24; c++) {
        if (c < 23) {
            issue(c + 1);
            asm volatile("cp.async.wait_group 1;" ::: "memory");
        } else {
            asm volatile("cp.async.wait_group 0;" ::: "memory");
        }
        __syncthreads();

        uint32_t abase = sbase + (uint32_t)(c & 1) * (2 * TILE_B) + aoff;
        uint32_t bbase = sbase + (uint32_t)(c & 1) * (2 * TILE_B) + TILE_B + boff;
        #pragma unroll
        for (int ks = 0; ks < 4; ks++) {
            uint32_t afr[4][4];
            #pragma unroll
            for (int mf = 0; mf < 4; mf++)
                ldm_x4(afr[mf], abase + (uint32_t)(mf * 16 * SPAD * 2 + ks * 32));
            uint32_t bfr[2][4];
            #pragma unroll
            for (int g = 0; g < 2; g++)
                ldm_x4(bfr[g], bbase + (uint32_t)(g * 16 * SPAD * 2 + ks * 32));
            #pragma unroll
            for (int mf = 0; mf < 4; mf++)
                #pragma unroll
                for (int nf = 0; nf < 4; nf++)
                    mma_bf16(acc[mf][nf], afr[mf],
                             bfr[nf >> 1][nf & 1], bfr[nf >> 1][(nf & 1) + 2]);
        }
        __syncthreads();
    }

    #pragma unroll
    for (int mf = 0; mf < 4; mf++) {
        int r0 = mblk + wm * 64 + mf * 16 + (lane >> 2);
        #pragma unroll
        for (int half = 0; half < 2; half++) {
            int r = r0 + half * 8;
            int tt = r >> 5, b2 = r & 31;
            float* orow = outp + (size_t)(b2 * TT + tt) * VV + nblk + wn * 32 + (lane & 3) * 2;
            #pragma unroll
            for (int nf = 0; nf < 4; nf++) {
                float2 v = make_float2(acc[mf][nf][2 * half], acc[mf][nf][2 * half + 1]);
                *(float2*)(orow + nf * 8) = v;
            }
        }
    }
}

// ---------------- host launch ----------------
extern "C" void kernel_launch(void* const* d_in, const int* in_sizes, int n_in,
                              void* d_out, int out_size)
{
    const float* src_memory  = (const float*)d_in[0];
    const void*  src_mask    = d_in[1];
    const float* init_hidden = (const float*)d_in[2];
    const float* init_cell   = (const float*)d_in[3];
    const float* init_output = (const float*)d_in[4];
    const void*  trg         = d_in[5];
    const float* emb         = (const float*)d_in[6];
    const float* W_ih        = (const float*)d_in[7];
    const float* W_hh        = (const float*)d_in[8];
    const float* b_ih        = (const float*)d_in[9];
    const float* b_hh        = (const float*)d_in[10];
    const float* Wq          = (const float*)d_in[11];
    const float* bq          = (const float*)d_in[12];
    const float* Wb          = (const float*)d_in[13];
    const float* bbias       = (const float*)d_in[14];
    const float* Wo1         = (const float*)d_in[15];
    const float* bo1         = (const float*)d_in[16];
    const float* Wo2         = (const float*)d_in[17];
    const float* bo2         = (const float*)d_in[18];

    float *p_out;
    unsigned short *p_Bh, *p_Bl, *p_Ah, *p_Al;
    cudaGetSymbolAddress((void**)&p_out, g_out);
    cudaGetSymbolAddress((void**)&p_Bh,  g_Bh);
    cudaGetSymbolAddress((void**)&p_Bl,  g_Bl);
    cudaGetSymbolAddress((void**)&p_Ah,  g_Ah);
    cudaGetSymbolAddress((void**)&p_Al,  g_Al);

    cudaFuncSetAttribute(logits_mma, cudaFuncAttributeMaxDynamicSharedMemorySize,
                         4 * TILE_B);
    cudaFuncSetAttribute(decoder_loop, cudaFuncAttributeMaxDynamicSharedMemorySize,
                         DSM_TOTAL);

    // #1 (also resets decoder_loop sync counters for this replay)
    prep1<<<2369, 256>>>((const int*)trg, (const int*)src_mask, init_hidden, init_cell,
                         Wq, Wb, bq, bbias, W_ih, W_hh, b_ih, b_hh, init_output, bo2);
    // #2
    prep2<<<2480, 256>>>(src_memory, src_mask, W_ih, Wo2, Wo1, emb, trg);
    // #3
    {
        int n4 = (VV * EE) / 4;
        conv_split<<<(n4 + 255) / 256, 256>>>(emb, p_Bh, p_Bl, n4);
    }
    // #4 — profiled by ncu (-s 5 -c 1)
    decoder_loop<<<NBLK, 256, DSM_TOTAL>>>(Wo1, bo1);
    // #5
    out_gemm<<<dim3(EE / 64, (TT * BB) / 64), 256>>>(Wo2, bo2);
    // #6
    {
        int n4 = (TT * BB * EE) / 4;
        conv_split<<<(n4 + 255) / 256, 256>>>(p_out, p_Ah, p_Al, n4);
    }
    // #7
    logits_mma<<<dim3(16, 250), 256, 4 * TILE_B>>>((float*)d_out);
}

// round 14
// speedup vs baseline: 3.2129x; 1.2011x over previous
#include <cuda_runtime.h>
#include <cuda_bf16.h>
#include <math.h>
#include <stdint.h>

// Problem dims
#define BB  32
#define SS  100
#define TT  64
#define HH  512
#define EE  512
#define VV  32000
#define G4H 2048
#define KU  1024     // recurrent gate K: H (u) + H (h); emb part precomputed
#define NBLK 128

// ---------------- device scratch ----------------
__device__ float2 g_W4p[1024 * KU];  // paired gate weights [pair][k2]: k2<512 W_U, else W_hh
__device__ float g_b4[G4H];
__device__ float g_GE[(size_t)TT * G4H * BB]; // [t][rr][b] = W_E . emb[token[b,t]]
__device__ float g_c0[G4H * BB];     // W_O @ init_output (t=0 bias), [rr][b]
__device__ float g_wob2[G4H];        // W_O @ bo2 (t>0 bias)
__device__ float g_Wqb[HH * HH];     // Wb @ Wq
__device__ float g_bqb[HH];          // Wb @ bq + bb
__device__ float g_P[BB * SS * HH];  // mem @ Wqb
__device__ float g_q0[BB * SS];      // bqb.mem with mask folded
__device__ float g_M2[(size_t)SS * HH * BB]; // [s][r][b] = Wo1_ctx . mem[b,s]
__device__ float g_w[SS * BB];       // RAW masked scores [s][b] (softmax deferred)
__device__ float g_h[2][BB * HH];
__device__ float g_c[BB * HH];
__device__ float g_uall[TT * BB * HH];
__device__ float g_out[TT * BB * EE];
__device__ int   g_trg64;
__device__ int   g_maskty;

// monotonic two-level barrier counters + score flag (reset each replay in prep1)
__device__ volatile unsigned g_leafc[8];
__device__ volatile unsigned g_rootc;
__device__ volatile unsigned g_scnt;

__device__ unsigned short g_Bh[(size_t)VV * EE];
__device__ unsigned short g_Bl[(size_t)VV * EE];
__device__ unsigned short g_Ah[(size_t)TT * BB * EE];
__device__ unsigned short g_Al[(size_t)TT * BB * EE];

// dynamic smem layout for decoder_loop
#define WP_OFF   0                    // float2[1024*8] = 64KB, index k*8+pair
#define WO1_OFF  65536                // float[4*512]   = 8KB
#define PH_OFF   73728                // phase union
#define DSM_TOTAL (73728 + 35456)

// ---------------- helpers ----------------
__device__ __forceinline__ uint32_t smem_u32(const void* p) {
    uint32_t a;
    asm("{ .reg .u64 t; cvta.to.shared.u64 t, %1; cvt.u32.u64 %0, t; }" : "=r"(a) : "l"(p));
    return a;
}
__device__ __forceinline__ void ldm_x4(uint32_t* r, uint32_t addr) {
    asm volatile("ldmatrix.sync.aligned.m8n8.x4.shared.b16 {%0,%1,%2,%3}, [%4];"
                 : "=r"(r[0]), "=r"(r[1]), "=r"(r[2]), "=r"(r[3]) : "r"(addr));
}
__device__ __forceinline__ void mma_bf16(float* d, const uint32_t* a, uint32_t b0, uint32_t b1) {
    asm volatile(
        "mma.sync.aligned.m16n8k16.row.col.f32.bf16.bf16.f32 "
        "{%0,%1,%2,%3}, {%4,%5,%6,%7}, {%8,%9}, {%0,%1,%2,%3};"
        : "+f"(d[0]), "+f"(d[1]), "+f"(d[2]), "+f"(d[3])
        : "r"(a[0]), "r"(a[1]), "r"(a[2]), "r"(a[3]), "r"(b0), "r"(b1));
}
__device__ __forceinline__ void cp_async16(uint32_t smem_dst, const void* gsrc) {
    asm volatile("cp.async.cg.shared.global [%0], [%1], 16;"
                 :: "r"(smem_dst), "l"(gsrc) : "memory");
}

// monotonic two-level barrier: leaf atomic + root atomic; spin on root value.
__device__ __forceinline__ void gsync2(int bid, unsigned seq) {
    __syncthreads();
    if (threadIdx.x == 0) {
        __threadfence();
        int lf = bid & 7;
        unsigned v = atomicAdd((unsigned*)&g_leafc[lf], 1u) + 1u;
        if (v == seq * 16u) atomicAdd((unsigned*)&g_rootc, 1u);
        unsigned tgt = seq * 8u;
        while (g_rootc < tgt) __nanosleep(20);
        __threadfence();
    }
    __syncthreads();
}

__device__ __forceinline__ int jmap(int rr) { return (rr & 3) * HH + (rr >> 2); }

// ---------------- prep1 ----------------
// blocks: [0] detect+init+ctr-reset | [1,1025) wqb | [1025,1281) c0 | [1281,1345) wob2 | [1345,2369) w4 hh
__global__ void __launch_bounds__(256) prep1(
    const int* __restrict__ trg_w, const int* __restrict__ mask_w,
    const float* __restrict__ ih, const float* __restrict__ ic,
    const float* __restrict__ Wq, const float* __restrict__ Wb,
    const float* __restrict__ bq, const float* __restrict__ bbias,
    const float* __restrict__ Wih, const float* __restrict__ Whh,
    const float* __restrict__ bih, const float* __restrict__ bhh,
    const float* __restrict__ init_output, const float* __restrict__ bo2)
{
    int bid = blockIdx.x, tid = threadIdx.x;
    int wid = tid >> 5, lane = tid & 31;

    if (bid == 0) {
        __shared__ int s_odd_nz, s_bin, s_f32;
        if (tid == 0) {
            s_odd_nz = 0; s_bin = 1; s_f32 = 1;
            for (int i = 0; i < 8; i++) g_leafc[i] = 0;
            g_rootc = 0;
            g_scnt = 0;
        }
        __syncthreads();
        for (int i = tid; i < (BB * TT) / 2; i += 256)
            if (trg_w[2 * i + 1] != 0) atomicOr(&s_odd_nz, 1);
        for (int i = tid; i < (BB * SS) / 4; i += 256) {
            int v = mask_w[i];
            if (v != 0 && v != 1)           atomicAnd(&s_bin, 0);
            if (v != 0 && v != 0x3f800000)  atomicAnd(&s_f32, 0);
        }
        for (int i = tid; i < BB * HH; i += 256) { g_h[0][i] = ih[i]; g_c[i] = ic[i]; }
        __syncthreads();
        if (tid == 0) {
            g_trg64 = s_odd_nz ? 0 : 1;
            g_maskty = s_bin ? 1 : (s_f32 ? 2 : 0);
        }
    } else if (bid < 1025) {
        int idx = bid - 1;
        int by = idx >> 5, bx = idx & 31;
        int ty = tid >> 4, tx = tid & 15;
        int r = by * 16 + ty, c = bx * 16 + tx;
        float acc = 0.f;
        for (int k = 0; k < HH; k++) acc += Wb[r * HH + k] * Wq[k * HH + c];
        g_Wqb[r * HH + c] = acc;
        if (bx == 0 && tx == 0) {
            float a = bbias[r];
            for (int k = 0; k < HH; k++) a += Wb[r * HH + k] * bq[k];
            g_bqb[r] = a;
        }
    } else if (bid < 1281) {
        int idx = bid - 1025;
        int rr = idx * 8 + wid;
        int j = jmap(rr);
        const float* wrow = Wih + (size_t)j * (2 * EE) + EE;
        for (int b = 0; b < BB; b++) {
            const float* io = init_output + (size_t)b * EE;
            float a = 0.f;
            for (int e = lane; e < EE; e += 32) a += wrow[e] * io[e];
            #pragma unroll
            for (int off = 16; off; off >>= 1) a += __shfl_down_sync(0xffffffffu, a, off);
            if (lane == 0) g_c0[rr * BB + b] = a;
        }
    } else if (bid < 1345) {
        int idx = bid - 1281;
        for (int q = 0; q < 4; q++) {
            int rr = idx * 32 + wid * 4 + q;
            int j = jmap(rr);
            const float* wrow = Wih + (size_t)j * (2 * EE) + EE;
            float a = 0.f;
            for (int e = lane; e < EE; e += 32) a += wrow[e] * bo2[e];
            #pragma unroll
            for (int off = 16; off; off >>= 1) a += __shfl_down_sync(0xffffffffu, a, off);
            if (lane == 0) g_wob2[rr] = a;
        }
    } else {
        int pi = bid - 1345;
        int bq2 = pi >> 3, w = pi & 7;
        int rrA = bq2 * 16 + w, rrB = rrA + 8;
        int jA = jmap(rrA), jB = jmap(rrB);
        for (int k = tid; k < HH; k += 256) {
            float a  = Whh[(size_t)jA * HH + k];
            float bv = Whh[(size_t)jB * HH + k];
            g_W4p[(size_t)pi * KU + 512 + k] = make_float2(a, bv);
        }
        if (tid == 0) g_b4[rrA] = bih[jA] + bhh[jA];
        if (tid == 1) g_b4[rrB] = bih[jB] + bhh[jB];
    }
}

// ---------------- prep2 ----------------
// blocks: [0,400) P | [400,800) q0 | [800,1056) W_U | [1056,1456) M2 | [1456,2480) G_E
__global__ void __launch_bounds__(256) prep2(
    const float* __restrict__ mem, const void* __restrict__ mask_raw,
    const float* __restrict__ Wih, const float* __restrict__ Wo2,
    const float* __restrict__ Wo1, const float* __restrict__ emb,
    const void* __restrict__ trg_raw)
{
    __shared__ float As[16][68];
    __shared__ float Bs[16][68];
    __shared__ int tokbuf[64];
    int bid = blockIdx.x, tid = threadIdx.x;

    if (bid < 400) {
        int m0 = (bid >> 3) * 64, j0 = (bid & 7) * 64;
        int tx = tid & 15, ty = tid >> 4;
        float acc[4][4];
        #pragma unroll
        for (int i = 0; i < 4; i++)
            #pragma unroll
            for (int j = 0; j < 4; j++) acc[i][j] = 0.f;
        for (int k0 = 0; k0 < HH; k0 += 16) {
            int row = tid >> 2, kq = (tid & 3) * 4;
            float4 va = *(const float4*)(mem + (size_t)(m0 + row) * HH + k0 + kq);
            As[kq][row] = va.x; As[kq + 1][row] = va.y;
            As[kq + 2][row] = va.z; As[kq + 3][row] = va.w;
            int kr = tid >> 4, jq = (tid & 15) * 4;
            float4 vb = *(const float4*)(g_Wqb + (size_t)(k0 + kr) * HH + j0 + jq);
            *(float4*)&Bs[kr][jq] = vb;
            __syncthreads();
            #pragma unroll
            for (int k = 0; k < 16; k++) {
                float a[4], b[4];
                #pragma unroll
                for (int i = 0; i < 4; i++) a[i] = As[k][ty * 4 + i];
                #pragma unroll
                for (int i = 0; i < 4; i++) b[i] = Bs[k][tx * 4 + i];
                #pragma unroll
                for (int i = 0; i < 4; i++)
                    #pragma unroll
                    for (int j = 0; j < 4; j++) acc[i][j] += a[i] * b[j];
            }
            __syncthreads();
        }
        #pragma unroll
        for (int i = 0; i < 4; i++)
            #pragma unroll
            for (int j = 0; j < 4; j++)
                g_P[(size_t)(m0 + ty * 4 + i) * HH + j0 + tx * 4 + j] = acc[i][j];
    } else if (bid < 800) {
        int m = (bid - 400) * 8 + (tid >> 5);
        int l = tid & 31;
        if (m < BB * SS) {
            float a = 0.f;
            for (int k = l; k < HH; k += 32) a += g_bqb[k] * mem[(size_t)m * HH + k];
            #pragma unroll
            for (int off = 16; off; off >>= 1) a += __shfl_down_sync(0xffffffffu, a, off);
            if (l == 0) {
                int mty = g_maskty;
                bool mv;
                if      (mty == 0) mv = ((const unsigned char*)mask_raw)[m] != 0;
                else if (mty == 1) mv = ((const int*)mask_raw)[m] != 0;
                else               mv = ((const float*)mask_raw)[m] != 0.0f;
                g_q0[m] = mv ? a : -1e9f;
            }
        }
    } else if (bid < 1056) {
        int idx = bid - 800;
        int r0 = (idx >> 3) * 64, h0 = (idx & 7) * 64;
        int tx = tid & 15, ty = tid >> 4;
        float acc[4][4];
        #pragma unroll
        for (int i = 0; i < 4; i++)
            #pragma unroll
            for (int j = 0; j < 4; j++) acc[i][j] = 0.f;
        for (int k0 = 0; k0 < EE; k0 += 16) {
            int row = tid >> 2, kq = (tid & 3) * 4;
            int j = jmap(r0 + row);
            float4 va = *(const float4*)(Wih + (size_t)j * (2 * EE) + EE + k0 + kq);
            As[kq][row] = va.x; As[kq + 1][row] = va.y;
            As[kq + 2][row] = va.z; As[kq + 3][row] = va.w;
            int kr = tid >> 4, jq = (tid & 15) * 4;
            float4 vb = *(const float4*)(Wo2 + (size_t)(k0 + kr) * HH + h0 + jq);
            *(float4*)&Bs[kr][jq] = vb;
            __syncthreads();
            #pragma unroll
            for (int k = 0; k < 16; k++) {
                float a[4], b[4];
                #pragma unroll
                for (int i = 0; i < 4; i++) a[i] = As[k][ty * 4 + i];
                #pragma unroll
                for (int i = 0; i < 4; i++) b[i] = Bs[k][tx * 4 + i];
                #pragma unroll
                for (int i = 0; i < 4; i++)
                    #pragma unroll
                    for (int jj = 0; jj < 4; jj++) acc[i][jj] += a[i] * b[jj];
            }
            __syncthreads();
        }
        #pragma unroll
        for (int i = 0; i < 4; i++) {
            int rr = r0 + ty * 4 + i;
            size_t pbase = ((size_t)((rr >> 4) * 8 + (rr & 7)) * KU);
            int half = (rr >> 3) & 1;
            #pragma unroll
            for (int jj = 0; jj < 4; jj++) {
                int h = h0 + tx * 4 + jj;
                ((float*)g_W4p)[(pbase + h) * 2 + half] = acc[i][jj];
            }
        }
    } else if (bid < 1456) {
        int idx = bid - 1056;
        int m0 = (idx >> 3) * 64, r0j = (idx & 7) * 64;
        int tx = tid & 15, ty = tid >> 4;
        float acc[4][4];
        #pragma unroll
        for (int i = 0; i < 4; i++)
            #pragma unroll
            for (int j = 0; j < 4; j++) acc[i][j] = 0.f;
        for (int k0 = 0; k0 < HH; k0 += 16) {
            int row = tid >> 2, kq = (tid & 3) * 4;
            float4 va = *(const float4*)(mem + (size_t)(m0 + row) * HH + k0 + kq);
            As[kq][row] = va.x; As[kq + 1][row] = va.y;
            As[kq + 2][row] = va.z; As[kq + 3][row] = va.w;
            float4 vb = *(const float4*)(Wo1 + (size_t)(r0j + row) * (2 * HH) + HH + k0 + kq);
            Bs[kq][row] = vb.x; Bs[kq + 1][row] = vb.y;
            Bs[kq + 2][row] = vb.z; Bs[kq + 3][row] = vb.w;
            __syncthreads();
            #pragma unroll
            for (int k = 0; k < 16; k++) {
                float a[4], b[4];
                #pragma unroll
                for (int i = 0; i < 4; i++) a[i] = As[k][ty * 4 + i];
                #pragma unroll
                for (int i = 0; i < 4; i++) b[i] = Bs[k][tx * 4 + i];
                #pragma unroll
                for (int i = 0; i < 4; i++)
                    #pragma unroll
                    for (int j = 0; j < 4; j++) acc[i][j] += a[i] * b[j];
            }
            __syncthreads();
        }
        #pragma unroll
        for (int i = 0; i < 4; i++) {
            int m = m0 + ty * 4 + i;
            int b = m / SS, s = m - b * SS;
            #pragma unroll
            for (int j = 0; j < 4; j++) {
                int r = r0j + tx * 4 + j;
                g_M2[((size_t)s * HH + r) * BB + b] = acc[i][j];
            }
        }
    } else {
        int idx = bid - 1456;
        int m0 = (idx >> 5) * 64, rr0 = (idx & 31) * 64;
        int tx = tid & 15, ty = tid >> 4;
        if (tid < 64) {
            int m = m0 + tid;
            int t = m >> 5, b = m & 31;
            long long v;
            if (g_trg64) v = ((const long long*)trg_raw)[b * TT + t];
            else         v = ((const int*)trg_raw)[b * TT + t];
            int tk = (int)v;
            if (tk < 0) tk = 0;
            if (tk >= VV) tk = VV - 1;
            tokbuf[tid] = tk;
        }
        __syncthreads();
        float acc[4][4];
        #pragma unroll
        for (int i = 0; i < 4; i++)
            #pragma unroll
            for (int j = 0; j < 4; j++) acc[i][j] = 0.f;
        for (int k0 = 0; k0 < EE; k0 += 16) {
            int row = tid >> 2, kq = (tid & 3) * 4;
            float4 va = *(const float4*)(emb + (size_t)tokbuf[row] * EE + k0 + kq);
            As[kq][row] = va.x; As[kq + 1][row] = va.y;
            As[kq + 2][row] = va.z; As[kq + 3][row] = va.w;
            float4 vb = *(const float4*)(Wih + (size_t)jmap(rr0 + row) * (2 * EE) + k0 + kq);
            Bs[kq][row] = vb.x; Bs[kq + 1][row] = vb.y;
            Bs[kq + 2][row] = vb.z; Bs[kq + 3][row] = vb.w;
            __syncthreads();
            #pragma unroll
            for (int k = 0; k < 16; k++) {
                float a[4], b[4];
                #pragma unroll
                for (int i = 0; i < 4; i++) a[i] = As[k][ty * 4 + i];
                #pragma unroll
                for (int i = 0; i < 4; i++) b[i] = Bs[k][tx * 4 + i];
                #pragma unroll
                for (int i = 0; i < 4; i++)
                    #pragma unroll
                    for (int j = 0; j < 4; j++) acc[i][j] += a[i] * b[j];
            }
            __syncthreads();
        }
        #pragma unroll
        for (int i = 0; i < 4; i++) {
            int m = m0 + ty * 4 + i;
            int t = m >> 5, b = m & 31;
            #pragma unroll
            for (int j = 0; j < 4; j++) {
                int rr = rr0 + tx * 4 + j;
                g_GE[((size_t)t * G4H + rr) * BB + b] = acc[i][j];
            }
        }
    }
}

// split fp32 -> bf16 hi + lo
__global__ void conv_split(const float* __restrict__ src,
                           unsigned short* __restrict__ hi,
                           unsigned short* __restrict__ lo, int n4) {
    int i = blockIdx.x * 256 + threadIdx.x;
    if (i >= n4) return;
    float4 v = ((const float4*)src)[i];
    __nv_bfloat16 h0 = __float2bfloat16(v.x);
    __nv_bfloat16 h1 = __float2bfloat16(v.y);
    __nv_bfloat16 h2 = __float2bfloat16(v.z);
    __nv_bfloat16 h3 = __float2bfloat16(v.w);
    __nv_bfloat16 l0 = __float2bfloat16(v.x - __bfloat162float(h0));
    __nv_bfloat16 l1 = __float2bfloat16(v.y - __bfloat162float(h1));
    __nv_bfloat16 l2 = __float2bfloat16(v.z - __bfloat162float(h2));
    __nv_bfloat16 l3 = __float2bfloat16(v.w - __bfloat162float(h3));
    __nv_bfloat162* H = (__nv_bfloat162*)hi;
    __nv_bfloat162* L = (__nv_bfloat162*)lo;
    H[2 * i]     = __halves2bfloat162(h0, h1);
    H[2 * i + 1] = __halves2bfloat162(h2, h3);
    L[2 * i]     = __halves2bfloat162(l0, l1);
    L[2 * i + 1] = __halves2bfloat162(l2, l3);
}

// ---------------- persistent decoder loop (2 barriers/step + soft score flag) ----------------
__global__ void __launch_bounds__(256) decoder_loop(
    const float* __restrict__ Wo1, const float* __restrict__ bo1)
{
    extern __shared__ __align__(16) char dsm[];
    float2* Wp   = (float2*)(dsm + WP_OFF);        // [k*8 + pair]
    float*  Wo1s = (float*)(dsm + WO1_OFF);        // [r*512 + k]
    float*  Za   = (float*)(dsm + PH_OFF);         // A: [2][32][65]
    float*  Gs   = (float*)(dsm + PH_OFF + 16640); // A: [16][33]
    float*  Zd   = (float*)(dsm + PH_OFF);         // D: [32][257]
    float*  red  = (float*)(dsm + PH_OFF + 32896); // D: [4][32]
    float*  mxs  = (float*)(dsm + PH_OFF + 33408); // D: [2][128]
    float*  sums = (float*)(dsm + PH_OFF + 34432); // D: [128]
    float*  ctxs = (float*)(dsm + PH_OFF + 34944); // D: [128]

    int tid = threadIdx.x, wid = tid >> 5, lane = tid & 31;
    int bid = blockIdx.x;
    int w3 = wid & 3, kh = wid >> 2;
    unsigned seq = 0;

    // persistent weight loads (once per kernel)
    for (int i = tid; i < 8192; i += 256) {
        int p = i >> 10, k = i & 1023;
        Wp[k * 8 + p] = g_W4p[(size_t)(bid * 8 + p) * KU + k];
    }
    for (int i = tid; i < 2048; i += 256) {
        int r = i >> 9, k = i & 511;
        Wo1s[r * 512 + k] = Wo1[(size_t)(bid * 4 + r) * (2 * HH) + k];
    }
    __syncthreads();

    for (int t = 0; t < TT; t++) {
        const float* u_prev = g_uall + (size_t)(t - 1) * BB * HH;   // unused at t=0
        const float* h_prev = g_h[t & 1];
        float*       h_cur  = g_h[(t + 1) & 1];

        // ---- Phase A: gates = G_E[t] + W_U u_prev + W_hh h_prev + bias; LSTM ----
        {
            float a0 = 0.f, a1 = 0.f, a2 = 0.f, a3 = 0.f;
            float4 pz0, pz1;
            int zb0 = tid >> 4, zc0 = (tid & 15) * 4;
            int zb1 = (256 + tid) >> 4, zc1 = ((256 + tid) & 15) * 4;

            auto loadA = [&](int kt) {
                if (kt < 8) {
                    int kg0 = kt * 64;
                    if (t == 0) {
                        pz0 = make_float4(0.f, 0.f, 0.f, 0.f);
                        pz1 = make_float4(0.f, 0.f, 0.f, 0.f);
                    } else {
                        pz0 = *(const float4*)(u_prev + zb0 * HH + kg0 + zc0);
                        pz1 = *(const float4*)(u_prev + zb1 * HH + kg0 + zc1);
                    }
                } else {
                    int kg0 = (kt - 8) * 64;
                    pz0 = *(const float4*)(h_prev + zb0 * HH + kg0 + zc0);
                    pz1 = *(const float4*)(h_prev + zb1 * HH + kg0 + zc1);
                }
            };

            loadA(0);
            for (int kt = 0; kt < 16; kt++) {
                {
                    float* z0 = Za + (kt & 1) * 2080 + zb0 * 65 + zc0;
                    z0[0] = pz0.x; z0[1] = pz0.y; z0[2] = pz0.z; z0[3] = pz0.w;
                    float* z1 = Za + (kt & 1) * 2080 + zb1 * 65 + zc1;
                    z1[0] = pz1.x; z1[1] = pz1.y; z1[2] = pz1.z; z1[3] = pz1.w;
                }
                __syncthreads();
                if (kt < 15) loadA(kt + 1);
                const float* zrow = Za + (kt & 1) * 2080 + lane * 65;
                const float2* wcol = Wp + (size_t)kt * 64 * 8 + wid;
                #pragma unroll
                for (int kk = 0; kk < 64; kk += 2) {
                    float z0 = zrow[kk], z1 = zrow[kk + 1];
                    float2 w0 = wcol[kk * 8], w1 = wcol[(kk + 1) * 8];
                    a0 += w0.x * z0; a1 += w0.y * z0;
                    a2 += w1.x * z1; a3 += w1.y * z1;
                }
            }
            __syncthreads();
            {
                int rbase = bid * 16;
                int r0 = rbase + wid, r1 = rbase + wid + 8;
                float e0 = (t == 0) ? g_c0[r0 * BB + lane] : g_wob2[r0];
                float e1 = (t == 0) ? g_c0[r1 * BB + lane] : g_wob2[r1];
                float ge0 = g_GE[((size_t)t * G4H + r0) * BB + lane];
                float ge1 = g_GE[((size_t)t * G4H + r1) * BB + lane];
                Gs[wid * 33 + lane]       = a0 + a2 + g_b4[r0] + e0 + ge0;
                Gs[(wid + 8) * 33 + lane] = a1 + a3 + g_b4[r1] + e1 + ge1;
            }
            __syncthreads();

            if (tid < 128) {
                int hl = tid >> 5, b = tid & 31;
                float gi = Gs[(4 * hl + 0) * 33 + b];
                float gf = Gs[(4 * hl + 1) * 33 + b];
                float gg = Gs[(4 * hl + 2) * 33 + b];
                float go = Gs[(4 * hl + 3) * 33 + b];
                gi = 1.f / (1.f + expf(-gi));
                gf = 1.f / (1.f + expf(-gf));
                go = 1.f / (1.f + expf(-go));
                gg = tanhf(gg);
                int h = bid * 4 + hl;
                int idx = b * HH + h;
                float c = gf * g_c[idx] + gi * gg;
                g_c[idx] = c;
                h_cur[idx] = go * tanhf(c);
            }
        }
        seq++; gsync2(bid, seq);

        // ---- Phase CD: scores -> soft flag -> D-h GEMV -> split softmax-ctx -> u ----
        {
            // (1) scores: q in registers, 25 scores for batch b
            {
                int b = bid & 31;
                int slice = bid >> 5;
                float qreg[16];
                #pragma unroll
                for (int i = 0; i < 16; i++) qreg[i] = h_cur[b * HH + lane + 32 * i];
                int s0 = slice * 25;
                for (int s = s0 + wid; s < s0 + 25; s += 8) {
                    const float* prow = g_P + (size_t)(b * SS + s) * HH + lane;
                    float a = 0.f;
                    #pragma unroll
                    for (int i = 0; i < 16; i++) a += qreg[i] * prow[32 * i];
                    #pragma unroll
                    for (int off = 16; off; off >>= 1) a += __shfl_down_sync(0xffffffffu, a, off);
                    if (lane == 0) g_w[s * BB + b] = a + g_q0[b * SS + s];
                }
            }
            __syncthreads();
            if (tid == 0) {
                __threadfence();
                atomicAdd((unsigned*)&g_scnt, 1u);
            }

            // (2) D-h GEMV (hides score propagation)
            int r0 = bid * 4;
            float acc = 0.f;
            float4 ph4[8];
            auto loadD = [&](int stg) {
                int koff = stg * 256;
                #pragma unroll
                for (int u2 = 0; u2 < 8; u2++) {
                    int slot = u2 * 256 + tid;
                    int b = slot >> 6, c4 = (slot & 63) * 4;
                    ph4[u2] = *(const float4*)(h_cur + b * HH + koff + c4);
                }
            };

            loadD(0);
            #pragma unroll
            for (int stg = 0; stg < 2; stg++) {
                #pragma unroll
                for (int u2 = 0; u2 < 8; u2++) {
                    int slot = u2 * 256 + tid;
                    int b = slot >> 6, c4 = (slot & 63) * 4;
                    float* zr = Zd + b * 257 + c4;
                    zr[0] = ph4[u2].x; zr[1] = ph4[u2].y; zr[2] = ph4[u2].z; zr[3] = ph4[u2].w;
                }
                __syncthreads();
                if (stg == 0) loadD(1);
                int kl = kh * 128;
                const float* wr = Wo1s + w3 * 512 + stg * 256 + kl;
                const float* zr = Zd + lane * 257 + kl;
                float pa = 0.f, pb = 0.f;
                #pragma unroll
                for (int kk = 0; kk < 128; kk += 2) {
                    pa += wr[kk]     * zr[kk];
                    pb += wr[kk + 1] * zr[kk + 1];
                }
                acc += pa + pb;
                __syncthreads();
            }
            if (kh == 1) red[w3 * 32 + lane] = acc;

            // (3) wait for all scores (expected zero wait)
            if (tid == 0) {
                unsigned tgt = (unsigned)(t + 1) * NBLK;
                while (g_scnt < tgt) __nanosleep(20);
                __threadfence();
            }
            __syncthreads();

            // (4) split softmax-ctx via M2: each warp-half handles 50 s-values
            {
                int r = r0 + w3;
                int s0 = kh * 50;
                float m = -1e30f;
                #pragma unroll 4
                for (int s = s0; s < s0 + 50; s++) m = fmaxf(m, g_w[s * BB + lane]);
                mxs[kh * 128 + w3 * 32 + lane] = m;
                __syncthreads();
                float gm = fmaxf(mxs[w3 * 32 + lane], mxs[128 + w3 * 32 + lane]);
                float sum0 = 0.f, sum1 = 0.f, ctx0 = 0.f, ctx1 = 0.f;
                #pragma unroll 2
                for (int s = s0; s < s0 + 50; s += 2) {
                    float e0 = __expf(g_w[s * BB + lane] - gm);
                    float e1 = __expf(g_w[(s + 1) * BB + lane] - gm);
                    sum0 += e0; sum1 += e1;
                    ctx0 += e0 * g_M2[((size_t)s * HH + r) * BB + lane];
                    ctx1 += e1 * g_M2[((size_t)(s + 1) * HH + r) * BB + lane];
                }
                float sum = sum0 + sum1, ctx = ctx0 + ctx1;
                if (kh == 1) {
                    sums[w3 * 32 + lane] = sum;
                    ctxs[w3 * 32 + lane] = ctx;
                }
                __syncthreads();
                if (kh == 0) {
                    sum += sums[w3 * 32 + lane];
                    ctx += ctxs[w3 * 32 + lane];
                    acc += ctx / sum;
                    float tot = acc + red[w3 * 32 + lane] + bo1[r];
                    g_uall[((size_t)t * BB + lane) * HH + r] = tanhf(tot);
                }
            }
        }
        seq++; gsync2(bid, seq);
    }
}

// ---------------- out = uall(2048,512) @ Wo2(512,512)^T + bo2 ----------------
__global__ void __launch_bounds__(256) out_gemm(const float* __restrict__ Wo2,
                                                const float* __restrict__ bo2)
{
    __shared__ float As[16][68];
    __shared__ float Bs[16][68];
    int tid = threadIdx.x;
    int m0 = blockIdx.y * 64, e0 = blockIdx.x * 64;
    int tx = tid & 15, ty = tid >> 4;

    float acc[4][4];
    #pragma unroll
    for (int i = 0; i < 4; i++)
        #pragma unroll
        for (int j = 0; j < 4; j++) acc[i][j] = 0.f;

    for (int k0 = 0; k0 < HH; k0 += 16) {
        int row = tid >> 2, kq = (tid & 3) * 4;
        float4 va = *(const float4*)(g_uall + (size_t)(m0 + row) * HH + k0 + kq);
        As[kq][row] = va.x; As[kq + 1][row] = va.y;
        As[kq + 2][row] = va.z; As[kq + 3][row] = va.w;
        float4 vb = *(const float4*)(Wo2 + (size_t)(e0 + row) * HH + k0 + kq);
        Bs[kq][row] = vb.x; Bs[kq + 1][row] = vb.y;
        Bs[kq + 2][row] = vb.z; Bs[kq + 3][row] = vb.w;
        __syncthreads();
        #pragma unroll
        for (int k = 0; k < 16; k++) {
            float a[4], b[4];
            #pragma unroll
            for (int i = 0; i < 4; i++) a[i] = As[k][ty * 4 + i];
            #pragma unroll
            for (int i = 0; i < 4; i++) b[i] = Bs[k][tx * 4 + i];
            #pragma unroll
            for (int i = 0; i < 4; i++)
                #pragma unroll
                for (int j = 0; j < 4; j++) acc[i][j] += a[i] * b[j];
        }
        __syncthreads();
    }
    #pragma unroll
    for (int i = 0; i < 4; i++)
        #pragma unroll
        for (int j = 0; j < 4; j++)
            g_out[(size_t)(m0 + ty * 4 + i) * EE + e0 + tx * 4 + j] =
                acc[i][j] + bo2[e0 + tx * 4 + j];
}

// ---------------- HMMA logits GEMM: 4-tile chunks, all 3 products per load ----------------
// D = Ah*Bh + Ah*Bl + Al*Bh. 8 K-chunks of 64; per chunk load Ah/Al/Bh/Bl tiles once.
#define SPAD 72
#define TILE_B (128 * SPAD * 2)      // 18432 bytes per tile
#define STAGE_B (4 * TILE_B)         // 73728 per stage (Ah|Al|Bh|Bl)
__global__ void __launch_bounds__(256) logits_mma(float* __restrict__ outp)
{
    extern __shared__ __align__(16) unsigned char dynsm[];

    int tid = threadIdx.x, lane = tid & 31, wid = tid >> 5;
    int wm = wid >> 2;
    int wn = wid & 3;
    int mblk = blockIdx.x * 128;
    int nblk = blockIdx.y * 128;

    uint32_t sbase = smem_u32(dynsm);
    uint32_t aoff = (uint32_t)((wm * 64 + (lane & 15)) * SPAD * 2 + (lane >> 4) * 16);
    uint32_t boff = (uint32_t)((wn * 32 + (lane & 15)) * SPAD * 2 + (lane >> 4) * 16);

    auto issue = [&](int c) {       // c = K-chunk 0..7
        int kb = c * 64;
        uint32_t st = sbase + (uint32_t)(c & 1) * STAGE_B;
        #pragma unroll
        for (int u = 0; u < 4; u++) {
            int unit = u * 256 + tid;
            int row = unit >> 3, seg = unit & 7;
            uint32_t so = (uint32_t)(row * (SPAD * 2) + seg * 16);
            size_t ga = (size_t)(mblk + row) * 512 + kb + seg * 8;
            size_t gb = (size_t)(nblk + row) * 512 + kb + seg * 8;
            cp_async16(st + so,              g_Ah + ga);
            cp_async16(st + TILE_B + so,     g_Al + ga);
            cp_async16(st + 2 * TILE_B + so, g_Bh + gb);
            cp_async16(st + 3 * TILE_B + so, g_Bl + gb);
        }
        asm volatile("cp.async.commit_group;" ::: "memory");
    };

    float acc[4][4][4];
    #pragma unroll
    for (int i = 0; i < 4; i++)
        #pragma unroll
        for (int j = 0; j < 4; j++)
            #pragma unroll
            for (int k = 0; k < 4; k++) acc[i][j][k] = 0.f;

    issue(0);
    for (int c = 0; c < 8; c++) {
        if (c < 7) {
            issue(c + 1);
            asm volatile("cp.async.wait_group 1;" ::: "memory");
        } else {
            asm volatile("cp.async.wait_group 0;" ::: "memory");
        }
        __syncthreads();

        uint32_t st = sbase + (uint32_t)(c & 1) * STAGE_B;
        #pragma unroll
        for (int ks = 0; ks < 4; ks++) {
            uint32_t ah[4][4], al[4][4], bh[2][4], bl[2][4];
            #pragma unroll
            for (int mf = 0; mf < 4; mf++) {
                uint32_t off = aoff + (uint32_t)(mf * 16 * SPAD * 2 + ks * 32);
                ldm_x4(ah[mf], st + off);
                ldm_x4(al[mf], st + TILE_B + off);
            }
            #pragma unroll
            for (int g = 0; g < 2; g++) {
                uint32_t off = boff + (uint32_t)(g * 16 * SPAD * 2 + ks * 32);
                ldm_x4(bh[g], st + 2 * TILE_B + off);
                ldm_x4(bl[g], st + 3 * TILE_B + off);
            }
            #pragma unroll
            for (int mf = 0; mf < 4; mf++)
                #pragma unroll
                for (int nf = 0; nf < 4; nf++) {
                    uint32_t b0h = bh[nf >> 1][nf & 1], b1h = bh[nf >> 1][(nf & 1) + 2];
                    uint32_t b0l = bl[nf >> 1][nf & 1], b1l = bl[nf >> 1][(nf & 1) + 2];
                    mma_bf16(acc[mf][nf], ah[mf], b0h, b1h);
                    mma_bf16(acc[mf][nf], ah[mf], b0l, b1l);
                    mma_bf16(acc[mf][nf], al[mf], b0h, b1h);
                }
        }
        __syncthreads();
    }

    #pragma unroll
    for (int mf = 0; mf < 4; mf++) {
        int r0 = mblk + wm * 64 + mf * 16 + (lane >> 2);
        #pragma unroll
        for (int half = 0; half < 2; half++) {
            int r = r0 + half * 8;
            int tt = r >> 5, b2 = r & 31;
            float* orow = outp + (size_t)(b2 * TT + tt) * VV + nblk + wn * 32 + (lane & 3) * 2;
            #pragma unroll
            for (int nf = 0; nf < 4; nf++) {
                float2 v = make_float2(acc[mf][nf][2 * half], acc[mf][nf][2 * half + 1]);
                *(float2*)(orow + nf * 8) = v;
            }
        }
    }
}

// ---------------- host launch ----------------
extern "C" void kernel_launch(void* const* d_in, const int* in_sizes, int n_in,
                              void* d_out, int out_size)
{
    const float* src_memory  = (const float*)d_in[0];
    const void*  src_mask    = d_in[1];
    const float* init_hidden = (const float*)d_in[2];
    const float* init_cell   = (const float*)d_in[3];
    const float* init_output = (const float*)d_in[4];
    const void*  trg         = d_in[5];
    const float* emb         = (const float*)d_in[6];
    const float* W_ih        = (const float*)d_in[7];
    const float* W_hh        = (const float*)d_in[8];
    const float* b_ih        = (const float*)d_in[9];
    const float* b_hh        = (const float*)d_in[10];
    const float* Wq          = (const float*)d_in[11];
    const float* bq          = (const float*)d_in[12];
    const float* Wb          = (const float*)d_in[13];
    const float* bbias       = (const float*)d_in[14];
    const float* Wo1         = (const float*)d_in[15];
    const float* bo1         = (const float*)d_in[16];
    const float* Wo2         = (const float*)d_in[17];
    const float* bo2         = (const float*)d_in[18];

    float *p_out;
    unsigned short *p_Bh, *p_Bl, *p_Ah, *p_Al;
    cudaGetSymbolAddress((void**)&p_out, g_out);
    cudaGetSymbolAddress((void**)&p_Bh,  g_Bh);
    cudaGetSymbolAddress((void**)&p_Bl,  g_Bl);
    cudaGetSymbolAddress((void**)&p_Ah,  g_Ah);
    cudaGetSymbolAddress((void**)&p_Al,  g_Al);

    cudaFuncSetAttribute(logits_mma, cudaFuncAttributeMaxDynamicSharedMemorySize,
                         2 * STAGE_B);
    cudaFuncSetAttribute(decoder_loop, cudaFuncAttributeMaxDynamicSharedMemorySize,
                         DSM_TOTAL);

    // #1 (also resets decoder_loop sync counters for this replay)
    prep1<<<2369, 256>>>((const int*)trg, (const int*)src_mask, init_hidden, init_cell,
                         Wq, Wb, bq, bbias, W_ih, W_hh, b_ih, b_hh, init_output, bo2);
    // #2
    prep2<<<2480, 256>>>(src_memory, src_mask, W_ih, Wo2, Wo1, emb, trg);
    // #3
    {
        int n4 = (VV * EE) / 4;
        conv_split<<<(n4 + 255) / 256, 256>>>(emb, p_Bh, p_Bl, n4);
    }
    // #4 — profiled by ncu (-s 5 -c 1)
    decoder_loop<<<NBLK, 256, DSM_TOTAL>>>(Wo1, bo1);
    // #5
    out_gemm<<<dim3(EE / 64, (TT * BB) / 64), 256>>>(Wo2, bo2);
    // #6
    {
        int n4 = (TT * BB * EE) / 4;
        conv_split<<<(n4 + 255) / 256, 256>>>(p_out, p_Ah, p_Al, n4);
    }
    // #7
    logits_mma<<<dim3(16, 250), 256, 2 * STAGE_B>>>((float*)d_out);
}

// round 15
// speedup vs baseline: 3.2699x; 1.0177x over previous
#include <cuda_runtime.h>
#include <cuda_bf16.h>
#include <math.h>
#include <stdint.h>

// Problem dims
#define BB  32
#define SS  100
#define TT  64
#define HH  512
#define EE  512
#define VV  32000
#define G4H 2048
#define KU  1024     // recurrent gate K: H (u) + H (h); emb part precomputed
#define NBLK 128

// ---------------- device scratch ----------------
__device__ float2 g_W4p[1024 * KU];  // paired gate weights [pair][k2]: k2<512 W_U, else W_hh
__device__ float g_b4[G4H];
__device__ float g_GE[(size_t)TT * G4H * BB]; // [t][rr][b] = W_E . emb[token[b,t]]
__device__ float g_c0[G4H * BB];     // W_O @ init_output (t=0 bias), [rr][b]
__device__ float g_wob2[G4H];        // W_O @ bo2 (t>0 bias)
__device__ float g_Wqb[HH * HH];     // Wb @ Wq
__device__ float g_bqb[HH];          // Wb @ bq + bb
__device__ float g_P[BB * SS * HH];  // mem @ Wqb
__device__ float g_q0[BB * SS];      // bqb.mem with mask folded
__device__ float g_M2[(size_t)SS * HH * BB]; // [s][r][b] = Wo1_ctx . mem[b,s]
__device__ float g_w[SS * BB];       // RAW masked scores [s][b] (softmax deferred)
__device__ float g_h[2][BB * HH];
__device__ float g_c[BB * HH];
__device__ float g_uall[TT * BB * HH];
__device__ int   g_trg64;
__device__ int   g_maskty;

// monotonic two-level barrier counters + score flag (reset each replay in prep1)
__device__ volatile unsigned g_leafc[8];
__device__ volatile unsigned g_rootc;
__device__ volatile unsigned g_scnt;

__device__ unsigned short g_Bh[(size_t)VV * EE];
__device__ unsigned short g_Bl[(size_t)VV * EE];
__device__ unsigned short g_Ah[(size_t)TT * BB * EE];
__device__ unsigned short g_Al[(size_t)TT * BB * EE];

// dynamic smem layout for decoder_loop
#define WP_OFF   0                    // float2[1024*8] = 64KB, index k*8+pair
#define WO1_OFF  65536                // float[4*512]   = 8KB
#define PH_OFF   73728                // phase union
#define DSM_TOTAL (73728 + 35456)

// ---------------- helpers ----------------
__device__ __forceinline__ uint32_t smem_u32(const void* p) {
    uint32_t a;
    asm("{ .reg .u64 t; cvta.to.shared.u64 t, %1; cvt.u32.u64 %0, t; }" : "=r"(a) : "l"(p));
    return a;
}
__device__ __forceinline__ void ldm_x4(uint32_t* r, uint32_t addr) {
    asm volatile("ldmatrix.sync.aligned.m8n8.x4.shared.b16 {%0,%1,%2,%3}, [%4];"
                 : "=r"(r[0]), "=r"(r[1]), "=r"(r[2]), "=r"(r[3]) : "r"(addr));
}
__device__ __forceinline__ void mma_bf16(float* d, const uint32_t* a, uint32_t b0, uint32_t b1) {
    asm volatile(
        "mma.sync.aligned.m16n8k16.row.col.f32.bf16.bf16.f32 "
        "{%0,%1,%2,%3}, {%4,%5,%6,%7}, {%8,%9}, {%0,%1,%2,%3};"
        : "+f"(d[0]), "+f"(d[1]), "+f"(d[2]), "+f"(d[3])
        : "r"(a[0]), "r"(a[1]), "r"(a[2]), "r"(a[3]), "r"(b0), "r"(b1));
}
__device__ __forceinline__ void cp_async16(uint32_t smem_dst, const void* gsrc) {
    asm volatile("cp.async.cg.shared.global [%0], [%1], 16;"
                 :: "r"(smem_dst), "l"(gsrc) : "memory");
}

// monotonic two-level barrier: leaf atomic + root atomic; spin on root value.
__device__ __forceinline__ void gsync2(int bid, unsigned seq) {
    __syncthreads();
    if (threadIdx.x == 0) {
        __threadfence();
        int lf = bid & 7;
        unsigned v = atomicAdd((unsigned*)&g_leafc[lf], 1u) + 1u;
        if (v == seq * 16u) atomicAdd((unsigned*)&g_rootc, 1u);
        unsigned tgt = seq * 8u;
        while (g_rootc < tgt) __nanosleep(20);
        __threadfence();
    }
    __syncthreads();
}

__device__ __forceinline__ int jmap(int rr) { return (rr & 3) * HH + (rr >> 2); }

// ---------------- prep1 ----------------
// blocks: [0] detect+init+ctrs+bqb | [1,65) wqb tiled | [65,321) c0 | [321,385) wob2 | [385,1409) w4 hh
__global__ void __launch_bounds__(256) prep1(
    const int* __restrict__ trg_w, const int* __restrict__ mask_w,
    const float* __restrict__ ih, const float* __restrict__ ic,
    const float* __restrict__ Wq, const float* __restrict__ Wb,
    const float* __restrict__ bq, const float* __restrict__ bbias,
    const float* __restrict__ Wih, const float* __restrict__ Whh,
    const float* __restrict__ bih, const float* __restrict__ bhh,
    const float* __restrict__ init_output, const float* __restrict__ bo2)
{
    __shared__ float As[16][68];
    __shared__ float Bs[16][68];
    int bid = blockIdx.x, tid = threadIdx.x;
    int wid = tid >> 5, lane = tid & 31;

    if (bid == 0) {
        __shared__ int s_odd_nz, s_bin, s_f32;
        if (tid == 0) {
            s_odd_nz = 0; s_bin = 1; s_f32 = 1;
            for (int i = 0; i < 8; i++) g_leafc[i] = 0;
            g_rootc = 0;
            g_scnt = 0;
        }
        __syncthreads();
        for (int i = tid; i < (BB * TT) / 2; i += 256)
            if (trg_w[2 * i + 1] != 0) atomicOr(&s_odd_nz, 1);
        for (int i = tid; i < (BB * SS) / 4; i += 256) {
            int v = mask_w[i];
            if (v != 0 && v != 1)           atomicAnd(&s_bin, 0);
            if (v != 0 && v != 0x3f800000)  atomicAnd(&s_f32, 0);
        }
        for (int i = tid; i < BB * HH; i += 256) { g_h[0][i] = ih[i]; g_c[i] = ic[i]; }
        // bqb = Wb @ bq + bb (8 warps x 64 rows)
        for (int r = wid * 64; r < wid * 64 + 64; r++) {
            float a = 0.f;
            const float* wrow = Wb + (size_t)r * HH;
            for (int e = lane; e < HH; e += 32) a += wrow[e] * bq[e];
            #pragma unroll
            for (int off = 16; off; off >>= 1) a += __shfl_down_sync(0xffffffffu, a, off);
            if (lane == 0) g_bqb[r] = a + bbias[r];
        }
        __syncthreads();
        if (tid == 0) {
            g_trg64 = s_odd_nz ? 0 : 1;
            g_maskty = s_bin ? 1 : (s_f32 ? 2 : 0);
        }
    } else if (bid < 65) {
        // Wqb = Wb @ Wq, tiled 64x64
        int idx = bid - 1;
        int r0 = (idx >> 3) * 64, c0 = (idx & 7) * 64;
        int tx = tid & 15, ty = tid >> 4;
        float acc[4][4];
        #pragma unroll
        for (int i = 0; i < 4; i++)
            #pragma unroll
            for (int j = 0; j < 4; j++) acc[i][j] = 0.f;
        for (int k0 = 0; k0 < HH; k0 += 16) {
            int row = tid >> 2, kq = (tid & 3) * 4;
            float4 va = *(const float4*)(Wb + (size_t)(r0 + row) * HH + k0 + kq);
            As[kq][row] = va.x; As[kq + 1][row] = va.y;
            As[kq + 2][row] = va.z; As[kq + 3][row] = va.w;
            int kr = tid >> 4, jq = (tid & 15) * 4;
            float4 vb = *(const float4*)(Wq + (size_t)(k0 + kr) * HH + c0 + jq);
            *(float4*)&Bs[kr][jq] = vb;
            __syncthreads();
            #pragma unroll
            for (int k = 0; k < 16; k++) {
                float a[4], b[4];
                #pragma unroll
                for (int i = 0; i < 4; i++) a[i] = As[k][ty * 4 + i];
                #pragma unroll
                for (int i = 0; i < 4; i++) b[i] = Bs[k][tx * 4 + i];
                #pragma unroll
                for (int i = 0; i < 4; i++)
                    #pragma unroll
                    for (int j = 0; j < 4; j++) acc[i][j] += a[i] * b[j];
            }
            __syncthreads();
        }
        #pragma unroll
        for (int i = 0; i < 4; i++)
            #pragma unroll
            for (int j = 0; j < 4; j++)
                g_Wqb[(size_t)(r0 + ty * 4 + i) * HH + c0 + tx * 4 + j] = acc[i][j];
    } else if (bid < 321) {
        int idx = bid - 65;
        int rr = idx * 8 + wid;
        int j = jmap(rr);
        const float* wrow = Wih + (size_t)j * (2 * EE) + EE;
        for (int b = 0; b < BB; b++) {
            const float* io = init_output + (size_t)b * EE;
            float a = 0.f;
            for (int e = lane; e < EE; e += 32) a += wrow[e] * io[e];
            #pragma unroll
            for (int off = 16; off; off >>= 1) a += __shfl_down_sync(0xffffffffu, a, off);
            if (lane == 0) g_c0[rr * BB + b] = a;
        }
    } else if (bid < 385) {
        int idx = bid - 321;
        for (int q = 0; q < 4; q++) {
            int rr = idx * 32 + wid * 4 + q;
            int j = jmap(rr);
            const float* wrow = Wih + (size_t)j * (2 * EE) + EE;
            float a = 0.f;
            for (int e = lane; e < EE; e += 32) a += wrow[e] * bo2[e];
            #pragma unroll
            for (int off = 16; off; off >>= 1) a += __shfl_down_sync(0xffffffffu, a, off);
            if (lane == 0) g_wob2[rr] = a;
        }
    } else {
        int pi = bid - 385;
        int bq2 = pi >> 3, w = pi & 7;
        int rrA = bq2 * 16 + w, rrB = rrA + 8;
        int jA = jmap(rrA), jB = jmap(rrB);
        for (int k = tid; k < HH; k += 256) {
            float a  = Whh[(size_t)jA * HH + k];
            float bv = Whh[(size_t)jB * HH + k];
            g_W4p[(size_t)pi * KU + 512 + k] = make_float2(a, bv);
        }
        if (tid == 0) g_b4[rrA] = bih[jA] + bhh[jA];
        if (tid == 1) g_b4[rrB] = bih[jB] + bhh[jB];
    }
}

// ---------------- prep2 ----------------
// blocks: [0,400) P | [400,800) q0 | [800,1056) W_U | [1056,1456) M2 | [1456,2480) G_E
__global__ void __launch_bounds__(256) prep2(
    const float* __restrict__ mem, const void* __restrict__ mask_raw,
    const float* __restrict__ Wih, const float* __restrict__ Wo2,
    const float* __restrict__ Wo1, const float* __restrict__ emb,
    const void* __restrict__ trg_raw)
{
    __shared__ float As[16][68];
    __shared__ float Bs[16][68];
    __shared__ int tokbuf[64];
    int bid = blockIdx.x, tid = threadIdx.x;

    if (bid < 400) {
        int m0 = (bid >> 3) * 64, j0 = (bid & 7) * 64;
        int tx = tid & 15, ty = tid >> 4;
        float acc[4][4];
        #pragma unroll
        for (int i = 0; i < 4; i++)
            #pragma unroll
            for (int j = 0; j < 4; j++) acc[i][j] = 0.f;
        for (int k0 = 0; k0 < HH; k0 += 16) {
            int row = tid >> 2, kq = (tid & 3) * 4;
            float4 va = *(const float4*)(mem + (size_t)(m0 + row) * HH + k0 + kq);
            As[kq][row] = va.x; As[kq + 1][row] = va.y;
            As[kq + 2][row] = va.z; As[kq + 3][row] = va.w;
            int kr = tid >> 4, jq = (tid & 15) * 4;
            float4 vb = *(const float4*)(g_Wqb + (size_t)(k0 + kr) * HH + j0 + jq);
            *(float4*)&Bs[kr][jq] = vb;
            __syncthreads();
            #pragma unroll
            for (int k = 0; k < 16; k++) {
                float a[4], b[4];
                #pragma unroll
                for (int i = 0; i < 4; i++) a[i] = As[k][ty * 4 + i];
                #pragma unroll
                for (int i = 0; i < 4; i++) b[i] = Bs[k][tx * 4 + i];
                #pragma unroll
                for (int i = 0; i < 4; i++)
                    #pragma unroll
                    for (int j = 0; j < 4; j++) acc[i][j] += a[i] * b[j];
            }
            __syncthreads();
        }
        #pragma unroll
        for (int i = 0; i < 4; i++)
            #pragma unroll
            for (int j = 0; j < 4; j++)
                g_P[(size_t)(m0 + ty * 4 + i) * HH + j0 + tx * 4 + j] = acc[i][j];
    } else if (bid < 800) {
        int m = (bid - 400) * 8 + (tid >> 5);
        int l = tid & 31;
        if (m < BB * SS) {
            float a = 0.f;
            for (int k = l; k < HH; k += 32) a += g_bqb[k] * mem[(size_t)m * HH + k];
            #pragma unroll
            for (int off = 16; off; off >>= 1) a += __shfl_down_sync(0xffffffffu, a, off);
            if (l == 0) {
                int mty = g_maskty;
                bool mv;
                if      (mty == 0) mv = ((const unsigned char*)mask_raw)[m] != 0;
                else if (mty == 1) mv = ((const int*)mask_raw)[m] != 0;
                else               mv = ((const float*)mask_raw)[m] != 0.0f;
                g_q0[m] = mv ? a : -1e9f;
            }
        }
    } else if (bid < 1056) {
        int idx = bid - 800;
        int r0 = (idx >> 3) * 64, h0 = (idx & 7) * 64;
        int tx = tid & 15, ty = tid >> 4;
        float acc[4][4];
        #pragma unroll
        for (int i = 0; i < 4; i++)
            #pragma unroll
            for (int j = 0; j < 4; j++) acc[i][j] = 0.f;
        for (int k0 = 0; k0 < EE; k0 += 16) {
            int row = tid >> 2, kq = (tid & 3) * 4;
            int j = jmap(r0 + row);
            float4 va = *(const float4*)(Wih + (size_t)j * (2 * EE) + EE + k0 + kq);
            As[kq][row] = va.x; As[kq + 1][row] = va.y;
            As[kq + 2][row] = va.z; As[kq + 3][row] = va.w;
            int kr = tid >> 4, jq = (tid & 15) * 4;
            float4 vb = *(const float4*)(Wo2 + (size_t)(k0 + kr) * HH + h0 + jq);
            *(float4*)&Bs[kr][jq] = vb;
            __syncthreads();
            #pragma unroll
            for (int k = 0; k < 16; k++) {
                float a[4], b[4];
                #pragma unroll
                for (int i = 0; i < 4; i++) a[i] = As[k][ty * 4 + i];
                #pragma unroll
                for (int i = 0; i < 4; i++) b[i] = Bs[k][tx * 4 + i];
                #pragma unroll
                for (int i = 0; i < 4; i++)
                    #pragma unroll
                    for (int jj = 0; jj < 4; jj++) acc[i][jj] += a[i] * b[jj];
            }
            __syncthreads();
        }
        #pragma unroll
        for (int i = 0; i < 4; i++) {
            int rr = r0 + ty * 4 + i;
            size_t pbase = ((size_t)((rr >> 4) * 8 + (rr & 7)) * KU);
            int half = (rr >> 3) & 1;
            #pragma unroll
            for (int jj = 0; jj < 4; jj++) {
                int h = h0 + tx * 4 + jj;
                ((float*)g_W4p)[(pbase + h) * 2 + half] = acc[i][jj];
            }
        }
    } else if (bid < 1456) {
        int idx = bid - 1056;
        int m0 = (idx >> 3) * 64, r0j = (idx & 7) * 64;
        int tx = tid & 15, ty = tid >> 4;
        float acc[4][4];
        #pragma unroll
        for (int i = 0; i < 4; i++)
            #pragma unroll
            for (int j = 0; j < 4; j++) acc[i][j] = 0.f;
        for (int k0 = 0; k0 < HH; k0 += 16) {
            int row = tid >> 2, kq = (tid & 3) * 4;
            float4 va = *(const float4*)(mem + (size_t)(m0 + row) * HH + k0 + kq);
            As[kq][row] = va.x; As[kq + 1][row] = va.y;
            As[kq + 2][row] = va.z; As[kq + 3][row] = va.w;
            float4 vb = *(const float4*)(Wo1 + (size_t)(r0j + row) * (2 * HH) + HH + k0 + kq);
            Bs[kq][row] = vb.x; Bs[kq + 1][row] = vb.y;
            Bs[kq + 2][row] = vb.z; Bs[kq + 3][row] = vb.w;
            __syncthreads();
            #pragma unroll
            for (int k = 0; k < 16; k++) {
                float a[4], b[4];
                #pragma unroll
                for (int i = 0; i < 4; i++) a[i] = As[k][ty * 4 + i];
                #pragma unroll
                for (int i = 0; i < 4; i++) b[i] = Bs[k][tx * 4 + i];
                #pragma unroll
                for (int i = 0; i < 4; i++)
                    #pragma unroll
                    for (int j = 0; j < 4; j++) acc[i][j] += a[i] * b[j];
            }
            __syncthreads();
        }
        #pragma unroll
        for (int i = 0; i < 4; i++) {
            int m = m0 + ty * 4 + i;
            int b = m / SS, s = m - b * SS;
            #pragma unroll
            for (int j = 0; j < 4; j++) {
                int r = r0j + tx * 4 + j;
                g_M2[((size_t)s * HH + r) * BB + b] = acc[i][j];
            }
        }
    } else {
        int idx = bid - 1456;
        int m0 = (idx >> 5) * 64, rr0 = (idx & 31) * 64;
        int tx = tid & 15, ty = tid >> 4;
        if (tid < 64) {
            int m = m0 + tid;
            int t = m >> 5, b = m & 31;
            long long v;
            if (g_trg64) v = ((const long long*)trg_raw)[b * TT + t];
            else         v = ((const int*)trg_raw)[b * TT + t];
            int tk = (int)v;
            if (tk < 0) tk = 0;
            if (tk >= VV) tk = VV - 1;
            tokbuf[tid] = tk;
        }
        __syncthreads();
        float acc[4][4];
        #pragma unroll
        for (int i = 0; i < 4; i++)
            #pragma unroll
            for (int j = 0; j < 4; j++) acc[i][j] = 0.f;
        for (int k0 = 0; k0 < EE; k0 += 16) {
            int row = tid >> 2, kq = (tid & 3) * 4;
            float4 va = *(const float4*)(emb + (size_t)tokbuf[row] * EE + k0 + kq);
            As[kq][row] = va.x; As[kq + 1][row] = va.y;
            As[kq + 2][row] = va.z; As[kq + 3][row] = va.w;
            float4 vb = *(const float4*)(Wih + (size_t)jmap(rr0 + row) * (2 * EE) + k0 + kq);
            Bs[kq][row] = vb.x; Bs[kq + 1][row] = vb.y;
            Bs[kq + 2][row] = vb.z; Bs[kq + 3][row] = vb.w;
            __syncthreads();
            #pragma unroll
            for (int k = 0; k < 16; k++) {
                float a[4], b[4];
                #pragma unroll
                for (int i = 0; i < 4; i++) a[i] = As[k][ty * 4 + i];
                #pragma unroll
                for (int i = 0; i < 4; i++) b[i] = Bs[k][tx * 4 + i];
                #pragma unroll
                for (int i = 0; i < 4; i++)
                    #pragma unroll
                    for (int j = 0; j < 4; j++) acc[i][j] += a[i] * b[j];
            }
            __syncthreads();
        }
        #pragma unroll
        for (int i = 0; i < 4; i++) {
            int m = m0 + ty * 4 + i;
            int t = m >> 5, b = m & 31;
            #pragma unroll
            for (int j = 0; j < 4; j++) {
                int rr = rr0 + tx * 4 + j;
                g_GE[((size_t)t * G4H + rr) * BB + b] = acc[i][j];
            }
        }
    }
}

// split fp32 -> bf16 hi + lo (emb only)
__global__ void conv_split(const float* __restrict__ src,
                           unsigned short* __restrict__ hi,
                           unsigned short* __restrict__ lo, int n4) {
    int i = blockIdx.x * 256 + threadIdx.x;
    if (i >= n4) return;
    float4 v = ((const float4*)src)[i];
    __nv_bfloat16 h0 = __float2bfloat16(v.x);
    __nv_bfloat16 h1 = __float2bfloat16(v.y);
    __nv_bfloat16 h2 = __float2bfloat16(v.z);
    __nv_bfloat16 h3 = __float2bfloat16(v.w);
    __nv_bfloat16 l0 = __float2bfloat16(v.x - __bfloat162float(h0));
    __nv_bfloat16 l1 = __float2bfloat16(v.y - __bfloat162float(h1));
    __nv_bfloat16 l2 = __float2bfloat16(v.z - __bfloat162float(h2));
    __nv_bfloat16 l3 = __float2bfloat16(v.w - __bfloat162float(h3));
    __nv_bfloat162* H = (__nv_bfloat162*)hi;
    __nv_bfloat162* L = (__nv_bfloat162*)lo;
    H[2 * i]     = __halves2bfloat162(h0, h1);
    H[2 * i + 1] = __halves2bfloat162(h2, h3);
    L[2 * i]     = __halves2bfloat162(l0, l1);
    L[2 * i + 1] = __halves2bfloat162(l2, l3);
}

// ---------------- persistent decoder loop (2 barriers/step + soft score flag) ----------------
__global__ void __launch_bounds__(256) decoder_loop(
    const float* __restrict__ Wo1, const float* __restrict__ bo1)
{
    extern __shared__ __align__(16) char dsm[];
    float2* Wp   = (float2*)(dsm + WP_OFF);
    float*  Wo1s = (float*)(dsm + WO1_OFF);
    float*  Za   = (float*)(dsm + PH_OFF);
    float*  Gs   = (float*)(dsm + PH_OFF + 16640);
    float*  Zd   = (float*)(dsm + PH_OFF);
    float*  red  = (float*)(dsm + PH_OFF + 32896);
    float*  mxs  = (float*)(dsm + PH_OFF + 33408);
    float*  sums = (float*)(dsm + PH_OFF + 34432);
    float*  ctxs = (float*)(dsm + PH_OFF + 34944);

    int tid = threadIdx.x, wid = tid >> 5, lane = tid & 31;
    int bid = blockIdx.x;
    int w3 = wid & 3, kh = wid >> 2;
    unsigned seq = 0;

    for (int i = tid; i < 8192; i += 256) {
        int p = i >> 10, k = i & 1023;
        Wp[k * 8 + p] = g_W4p[(size_t)(bid * 8 + p) * KU + k];
    }
    for (int i = tid; i < 2048; i += 256) {
        int r = i >> 9, k = i & 511;
        Wo1s[r * 512 + k] = Wo1[(size_t)(bid * 4 + r) * (2 * HH) + k];
    }
    __syncthreads();

    for (int t = 0; t < TT; t++) {
        const float* u_prev = g_uall + (size_t)(t - 1) * BB * HH;
        const float* h_prev = g_h[t & 1];
        float*       h_cur  = g_h[(t + 1) & 1];

        // ---- Phase A ----
        {
            float a0 = 0.f, a1 = 0.f, a2 = 0.f, a3 = 0.f;
            float4 pz0, pz1;
            int zb0 = tid >> 4, zc0 = (tid & 15) * 4;
            int zb1 = (256 + tid) >> 4, zc1 = ((256 + tid) & 15) * 4;

            auto loadA = [&](int kt) {
                if (kt < 8) {
                    int kg0 = kt * 64;
                    if (t == 0) {
                        pz0 = make_float4(0.f, 0.f, 0.f, 0.f);
                        pz1 = make_float4(0.f, 0.f, 0.f, 0.f);
                    } else {
                        pz0 = *(const float4*)(u_prev + zb0 * HH + kg0 + zc0);
                        pz1 = *(const float4*)(u_prev + zb1 * HH + kg0 + zc1);
                    }
                } else {
                    int kg0 = (kt - 8) * 64;
                    pz0 = *(const float4*)(h_prev + zb0 * HH + kg0 + zc0);
                    pz1 = *(const float4*)(h_prev + zb1 * HH + kg0 + zc1);
                }
            };

            loadA(0);
            for (int kt = 0; kt < 16; kt++) {
                {
                    float* z0 = Za + (kt & 1) * 2080 + zb0 * 65 + zc0;
                    z0[0] = pz0.x; z0[1] = pz0.y; z0[2] = pz0.z; z0[3] = pz0.w;
                    float* z1 = Za + (kt & 1) * 2080 + zb1 * 65 + zc1;
                    z1[0] = pz1.x; z1[1] = pz1.y; z1[2] = pz1.z; z1[3] = pz1.w;
                }
                __syncthreads();
                if (kt < 15) loadA(kt + 1);
                const float* zrow = Za + (kt & 1) * 2080 + lane * 65;
                const float2* wcol = Wp + (size_t)kt * 64 * 8 + wid;
                #pragma unroll
                for (int kk = 0; kk < 64; kk += 2) {
                    float z0 = zrow[kk], z1 = zrow[kk + 1];
                    float2 w0 = wcol[kk * 8], w1 = wcol[(kk + 1) * 8];
                    a0 += w0.x * z0; a1 += w0.y * z0;
                    a2 += w1.x * z1; a3 += w1.y * z1;
                }
            }
            __syncthreads();
            {
                int rbase = bid * 16;
                int r0 = rbase + wid, r1 = rbase + wid + 8;
                float e0 = (t == 0) ? g_c0[r0 * BB + lane] : g_wob2[r0];
                float e1 = (t == 0) ? g_c0[r1 * BB + lane] : g_wob2[r1];
                float ge0 = g_GE[((size_t)t * G4H + r0) * BB + lane];
                float ge1 = g_GE[((size_t)t * G4H + r1) * BB + lane];
                Gs[wid * 33 + lane]       = a0 + a2 + g_b4[r0] + e0 + ge0;
                Gs[(wid + 8) * 33 + lane] = a1 + a3 + g_b4[r1] + e1 + ge1;
            }
            __syncthreads();

            if (tid < 128) {
                int hl = tid >> 5, b = tid & 31;
                float gi = Gs[(4 * hl + 0) * 33 + b];
                float gf = Gs[(4 * hl + 1) * 33 + b];
                float gg = Gs[(4 * hl + 2) * 33 + b];
                float go = Gs[(4 * hl + 3) * 33 + b];
                gi = 1.f / (1.f + expf(-gi));
                gf = 1.f / (1.f + expf(-gf));
                go = 1.f / (1.f + expf(-go));
                gg = tanhf(gg);
                int h = bid * 4 + hl;
                int idx = b * HH + h;
                float c = gf * g_c[idx] + gi * gg;
                g_c[idx] = c;
                h_cur[idx] = go * tanhf(c);
            }
        }
        seq++; gsync2(bid, seq);

        // ---- Phase CD ----
        {
            {
                int b = bid & 31;
                int slice = bid >> 5;
                float qreg[16];
                #pragma unroll
                for (int i = 0; i < 16; i++) qreg[i] = h_cur[b * HH + lane + 32 * i];
                int s0 = slice * 25;
                for (int s = s0 + wid; s < s0 + 25; s += 8) {
                    const float* prow = g_P + (size_t)(b * SS + s) * HH + lane;
                    float a = 0.f;
                    #pragma unroll
                    for (int i = 0; i < 16; i++) a += qreg[i] * prow[32 * i];
                    #pragma unroll
                    for (int off = 16; off; off >>= 1) a += __shfl_down_sync(0xffffffffu, a, off);
                    if (lane == 0) g_w[s * BB + b] = a + g_q0[b * SS + s];
                }
            }
            __syncthreads();
            if (tid == 0) {
                __threadfence();
                atomicAdd((unsigned*)&g_scnt, 1u);
            }

            int r0 = bid * 4;
            float acc = 0.f;
            float4 ph4[8];
            auto loadD = [&](int stg) {
                int koff = stg * 256;
                #pragma unroll
                for (int u2 = 0; u2 < 8; u2++) {
                    int slot = u2 * 256 + tid;
                    int b = slot >> 6, c4 = (slot & 63) * 4;
                    ph4[u2] = *(const float4*)(h_cur + b * HH + koff + c4);
                }
            };

            loadD(0);
            #pragma unroll
            for (int stg = 0; stg < 2; stg++) {
                #pragma unroll
                for (int u2 = 0; u2 < 8; u2++) {
                    int slot = u2 * 256 + tid;
                    int b = slot >> 6, c4 = (slot & 63) * 4;
                    float* zr = Zd + b * 257 + c4;
                    zr[0] = ph4[u2].x; zr[1] = ph4[u2].y; zr[2] = ph4[u2].z; zr[3] = ph4[u2].w;
                }
                __syncthreads();
                if (stg == 0) loadD(1);
                int kl = kh * 128;
                const float* wr = Wo1s + w3 * 512 + stg * 256 + kl;
                const float* zr = Zd + lane * 257 + kl;
                float pa = 0.f, pb = 0.f;
                #pragma unroll
                for (int kk = 0; kk < 128; kk += 2) {
                    pa += wr[kk]     * zr[kk];
                    pb += wr[kk + 1] * zr[kk + 1];
                }
                acc += pa + pb;
                __syncthreads();
            }
            if (kh == 1) red[w3 * 32 + lane] = acc;

            if (tid == 0) {
                unsigned tgt = (unsigned)(t + 1) * NBLK;
                while (g_scnt < tgt) __nanosleep(20);
                __threadfence();
            }
            __syncthreads();

            {
                int r = r0 + w3;
                int s0 = kh * 50;
                float m = -1e30f;
                #pragma unroll 4
                for (int s = s0; s < s0 + 50; s++) m = fmaxf(m, g_w[s * BB + lane]);
                mxs[kh * 128 + w3 * 32 + lane] = m;
                __syncthreads();
                float gm = fmaxf(mxs[w3 * 32 + lane], mxs[128 + w3 * 32 + lane]);
                float sum0 = 0.f, sum1 = 0.f, ctx0 = 0.f, ctx1 = 0.f;
                #pragma unroll 2
                for (int s = s0; s < s0 + 50; s += 2) {
                    float e0 = __expf(g_w[s * BB + lane] - gm);
                    float e1 = __expf(g_w[(s + 1) * BB + lane] - gm);
                    sum0 += e0; sum1 += e1;
                    ctx0 += e0 * g_M2[((size_t)s * HH + r) * BB + lane];
                    ctx1 += e1 * g_M2[((size_t)(s + 1) * HH + r) * BB + lane];
                }
                float sum = sum0 + sum1, ctx = ctx0 + ctx1;
                if (kh == 1) {
                    sums[w3 * 32 + lane] = sum;
                    ctxs[w3 * 32 + lane] = ctx;
                }
                __syncthreads();
                if (kh == 0) {
                    sum += sums[w3 * 32 + lane];
                    ctx += ctxs[w3 * 32 + lane];
                    acc += ctx / sum;
                    float tot = acc + red[w3 * 32 + lane] + bo1[r];
                    g_uall[((size_t)t * BB + lane) * HH + r] = tanhf(tot);
                }
            }
        }
        seq++; gsync2(bid, seq);
    }
}

// ---------------- out_gemm: uall @ Wo2^T + bo2 -> Ah/Al bf16 split directly ----------------
__global__ void __launch_bounds__(256) out_gemm(const float* __restrict__ Wo2,
                                                const float* __restrict__ bo2)
{
    __shared__ float As[16][68];
    __shared__ float Bs[16][68];
    int tid = threadIdx.x;
    int m0 = blockIdx.y * 64, e0 = blockIdx.x * 64;
    int tx = tid & 15, ty = tid >> 4;

    float acc[4][4];
    #pragma unroll
    for (int i = 0; i < 4; i++)
        #pragma unroll
        for (int j = 0; j < 4; j++) acc[i][j] = 0.f;

    for (int k0 = 0; k0 < HH; k0 += 16) {
        int row = tid >> 2, kq = (tid & 3) * 4;
        float4 va = *(const float4*)(g_uall + (size_t)(m0 + row) * HH + k0 + kq);
        As[kq][row] = va.x; As[kq + 1][row] = va.y;
        As[kq + 2][row] = va.z; As[kq + 3][row] = va.w;
        float4 vb = *(const float4*)(Wo2 + (size_t)(e0 + row) * HH + k0 + kq);
        Bs[kq][row] = vb.x; Bs[kq + 1][row] = vb.y;
        Bs[kq + 2][row] = vb.z; Bs[kq + 3][row] = vb.w;
        __syncthreads();
        #pragma unroll
        for (int k = 0; k < 16; k++) {
            float a[4], b[4];
            #pragma unroll
            for (int i = 0; i < 4; i++) a[i] = As[k][ty * 4 + i];
            #pragma unroll
            for (int i = 0; i < 4; i++) b[i] = Bs[k][tx * 4 + i];
            #pragma unroll
            for (int i = 0; i < 4; i++)
                #pragma unroll
                for (int j = 0; j < 4; j++) acc[i][j] += a[i] * b[j];
        }
        __syncthreads();
    }
    #pragma unroll
    for (int i = 0; i < 4; i++) {
        size_t rowoff = (size_t)(m0 + ty * 4 + i) * EE;
        #pragma unroll
        for (int j = 0; j < 4; j++) {
            int e = e0 + tx * 4 + j;
            float o = acc[i][j] + bo2[e];
            __nv_bfloat16 h = __float2bfloat16(o);
            __nv_bfloat16 l = __float2bfloat16(o - __bfloat162float(h));
            g_Ah[rowoff + e] = *(unsigned short*)&h;
            g_Al[rowoff + e] = *(unsigned short*)&l;
        }
    }
}

// ---------------- HMMA logits GEMM: K-chunk 32, 2 CTAs/SM ----------------
// D = Ah*Bh + Ah*Bl + Al*Bh. 16 K-chunks of 32; per chunk load Ah/Al/Bh/Bl tiles once.
#define LSPAD_B 80                    // bytes per smem row (64B data + 16 pad)
#define LTILE_B (128 * LSPAD_B)       // 10240
#define LSTAGE_B (4 * LTILE_B)        // 40960 per stage
__global__ void __launch_bounds__(256, 2) logits_mma(float* __restrict__ outp)
{
    extern __shared__ __align__(16) unsigned char dynsm[];

    int tid = threadIdx.x, lane = tid & 31, wid = tid >> 5;
    int wm = wid >> 2;
    int wn = wid & 3;
    int mblk = blockIdx.x * 128;
    int nblk = blockIdx.y * 128;

    uint32_t sbase = smem_u32(dynsm);
    uint32_t aoff = (uint32_t)((wm * 64 + (lane & 15)) * LSPAD_B + (lane >> 4) * 16);
    uint32_t boff = (uint32_t)((wn * 32 + (lane & 15)) * LSPAD_B + (lane >> 4) * 16);

    auto issue = [&](int c) {       // c = K-chunk 0..15
        int kb = c * 32;
        uint32_t st = sbase + (uint32_t)(c & 1) * LSTAGE_B;
        #pragma unroll
        for (int u = 0; u < 2; u++) {
            int unit = u * 256 + tid;
            int row = unit >> 2, seg = unit & 3;
            uint32_t so = (uint32_t)(row * LSPAD_B + seg * 16);
            size_t ga = (size_t)(mblk + row) * 512 + kb + seg * 8;
            size_t gb = (size_t)(nblk + row) * 512 + kb + seg * 8;
            cp_async16(st + so,               g_Ah + ga);
            cp_async16(st + LTILE_B + so,     g_Al + ga);
            cp_async16(st + 2 * LTILE_B + so, g_Bh + gb);
            cp_async16(st + 3 * LTILE_B + so, g_Bl + gb);
        }
        asm volatile("cp.async.commit_group;" ::: "memory");
    };

    float acc[4][4][4];
    #pragma unroll
    for (int i = 0; i < 4; i++)
        #pragma unroll
        for (int j = 0; j < 4; j++)
            #pragma unroll
            for (int k = 0; k < 4; k++) acc[i][j][k] = 0.f;

    issue(0);
    for (int c = 0; c < 16; c++) {
        if (c < 15) {
            issue(c + 1);
            asm volatile("cp.async.wait_group 1;" ::: "memory");
        } else {
            asm volatile("cp.async.wait_group 0;" ::: "memory");
        }
        __syncthreads();

        uint32_t st = sbase + (uint32_t)(c & 1) * LSTAGE_B;
        #pragma unroll
        for (int ks = 0; ks < 2; ks++) {
            uint32_t ah[4][4], al[4][4], bh[2][4], bl[2][4];
            #pragma unroll
            for (int mf = 0; mf < 4; mf++) {
                uint32_t off = aoff + (uint32_t)(mf * 16 * LSPAD_B + ks * 32);
                ldm_x4(ah[mf], st + off);
                ldm_x4(al[mf], st + LTILE_B + off);
            }
            #pragma unroll
            for (int g = 0; g < 2; g++) {
                uint32_t off = boff + (uint32_t)(g * 16 * LSPAD_B + ks * 32);
                ldm_x4(bh[g], st + 2 * LTILE_B + off);
                ldm_x4(bl[g], st + 3 * LTILE_B + off);
            }
            #pragma unroll
            for (int mf = 0; mf < 4; mf++)
                #pragma unroll
                for (int nf = 0; nf < 4; nf++) {
                    uint32_t b0h = bh[nf >> 1][nf & 1], b1h = bh[nf >> 1][(nf & 1) + 2];
                    uint32_t b0l = bl[nf >> 1][nf & 1], b1l = bl[nf >> 1][(nf & 1) + 2];
                    mma_bf16(acc[mf][nf], ah[mf], b0h, b1h);
                    mma_bf16(acc[mf][nf], ah[mf], b0l, b1l);
                    mma_bf16(acc[mf][nf], al[mf], b0h, b1h);
                }
        }
        __syncthreads();
    }

    #pragma unroll
    for (int mf = 0; mf < 4; mf++) {
        int r0 = mblk + wm * 64 + mf * 16 + (lane >> 2);
        #pragma unroll
        for (int half = 0; half < 2; half++) {
            int r = r0 + half * 8;
            int tt = r >> 5, b2 = r & 31;
            float* orow = outp + (size_t)(b2 * TT + tt) * VV + nblk + wn * 32 + (lane & 3) * 2;
            #pragma unroll
            for (int nf = 0; nf < 4; nf++) {
                float2 v = make_float2(acc[mf][nf][2 * half], acc[mf][nf][2 * half + 1]);
                *(float2*)(orow + nf * 8) = v;
            }
        }
    }
}

// ---------------- host launch ----------------
extern "C" void kernel_launch(void* const* d_in, const int* in_sizes, int n_in,
                              void* d_out, int out_size)
{
    const float* src_memory  = (const float*)d_in[0];
    const void*  src_mask    = d_in[1];
    const float* init_hidden = (const float*)d_in[2];
    const float* init_cell   = (const float*)d_in[3];
    const float* init_output = (const float*)d_in[4];
    const void*  trg         = d_in[5];
    const float* emb         = (const float*)d_in[6];
    const float* W_ih        = (const float*)d_in[7];
    const float* W_hh        = (const float*)d_in[8];
    const float* b_ih        = (const float*)d_in[9];
    const float* b_hh        = (const float*)d_in[10];
    const float* Wq          = (const float*)d_in[11];
    const float* bq          = (const float*)d_in[12];
    const float* Wb          = (const float*)d_in[13];
    const float* bbias       = (const float*)d_in[14];
    const float* Wo1         = (const float*)d_in[15];
    const float* bo1         = (const float*)d_in[16];
    const float* Wo2         = (const float*)d_in[17];
    const float* bo2         = (const float*)d_in[18];

    unsigned short *p_Bh, *p_Bl;
    cudaGetSymbolAddress((void**)&p_Bh,  g_Bh);
    cudaGetSymbolAddress((void**)&p_Bl,  g_Bl);

    cudaFuncSetAttribute(logits_mma, cudaFuncAttributeMaxDynamicSharedMemorySize,
                         2 * LSTAGE_B);
    cudaFuncSetAttribute(decoder_loop, cudaFuncAttributeMaxDynamicSharedMemorySize,
                         DSM_TOTAL);

    // #1 (also resets decoder_loop sync counters for this replay)
    prep1<<<1409, 256>>>((const int*)trg, (const int*)src_mask, init_hidden, init_cell,
                         Wq, Wb, bq, bbias, W_ih, W_hh, b_ih, b_hh, init_output, bo2);
    // #2
    prep2<<<2480, 256>>>(src_memory, src_mask, W_ih, Wo2, Wo1, emb, trg);
    // #3
    {
        int n4 = (VV * EE) / 4;
        conv_split<<<(n4 + 255) / 256, 256>>>(emb, p_Bh, p_Bl, n4);
    }
    // #4 — profiled by ncu (-s 5 -c 1)
    decoder_loop<<<NBLK, 256, DSM_TOTAL>>>(Wo1, bo1);
    // #5 (fused epilogue writes Ah/Al)
    out_gemm<<<dim3(EE / 64, (TT * BB) / 64), 256>>>(Wo2, bo2);
    // #6
    logits_mma<<<dim3(16, 250), 256, 2 * LSTAGE_B>>>((float*)d_out);
}